// round 1
// baseline (speedup 1.0000x reference)
#include <cuda_runtime.h>
#include <cstddef>

// ---------------- problem constants ----------------
#define D_MODEL 768
#define D_INNER 1536
#define D_STATE 16
#define DT_RANK 48
#define NB 2
#define SEQ 1024
#define BL (NB * SEQ)                 // 2048
#define DBC_N (DT_RANK + 2 * D_STATE) // 80

// ---------------- scratch (static __device__ arrays; no allocs) ----------------
__device__ float g_xz[BL * 2 * D_INNER];     // in_proj output [2048, 3072]
__device__ float g_xsc[BL * D_INNER];        // conv+silu output
__device__ float g_zs[BL * D_INNER];         // silu(z)
__device__ float g_dbc_f[BL * DBC_N];
__device__ float g_dbc_b[BL * DBC_N];
__device__ float g_delta_f[BL * D_INNER];
__device__ float g_delta_b[BL * D_INNER];
__device__ float g_y_f[BL * D_INNER];
__device__ float g_y_b[BL * D_INNER];
__device__ float g_u[BL * D_INNER];

// ---------------- math helpers ----------------
__device__ __forceinline__ float siluf(float x) {
    return x / (1.f + __expf(-x));
}
__device__ __forceinline__ float softplusf(float x) {
    return (x > 20.f) ? x : log1pf(__expf(x));
}

// ---------------- SGEMM: C[M,N] = A[M,K] * B[N,K]^T (+ optional bias/softplus) ----------------
// BM=128, BN=128, BK=8, 8x8 per thread, 256 threads.
template <int EPI>
__global__ void __launch_bounds__(256) sgemm_nt(
    const float* __restrict__ A, int lda,
    const float* __restrict__ B, int ldb,
    float* __restrict__ C, int ldc,
    int M, int N, int K,
    const float* __restrict__ bias)
{
    constexpr int BM = 128, BN = 128, BK = 8, TM = 8, TN = 8;
    __shared__ float As[BK][BM];
    __shared__ float Bs[BK][BN];

    const int tid = threadIdx.x;
    const int rowBase = blockIdx.y * BM;
    const int colBase = blockIdx.x * BN;
    const int ldRow = tid >> 1;           // 0..127
    const int c4 = (tid & 1) << 2;        // 0 or 4
    const int trow = tid >> 4;            // 0..15
    const int tcol = tid & 15;            // 0..15

    float acc[TM][TN];
#pragma unroll
    for (int i = 0; i < TM; i++)
#pragma unroll
        for (int j = 0; j < TN; j++) acc[i][j] = 0.f;

    for (int k0 = 0; k0 < K; k0 += BK) {
        float4 av = make_float4(0.f, 0.f, 0.f, 0.f);
        float4 bv = make_float4(0.f, 0.f, 0.f, 0.f);
        const int gr = rowBase + ldRow;
        if (gr < M)
            av = *reinterpret_cast<const float4*>(A + (size_t)gr * lda + k0 + c4);
        const int gn = colBase + ldRow;
        if (gn < N)
            bv = *reinterpret_cast<const float4*>(B + (size_t)gn * ldb + k0 + c4);
        As[c4 + 0][ldRow] = av.x; As[c4 + 1][ldRow] = av.y;
        As[c4 + 2][ldRow] = av.z; As[c4 + 3][ldRow] = av.w;
        Bs[c4 + 0][ldRow] = bv.x; Bs[c4 + 1][ldRow] = bv.y;
        Bs[c4 + 2][ldRow] = bv.z; Bs[c4 + 3][ldRow] = bv.w;
        __syncthreads();

#pragma unroll
        for (int kk = 0; kk < BK; kk++) {
            float4 a0 = *reinterpret_cast<const float4*>(&As[kk][trow * TM]);
            float4 a1 = *reinterpret_cast<const float4*>(&As[kk][trow * TM + 4]);
            float4 b0 = *reinterpret_cast<const float4*>(&Bs[kk][tcol * TN]);
            float4 b1 = *reinterpret_cast<const float4*>(&Bs[kk][tcol * TN + 4]);
            float ra[8] = {a0.x, a0.y, a0.z, a0.w, a1.x, a1.y, a1.z, a1.w};
            float rb[8] = {b0.x, b0.y, b0.z, b0.w, b1.x, b1.y, b1.z, b1.w};
#pragma unroll
            for (int i = 0; i < 8; i++)
#pragma unroll
                for (int j = 0; j < 8; j++)
                    acc[i][j] = fmaf(ra[i], rb[j], acc[i][j]);
        }
        __syncthreads();
    }

#pragma unroll
    for (int i = 0; i < TM; i++) {
        const int r = rowBase + trow * TM + i;
        if (r >= M) continue;
#pragma unroll
        for (int j = 0; j < TN; j++) {
            const int cidx = colBase + tcol * TN + j;
            if (cidx >= N) continue;
            float v = acc[i][j];
            if (EPI == 1) v = softplusf(v + bias[cidx]);
            C[(size_t)r * ldc + cidx] = v;
        }
    }
}

// ---------------- causal depthwise conv(4) + SiLU, and silu(z) ----------------
__global__ void conv_silu_kernel(
    const float* __restrict__ xz,
    const float* __restrict__ cw,
    const float* __restrict__ cb,
    float* __restrict__ xsc,
    float* __restrict__ zs)
{
    const int idx = blockIdx.x * blockDim.x + threadIdx.x;
    if (idx >= BL * D_INNER) return;
    const int e = idx % D_INNER;
    const int row = idx / D_INNER;   // row = b*SEQ + l
    const int l = row & (SEQ - 1);

    const float w0 = cw[e * 4 + 0];
    const float w1 = cw[e * 4 + 1];
    const float w2 = cw[e * 4 + 2];
    const float w3 = cw[e * 4 + 3];

    const float* base = xz + (size_t)row * (2 * D_INNER) + e;
    float acc = cb[e];
    acc = fmaf(w3, base[0], acc);
    if (l >= 1) acc = fmaf(w2, base[-(ptrdiff_t)(2 * D_INNER)], acc);
    if (l >= 2) acc = fmaf(w1, base[-(ptrdiff_t)(4 * D_INNER)], acc);
    if (l >= 3) acc = fmaf(w0, base[-(ptrdiff_t)(6 * D_INNER)], acc);
    xsc[idx] = siluf(acc);

    const float z = xz[(size_t)row * (2 * D_INNER) + D_INNER + e];
    zs[idx] = siluf(z);
}

// ---------------- selective scan (both directions via blockIdx.z) ----------------
// block: 512 threads = 32 channels (e) x 16 states (n); grid: (48, NB, 2)
__global__ void __launch_bounds__(512) scan_kernel(
    const float* __restrict__ delta_f, const float* __restrict__ delta_b,
    const float* __restrict__ dbc_f,  const float* __restrict__ dbc_b,
    const float* __restrict__ A_log,  const float* __restrict__ A_b_log,
    const float* __restrict__ xsc,
    float* __restrict__ y_f, float* __restrict__ y_b)
{
    const int dir = blockIdx.z;
    const int b = blockIdx.y;
    const int e0 = blockIdx.x * 32;
    const int t = threadIdx.x;
    const int el = t >> 4;   // 0..31 channel within tile
    const int n = t & 15;    // state index
    const int e = e0 + el;

    const float* delta = dir ? delta_b : delta_f;
    const float* dbc = dir ? dbc_b : dbc_f;
    const float* Alog = dir ? A_b_log : A_log;
    float* y = dir ? y_b : y_f;

    const float An = -__expf(Alog[e * D_STATE + n]);

    __shared__ float s_d[16 * 32];
    __shared__ float s_x[16 * 32];
    __shared__ float s_bc[16 * 32];
    __shared__ float s_y[16 * 32];

    const int lj = t >> 5;   // 0..15 (timestep within chunk, for loads)
    const int lc = t & 31;   // 0..31 (column within 32-wide load)

    float h = 0.f;
    const size_t rowb = (size_t)b * SEQ;

    for (int c = 0; c < SEQ / 16; c++) {
        {
            const int i = c * 16 + lj;
            const int l = dir ? (SEQ - 1 - i) : i;
            const size_t row = rowb + l;
            s_d[lj * 32 + lc]  = delta[row * D_INNER + e0 + lc];
            s_x[lj * 32 + lc]  = xsc[row * D_INNER + e0 + lc];
            s_bc[lj * 32 + lc] = dbc[row * DBC_N + DT_RANK + lc]; // B:0..15, C:16..31
        }
        __syncthreads();

#pragma unroll
        for (int j = 0; j < 16; j++) {
            const float dlt = s_d[j * 32 + el];
            const float xv  = s_x[j * 32 + el];
            const float Bv  = s_bc[j * 32 + n];
            const float Cv  = s_bc[j * 32 + 16 + n];
            const float dA = __expf(dlt * An);
            h = fmaf(dA, h, dlt * xv * Bv);
            float p = h * Cv;
            p += __shfl_xor_sync(0xffffffffu, p, 8);
            p += __shfl_xor_sync(0xffffffffu, p, 4);
            p += __shfl_xor_sync(0xffffffffu, p, 2);
            p += __shfl_xor_sync(0xffffffffu, p, 1);
            if (n == 0) s_y[j * 32 + el] = p;
        }
        __syncthreads();

        {
            const int i = c * 16 + lj;
            const int l = dir ? (SEQ - 1 - i) : i;
            y[(rowb + l) * D_INNER + e0 + lc] = s_y[lj * 32 + lc];
        }
        // no extra barrier needed: next chunk's loads touch s_d/s_x/s_bc only,
        // and the top-of-loop barrier orders them before the next compute.
    }
}

// ---------------- fuse: u = (y_f + y_b + (D + D_b) * xs) * silu(z) ----------------
__global__ void fuse_kernel(
    const float* __restrict__ yf, const float* __restrict__ yb,
    const float* __restrict__ xsc, const float* __restrict__ zs,
    const float* __restrict__ D1, const float* __restrict__ D2,
    float* __restrict__ u)
{
    const int idx = blockIdx.x * blockDim.x + threadIdx.x;
    if (idx >= BL * D_INNER) return;
    const int e = idx % D_INNER;
    const float v = yf[idx] + yb[idx] + (D1[e] + D2[e]) * xsc[idx];
    u[idx] = v * zs[idx];
}

// ---------------- launcher ----------------
extern "C" void kernel_launch(void* const* d_in, const int* in_sizes, int n_in,
                              void* d_out, int out_size)
{
    const float* x          = (const float*)d_in[0];   // [2,1024,768]
    const float* in_proj_w  = (const float*)d_in[1];   // [3072,768]
    const float* conv_w     = (const float*)d_in[2];   // [1536,4]
    const float* conv_bias  = (const float*)d_in[3];   // [1536]
    const float* x_proj_w   = (const float*)d_in[4];   // [80,1536]
    const float* dt_proj_w  = (const float*)d_in[5];   // [1536,48]
    const float* dt_proj_b  = (const float*)d_in[6];   // [1536]
    const float* A_log      = (const float*)d_in[7];   // [1536,16]
    const float* D_param    = (const float*)d_in[8];   // [1536]
    const float* out_proj_w = (const float*)d_in[9];   // [768,1536]
    const float* A_b_log    = (const float*)d_in[10];  // [1536,16]
    const float* x_proj_b_w = (const float*)d_in[11];  // [80,1536]
    const float* dt_proj_b_w= (const float*)d_in[12];  // [1536,48]
    const float* dt_proj_b_b= (const float*)d_in[13];  // [1536]
    const float* D_b        = (const float*)d_in[14];  // [1536]
    float* out = (float*)d_out;                        // [2,1024,768]

    float *p_xz, *p_xsc, *p_zs, *p_dbc_f, *p_dbc_b;
    float *p_delta_f, *p_delta_b, *p_y_f, *p_y_b, *p_u;
    cudaGetSymbolAddress((void**)&p_xz, g_xz);
    cudaGetSymbolAddress((void**)&p_xsc, g_xsc);
    cudaGetSymbolAddress((void**)&p_zs, g_zs);
    cudaGetSymbolAddress((void**)&p_dbc_f, g_dbc_f);
    cudaGetSymbolAddress((void**)&p_dbc_b, g_dbc_b);
    cudaGetSymbolAddress((void**)&p_delta_f, g_delta_f);
    cudaGetSymbolAddress((void**)&p_delta_b, g_delta_b);
    cudaGetSymbolAddress((void**)&p_y_f, g_y_f);
    cudaGetSymbolAddress((void**)&p_y_b, g_y_b);
    cudaGetSymbolAddress((void**)&p_u, g_u);

    // 1) xz = x @ in_proj_w^T : [2048, 3072]
    sgemm_nt<0><<<dim3((2 * D_INNER) / 128, BL / 128), 256>>>(
        x, D_MODEL, in_proj_w, D_MODEL, p_xz, 2 * D_INNER,
        BL, 2 * D_INNER, D_MODEL, nullptr);

    // 2) causal conv + silu, silu(z)
    conv_silu_kernel<<<(BL * D_INNER + 255) / 256, 256>>>(
        p_xz, conv_w, conv_bias, p_xsc, p_zs);

    // 3) dbc_f = xs @ x_proj_w^T : [2048, 80]
    sgemm_nt<0><<<dim3(1, BL / 128), 256>>>(
        p_xsc, D_INNER, x_proj_w, D_INNER, p_dbc_f, DBC_N,
        BL, DBC_N, D_INNER, nullptr);

    // 4) dbc_b = xs @ x_proj_b_w^T
    sgemm_nt<0><<<dim3(1, BL / 128), 256>>>(
        p_xsc, D_INNER, x_proj_b_w, D_INNER, p_dbc_b, DBC_N,
        BL, DBC_N, D_INNER, nullptr);

    // 5) delta_f = softplus(dbc_f[:, :48] @ dt_proj_w^T + dt_proj_b) : [2048, 1536]
    sgemm_nt<1><<<dim3(D_INNER / 128, BL / 128), 256>>>(
        p_dbc_f, DBC_N, dt_proj_w, DT_RANK, p_delta_f, D_INNER,
        BL, D_INNER, DT_RANK, dt_proj_b);

    // 6) delta_b
    sgemm_nt<1><<<dim3(D_INNER / 128, BL / 128), 256>>>(
        p_dbc_b, DBC_N, dt_proj_b_w, DT_RANK, p_delta_b, D_INNER,
        BL, D_INNER, DT_RANK, dt_proj_b_b);

    // 7) selective scan, both directions
    scan_kernel<<<dim3(D_INNER / 32, NB, 2), 512>>>(
        p_delta_f, p_delta_b, p_dbc_f, p_dbc_b,
        A_log, A_b_log, p_xsc, p_y_f, p_y_b);

    // 8) fuse: u = (y_f + y_b + (D + D_b) * xs) * silu(z)
    fuse_kernel<<<(BL * D_INNER + 255) / 256, 256>>>(
        p_y_f, p_y_b, p_xsc, p_zs, D_param, D_b, p_u);

    // 9) out = u @ out_proj_w^T : [2048, 768]
    sgemm_nt<0><<<dim3(D_MODEL / 128, BL / 128), 256>>>(
        p_u, D_INNER, out_proj_w, D_INNER, out, D_MODEL,
        BL, D_MODEL, D_INNER, nullptr);
}

// round 2
// speedup vs baseline: 1.6854x; 1.6854x over previous
#include <cuda_runtime.h>
#include <cstddef>

// ---------------- problem constants ----------------
#define D_MODEL 768
#define D_INNER 1536
#define D_STATE 16
#define DT_RANK 48
#define NB 2
#define SEQ 1024
#define BL (NB * SEQ)                 // 2048
#define DBC_N (DT_RANK + 2 * D_STATE) // 80

// ---------------- scratch (static __device__ arrays; no allocs) ----------------
__device__ float g_xz[BL * 2 * D_INNER];     // in_proj output [2048, 3072]
__device__ float g_xsc[BL * D_INNER];        // conv+silu output
__device__ float g_zs[BL * D_INNER];         // silu(z)
__device__ float g_dbc_f[BL * DBC_N];
__device__ float g_dbc_b[BL * DBC_N];
__device__ float g_delta_f[BL * D_INNER];
__device__ float g_delta_b[BL * D_INNER];
__device__ float g_y_f[BL * D_INNER];
__device__ float g_y_b[BL * D_INNER];
__device__ float g_u[BL * D_INNER];

// ---------------- math helpers ----------------
__device__ __forceinline__ float siluf(float x) {
    return x / (1.f + __expf(-x));
}
__device__ __forceinline__ float softplusf(float x) {
    return (x > 20.f) ? x : log1pf(__expf(x));
}

// ---------------- SGEMM: C[M,N] = A[M,K] * B[N,K]^T, double-buffered ----------------
// BM=128, BN=128, BK=8, 8x8 per thread, 256 threads. All dims assumed to divide
// the tile sizes exactly (true for every GEMM in this problem).
// Optional second problem selected by blockIdx.z (A2/B2/C2/bias2).
template <int EPI>
__global__ void __launch_bounds__(256) sgemm_nt(
    const float* __restrict__ A, int lda,
    const float* __restrict__ B, int ldb,
    float* __restrict__ C, int ldc,
    int K,
    const float* __restrict__ bias,
    const float* __restrict__ A2,
    const float* __restrict__ B2,
    float* __restrict__ C2,
    const float* __restrict__ bias2)
{
    if (blockIdx.z == 1) { A = A2; B = B2; C = C2; bias = bias2; }

    constexpr int BM = 128, BN = 128, BK = 8, TM = 8, TN = 8;
    __shared__ float As[2][BK][BM];
    __shared__ float Bs[2][BK][BN];

    const int tid = threadIdx.x;
    const int rowBase = blockIdx.y * BM;
    const int colBase = blockIdx.x * BN;
    const int ldRow = tid >> 1;           // 0..127
    const int c4 = (tid & 1) << 2;        // 0 or 4
    const int trow = tid >> 4;            // 0..15
    const int tcol = tid & 15;            // 0..15

    const float* Aptr = A + (size_t)(rowBase + ldRow) * lda + c4;
    const float* Bptr = B + (size_t)(colBase + ldRow) * ldb + c4;

    float acc[TM][TN];
#pragma unroll
    for (int i = 0; i < TM; i++)
#pragma unroll
        for (int j = 0; j < TN; j++) acc[i][j] = 0.f;

    // prologue: load tile 0 into buffer 0
    {
        float4 av = *reinterpret_cast<const float4*>(Aptr);
        float4 bv = *reinterpret_cast<const float4*>(Bptr);
        As[0][c4 + 0][ldRow] = av.x; As[0][c4 + 1][ldRow] = av.y;
        As[0][c4 + 2][ldRow] = av.z; As[0][c4 + 3][ldRow] = av.w;
        Bs[0][c4 + 0][ldRow] = bv.x; Bs[0][c4 + 1][ldRow] = bv.y;
        Bs[0][c4 + 2][ldRow] = bv.z; Bs[0][c4 + 3][ldRow] = bv.w;
    }
    __syncthreads();

    int buf = 0;
    for (int k0 = BK; k0 <= K; k0 += BK) {
        float4 av, bv;
        const bool more = (k0 < K);
        if (more) {
            av = *reinterpret_cast<const float4*>(Aptr + k0);
            bv = *reinterpret_cast<const float4*>(Bptr + k0);
        }

#pragma unroll
        for (int kk = 0; kk < BK; kk++) {
            float4 a0 = *reinterpret_cast<const float4*>(&As[buf][kk][trow * TM]);
            float4 a1 = *reinterpret_cast<const float4*>(&As[buf][kk][trow * TM + 4]);
            float4 b0 = *reinterpret_cast<const float4*>(&Bs[buf][kk][tcol * TN]);
            float4 b1 = *reinterpret_cast<const float4*>(&Bs[buf][kk][tcol * TN + 4]);
            float ra[8] = {a0.x, a0.y, a0.z, a0.w, a1.x, a1.y, a1.z, a1.w};
            float rb[8] = {b0.x, b0.y, b0.z, b0.w, b1.x, b1.y, b1.z, b1.w};
#pragma unroll
            for (int i = 0; i < 8; i++)
#pragma unroll
                for (int j = 0; j < 8; j++)
                    acc[i][j] = fmaf(ra[i], rb[j], acc[i][j]);
        }

        if (more) {
            const int nb = buf ^ 1;
            As[nb][c4 + 0][ldRow] = av.x; As[nb][c4 + 1][ldRow] = av.y;
            As[nb][c4 + 2][ldRow] = av.z; As[nb][c4 + 3][ldRow] = av.w;
            Bs[nb][c4 + 0][ldRow] = bv.x; Bs[nb][c4 + 1][ldRow] = bv.y;
            Bs[nb][c4 + 2][ldRow] = bv.z; Bs[nb][c4 + 3][ldRow] = bv.w;
        }
        __syncthreads();
        buf ^= 1;
    }

    // epilogue: vectorized float4 stores
#pragma unroll
    for (int i = 0; i < TM; i++) {
        const int r = rowBase + trow * TM + i;
        float* Crow = C + (size_t)r * ldc + colBase + tcol * TN;
#pragma unroll
        for (int g = 0; g < 2; g++) {
            float4 v;
            float vv[4];
#pragma unroll
            for (int q = 0; q < 4; q++) {
                float t = acc[i][g * 4 + q];
                if (EPI == 1) {
                    const int cidx = colBase + tcol * TN + g * 4 + q;
                    t = softplusf(t + bias[cidx]);
                }
                vv[q] = t;
            }
            v.x = vv[0]; v.y = vv[1]; v.z = vv[2]; v.w = vv[3];
            *reinterpret_cast<float4*>(Crow + g * 4) = v;
        }
    }
}

// ---------------- x_proj: dbc[M,80] = xs[M,1536] @ W[80,1536]^T, both dirs ----------------
// grid (M/32, 2), 256 threads. Thread tile 2 rows x 5 cols.
__global__ void __launch_bounds__(256) xproj_kernel(
    const float* __restrict__ xsc,
    const float* __restrict__ w_f, const float* __restrict__ w_b,
    float* __restrict__ dbc_f, float* __restrict__ dbc_b)
{
    const int dir = blockIdx.y;
    const float* W = dir ? w_b : w_f;
    float* C = dir ? dbc_b : dbc_f;
    const int m0 = blockIdx.x * 32;
    const int tid = threadIdx.x;
    const int trow = tid >> 4;   // 0..15
    const int tcol = tid & 15;   // 0..15

    constexpr int BK = 32;
    __shared__ float As[BK][32];
    __shared__ float Bs[BK][80];

    float acc0[5] = {0.f, 0.f, 0.f, 0.f, 0.f};
    float acc1[5] = {0.f, 0.f, 0.f, 0.f, 0.f};

    const int arow = tid >> 3;          // 0..31
    const int ac4 = (tid & 7) << 2;     // 0..28

    for (int k0 = 0; k0 < D_INNER; k0 += BK) {
        // A tile: 32 rows x 32 cols (one float4 per thread)
        {
            float4 v = *reinterpret_cast<const float4*>(
                xsc + (size_t)(m0 + arow) * D_INNER + k0 + ac4);
            As[ac4 + 0][arow] = v.x; As[ac4 + 1][arow] = v.y;
            As[ac4 + 2][arow] = v.z; As[ac4 + 3][arow] = v.w;
        }
        // B tile: 80 rows x 32 cols = 640 float4 over 256 threads
#pragma unroll
        for (int i = 0; i < 3; i++) {
            const int idx = tid + 256 * i;
            if (idx < 640) {
                const int n = idx >> 3;
                const int bc4 = (idx & 7) << 2;
                float4 v = *reinterpret_cast<const float4*>(
                    W + (size_t)n * D_INNER + k0 + bc4);
                Bs[bc4 + 0][n] = v.x; Bs[bc4 + 1][n] = v.y;
                Bs[bc4 + 2][n] = v.z; Bs[bc4 + 3][n] = v.w;
            }
        }
        __syncthreads();

#pragma unroll
        for (int kk = 0; kk < BK; kk++) {
            const float a0 = As[kk][trow * 2];
            const float a1 = As[kk][trow * 2 + 1];
#pragma unroll
            for (int j = 0; j < 5; j++) {
                const float b = Bs[kk][tcol + 16 * j];
                acc0[j] = fmaf(a0, b, acc0[j]);
                acc1[j] = fmaf(a1, b, acc1[j]);
            }
        }
        __syncthreads();
    }

    const int r0 = m0 + trow * 2;
#pragma unroll
    for (int j = 0; j < 5; j++) {
        C[(size_t)r0 * DBC_N + tcol + 16 * j] = acc0[j];
        C[(size_t)(r0 + 1) * DBC_N + tcol + 16 * j] = acc1[j];
    }
}

// ---------------- causal depthwise conv(4) + SiLU, and silu(z) ----------------
__global__ void conv_silu_kernel(
    const float* __restrict__ xz,
    const float* __restrict__ cw,
    const float* __restrict__ cb,
    float* __restrict__ xsc,
    float* __restrict__ zs)
{
    const int idx = blockIdx.x * blockDim.x + threadIdx.x;
    if (idx >= BL * D_INNER) return;
    const int e = idx % D_INNER;
    const int row = idx / D_INNER;   // row = b*SEQ + l
    const int l = row & (SEQ - 1);

    const float w0 = cw[e * 4 + 0];
    const float w1 = cw[e * 4 + 1];
    const float w2 = cw[e * 4 + 2];
    const float w3 = cw[e * 4 + 3];

    const float* base = xz + (size_t)row * (2 * D_INNER) + e;
    float acc = cb[e];
    acc = fmaf(w3, base[0], acc);
    if (l >= 1) acc = fmaf(w2, base[-(ptrdiff_t)(2 * D_INNER)], acc);
    if (l >= 2) acc = fmaf(w1, base[-(ptrdiff_t)(4 * D_INNER)], acc);
    if (l >= 3) acc = fmaf(w0, base[-(ptrdiff_t)(6 * D_INNER)], acc);
    xsc[idx] = siluf(acc);

    const float z = xz[(size_t)row * (2 * D_INNER) + D_INNER + e];
    zs[idx] = siluf(z);
}

// ---------------- selective scan (both directions via blockIdx.z) ----------------
// block: 512 threads = 32 channels (e) x 16 states (n); grid: (48, NB, 2)
__global__ void __launch_bounds__(512) scan_kernel(
    const float* __restrict__ delta_f, const float* __restrict__ delta_b,
    const float* __restrict__ dbc_f,  const float* __restrict__ dbc_b,
    const float* __restrict__ A_log,  const float* __restrict__ A_b_log,
    const float* __restrict__ xsc,
    float* __restrict__ y_f, float* __restrict__ y_b)
{
    const int dir = blockIdx.z;
    const int b = blockIdx.y;
    const int e0 = blockIdx.x * 32;
    const int t = threadIdx.x;
    const int el = t >> 4;   // 0..31 channel within tile
    const int n = t & 15;    // state index
    const int e = e0 + el;

    const float* delta = dir ? delta_b : delta_f;
    const float* dbc = dir ? dbc_b : dbc_f;
    const float* Alog = dir ? A_b_log : A_log;
    float* y = dir ? y_b : y_f;

    const float An = -__expf(Alog[e * D_STATE + n]);

    __shared__ float s_d[16 * 32];
    __shared__ float s_x[16 * 32];
    __shared__ float s_bc[16 * 32];
    __shared__ float s_y[16 * 32];

    const int lj = t >> 5;   // 0..15 (timestep within chunk, for loads)
    const int lc = t & 31;   // 0..31 (column within 32-wide load)

    float h = 0.f;
    const size_t rowb = (size_t)b * SEQ;

    for (int c = 0; c < SEQ / 16; c++) {
        {
            const int i = c * 16 + lj;
            const int l = dir ? (SEQ - 1 - i) : i;
            const size_t row = rowb + l;
            s_d[lj * 32 + lc]  = delta[row * D_INNER + e0 + lc];
            s_x[lj * 32 + lc]  = xsc[row * D_INNER + e0 + lc];
            s_bc[lj * 32 + lc] = dbc[row * DBC_N + DT_RANK + lc]; // B:0..15, C:16..31
        }
        __syncthreads();

#pragma unroll
        for (int j = 0; j < 16; j++) {
            const float dlt = s_d[j * 32 + el];
            const float xv  = s_x[j * 32 + el];
            const float Bv  = s_bc[j * 32 + n];
            const float Cv  = s_bc[j * 32 + 16 + n];
            const float dA = __expf(dlt * An);
            h = fmaf(dA, h, dlt * xv * Bv);
            float p = h * Cv;
            p += __shfl_xor_sync(0xffffffffu, p, 8);
            p += __shfl_xor_sync(0xffffffffu, p, 4);
            p += __shfl_xor_sync(0xffffffffu, p, 2);
            p += __shfl_xor_sync(0xffffffffu, p, 1);
            if (n == 0) s_y[j * 32 + el] = p;
        }
        __syncthreads();

        {
            const int i = c * 16 + lj;
            const int l = dir ? (SEQ - 1 - i) : i;
            y[(rowb + l) * D_INNER + e0 + lc] = s_y[lj * 32 + lc];
        }
    }
}

// ---------------- fuse: u = (y_f + y_b + (D + D_b) * xs) * silu(z), float4 ----------------
__global__ void fuse_kernel(
    const float* __restrict__ yf, const float* __restrict__ yb,
    const float* __restrict__ xsc, const float* __restrict__ zs,
    const float* __restrict__ D1, const float* __restrict__ D2,
    float* __restrict__ u)
{
    const int idx4 = blockIdx.x * blockDim.x + threadIdx.x;
    if (idx4 >= (BL * D_INNER) / 4) return;
    const int e4 = (idx4 * 4) % D_INNER;

    const float4 a = *reinterpret_cast<const float4*>(yf + idx4 * 4);
    const float4 bq = *reinterpret_cast<const float4*>(yb + idx4 * 4);
    const float4 xv = *reinterpret_cast<const float4*>(xsc + idx4 * 4);
    const float4 zv = *reinterpret_cast<const float4*>(zs + idx4 * 4);
    const float4 d1 = *reinterpret_cast<const float4*>(D1 + e4);
    const float4 d2 = *reinterpret_cast<const float4*>(D2 + e4);

    float4 r;
    r.x = (a.x + bq.x + (d1.x + d2.x) * xv.x) * zv.x;
    r.y = (a.y + bq.y + (d1.y + d2.y) * xv.y) * zv.y;
    r.z = (a.z + bq.z + (d1.z + d2.z) * xv.z) * zv.z;
    r.w = (a.w + bq.w + (d1.w + d2.w) * xv.w) * zv.w;
    *reinterpret_cast<float4*>(u + idx4 * 4) = r;
}

// ---------------- launcher ----------------
extern "C" void kernel_launch(void* const* d_in, const int* in_sizes, int n_in,
                              void* d_out, int out_size)
{
    const float* x          = (const float*)d_in[0];   // [2,1024,768]
    const float* in_proj_w  = (const float*)d_in[1];   // [3072,768]
    const float* conv_w     = (const float*)d_in[2];   // [1536,4]
    const float* conv_bias  = (const float*)d_in[3];   // [1536]
    const float* x_proj_w   = (const float*)d_in[4];   // [80,1536]
    const float* dt_proj_w  = (const float*)d_in[5];   // [1536,48]
    const float* dt_proj_b  = (const float*)d_in[6];   // [1536]
    const float* A_log      = (const float*)d_in[7];   // [1536,16]
    const float* D_param    = (const float*)d_in[8];   // [1536]
    const float* out_proj_w = (const float*)d_in[9];   // [768,1536]
    const float* A_b_log    = (const float*)d_in[10];  // [1536,16]
    const float* x_proj_b_w = (const float*)d_in[11];  // [80,1536]
    const float* dt_proj_b_w= (const float*)d_in[12];  // [1536,48]
    const float* dt_proj_b_b= (const float*)d_in[13];  // [1536]
    const float* D_b        = (const float*)d_in[14];  // [1536]
    float* out = (float*)d_out;                        // [2,1024,768]

    float *p_xz, *p_xsc, *p_zs, *p_dbc_f, *p_dbc_b;
    float *p_delta_f, *p_delta_b, *p_y_f, *p_y_b, *p_u;
    cudaGetSymbolAddress((void**)&p_xz, g_xz);
    cudaGetSymbolAddress((void**)&p_xsc, g_xsc);
    cudaGetSymbolAddress((void**)&p_zs, g_zs);
    cudaGetSymbolAddress((void**)&p_dbc_f, g_dbc_f);
    cudaGetSymbolAddress((void**)&p_dbc_b, g_dbc_b);
    cudaGetSymbolAddress((void**)&p_delta_f, g_delta_f);
    cudaGetSymbolAddress((void**)&p_delta_b, g_delta_b);
    cudaGetSymbolAddress((void**)&p_y_f, g_y_f);
    cudaGetSymbolAddress((void**)&p_y_b, g_y_b);
    cudaGetSymbolAddress((void**)&p_u, g_u);

    // 1) xz = x @ in_proj_w^T : [2048, 3072]
    sgemm_nt<0><<<dim3((2 * D_INNER) / 128, BL / 128, 1), 256>>>(
        x, D_MODEL, in_proj_w, D_MODEL, p_xz, 2 * D_INNER,
        D_MODEL, nullptr, nullptr, nullptr, nullptr, nullptr);

    // 2) causal conv + silu, silu(z)
    conv_silu_kernel<<<(BL * D_INNER + 255) / 256, 256>>>(
        p_xz, conv_w, conv_bias, p_xsc, p_zs);

    // 3+4) dbc_{f,b} = xs @ x_proj_{f,b}^T : [2048, 80] each, one launch
    xproj_kernel<<<dim3(BL / 32, 2), 256>>>(
        p_xsc, x_proj_w, x_proj_b_w, p_dbc_f, p_dbc_b);

    // 5+6) delta_{f,b} = softplus(dbc_{f,b}[:, :48] @ dt_proj_{f,b}^T + bias), one launch
    sgemm_nt<1><<<dim3(D_INNER / 128, BL / 128, 2), 256>>>(
        p_dbc_f, DBC_N, dt_proj_w, DT_RANK, p_delta_f, D_INNER,
        DT_RANK, dt_proj_b,
        p_dbc_b, dt_proj_b_w, p_delta_b, dt_proj_b_b);

    // 7) selective scan, both directions
    scan_kernel<<<dim3(D_INNER / 32, NB, 2), 512>>>(
        p_delta_f, p_delta_b, p_dbc_f, p_dbc_b,
        A_log, A_b_log, p_xsc, p_y_f, p_y_b);

    // 8) fuse: u = (y_f + y_b + (D + D_b) * xs) * silu(z)
    fuse_kernel<<<(BL * D_INNER / 4 + 255) / 256, 256>>>(
        p_y_f, p_y_b, p_xsc, p_zs, D_param, D_b, p_u);

    // 9) out = u @ out_proj_w^T : [2048, 768]
    sgemm_nt<0><<<dim3(D_MODEL / 128, BL / 128, 1), 256>>>(
        p_u, D_INNER, out_proj_w, D_INNER, out, D_MODEL,
        D_INNER, nullptr, nullptr, nullptr, nullptr, nullptr);
}

// round 4
// speedup vs baseline: 2.6211x; 1.5552x over previous
#include <cuda_runtime.h>
#include <cuda_bf16.h>
#include <cstdint>
#include <cstddef>

// ---------------- problem constants ----------------
#define D_MODEL 768
#define D_INNER 1536
#define D_STATE 16
#define DT_RANK 48
#define NB 2
#define SEQ 1024
#define BL (NB * SEQ)                 // 2048
#define DBC_N (DT_RANK + 2 * D_STATE) // 80
#define KIN  D_MODEL                  // 768
#define KIN3 (3 * KIN)                // 2304
#define KOUT D_INNER                  // 1536
#define KOUT3 (3 * KOUT)              // 4608

// ---------------- scratch (static __device__ arrays; no allocs) ----------------
__device__ float g_xz[BL * 2 * D_INNER];
__device__ float g_xsc[BL * D_INNER];
__device__ float g_zs[BL * D_INNER];
__device__ float g_dbc_f[BL * DBC_N];
__device__ float g_dbc_b[BL * DBC_N];
__device__ float g_delta_f[BL * D_INNER];
__device__ float g_delta_b[BL * D_INNER];
__device__ float g_y_f[BL * D_INNER];
__device__ float g_y_b[BL * D_INNER];
__device__ __nv_bfloat16 g_ax[BL * KIN3];              // x split (hi|hi|lo)
__device__ __nv_bfloat16 g_wi[2 * D_INNER * KIN3];     // in_proj_w split (hi|lo|hi)
__device__ __nv_bfloat16 g_u3[BL * KOUT3];             // u split (hi|hi|lo)
__device__ __nv_bfloat16 g_wo[D_MODEL * KOUT3];        // out_proj_w split (hi|lo|hi)

// ---------------- math helpers ----------------
__device__ __forceinline__ float siluf(float x) { return x / (1.f + __expf(-x)); }
__device__ __forceinline__ float softplusf(float x) {
    return (x > 20.f) ? x : log1pf(__expf(x));
}

__device__ __forceinline__ uint32_t smem_u32(const void* p) {
    uint32_t a;
    asm("{ .reg .u64 t; cvta.to.shared.u64 t, %1; cvt.u32.u64 %0, t; }" : "=r"(a) : "l"(p));
    return a;
}
__device__ __forceinline__ void cp_async16(uint32_t saddr, const void* g) {
    asm volatile("cp.async.cg.shared.global [%0], [%1], 16;" :: "r"(saddr), "l"(g));
}
__device__ __forceinline__ void cp_commit() {
    asm volatile("cp.async.commit_group;" ::: "memory");
}
__device__ __forceinline__ void ldm_x4(uint32_t& r0, uint32_t& r1, uint32_t& r2,
                                       uint32_t& r3, uint32_t addr) {
    asm volatile("ldmatrix.sync.aligned.m8n8.x4.shared.b16 {%0,%1,%2,%3}, [%4];"
                 : "=r"(r0), "=r"(r1), "=r"(r2), "=r"(r3) : "r"(addr));
}
__device__ __forceinline__ void mma_bf16(float* c, const uint32_t* a, const uint32_t* b) {
    asm volatile(
        "mma.sync.aligned.m16n8k16.row.col.f32.bf16.bf16.f32 "
        "{%0,%1,%2,%3}, {%4,%5,%6,%7}, {%8,%9}, {%0,%1,%2,%3};"
        : "+f"(c[0]), "+f"(c[1]), "+f"(c[2]), "+f"(c[3])
        : "r"(a[0]), "r"(a[1]), "r"(a[2]), "r"(a[3]), "r"(b[0]), "r"(b[1]));
}

// ---------------- HMMA bf16 GEMM: C[M,N] = A'[M,Kp] * B'[N,Kp]^T ----------------
// BM=BN=128, BK=32 bf16, 8 warps (4M x 2N), warp tile 32x64,
// 4-stage cp.async pipeline, 80B-padded smem rows (conflict-free ldmatrix).
// grid (N/128, M/128), 256 threads, dynamic smem 81920B.
#define ROWB 80
#define STAGE_BYTES 20480
#define OFFB 10240
__global__ void __launch_bounds__(256) hmma_bf16_nt(
    const __nv_bfloat16* __restrict__ A,
    const __nv_bfloat16* __restrict__ B,
    float* __restrict__ C, int ldc, int Kp, int nChunks)
{
    extern __shared__ char smem[];
    const uint32_t sb = smem_u32(smem);
    const int tid = threadIdx.x;
    const int rowBase = blockIdx.y * 128;
    const int colBase = blockIdx.x * 128;

    // per-thread global->smem load slots (2 x 16B for A, 2 x 16B for B per stage)
    const int r0 = tid >> 2, c0 = tid & 3;
    const int r1 = (tid + 256) >> 2, c1 = (tid + 256) & 3;
    const char* gA0 = (const char*)(A + (size_t)(rowBase + r0) * Kp + c0 * 8);
    const char* gA1 = (const char*)(A + (size_t)(rowBase + r1) * Kp + c1 * 8);
    const char* gB0 = (const char*)(B + (size_t)(colBase + r0) * Kp + c0 * 8);
    const char* gB1 = (const char*)(B + (size_t)(colBase + r1) * Kp + c1 * 8);
    const uint32_t sA0 = r0 * ROWB + c0 * 16, sA1 = r1 * ROWB + c1 * 16;
    const uint32_t sB0 = OFFB + sA0, sB1 = OFFB + sA1;

#define LOAD_STAGE(c) do {                                                  \
    const uint32_t _base = sb + ((c) & 3) * STAGE_BYTES;                    \
    const size_t _gk = (size_t)(c) * 64;                                    \
    cp_async16(_base + sA0, gA0 + _gk);                                     \
    cp_async16(_base + sA1, gA1 + _gk);                                     \
    cp_async16(_base + sB0, gB0 + _gk);                                     \
    cp_async16(_base + sB1, gB1 + _gk);                                     \
} while (0)

    const int wid = tid >> 5;
    const int l = tid & 31;
    const int wm = wid & 3;       // 0..3 (M)
    const int wn = wid >> 2;      // 0..1 (N)

    // ldmatrix lane offsets
    const int a_row = ((l >> 3) & 1) * 8 + (l & 7);
    const int a_k   = (l >> 4) * 8;
    const int b_n   = (l >> 4) * 8 + (l & 7);
    const int b_k   = ((l >> 3) & 1) * 8;

    float acc[2][8][4];
#pragma unroll
    for (int i = 0; i < 2; i++)
#pragma unroll
        for (int j = 0; j < 8; j++)
#pragma unroll
            for (int q = 0; q < 4; q++) acc[i][j][q] = 0.f;

    LOAD_STAGE(0); cp_commit();
    LOAD_STAGE(1); cp_commit();
    LOAD_STAGE(2); cp_commit();

    for (int c = 0; c < nChunks; c++) {
        asm volatile("cp.async.wait_group 2;" ::: "memory");
        __syncthreads();

        const uint32_t stb = sb + (c & 3) * STAGE_BYTES;
        const uint32_t aW = stb + (wm * 32) * ROWB;
        const uint32_t bW = stb + OFFB + (wn * 64) * ROWB;

#pragma unroll
        for (int ks = 0; ks < 2; ks++) {
            uint32_t a[2][4];
#pragma unroll
            for (int mi = 0; mi < 2; mi++)
                ldm_x4(a[mi][0], a[mi][1], a[mi][2], a[mi][3],
                       aW + (mi * 16 + a_row) * ROWB + (ks * 16 + a_k) * 2);
            uint32_t b[8][2];
#pragma unroll
            for (int nf = 0; nf < 4; nf++) {
                uint32_t q0, q1, q2, q3;
                ldm_x4(q0, q1, q2, q3,
                       bW + (nf * 16 + b_n) * ROWB + (ks * 16 + b_k) * 2);
                b[nf * 2][0] = q0; b[nf * 2][1] = q1;
                b[nf * 2 + 1][0] = q2; b[nf * 2 + 1][1] = q3;
            }
#pragma unroll
            for (int mi = 0; mi < 2; mi++)
#pragma unroll
                for (int nb = 0; nb < 8; nb++)
                    mma_bf16(acc[mi][nb], a[mi], b[nb]);
        }
        __syncthreads();
        if (c + 3 < nChunks) LOAD_STAGE(c + 3);
        cp_commit();
    }

    // epilogue: direct float2 stores
    const int lrow = l >> 2;
    const int lcol = (l & 3) * 2;
#pragma unroll
    for (int mi = 0; mi < 2; mi++) {
        const int grow = rowBase + wm * 32 + mi * 16 + lrow;
#pragma unroll
        for (int nb = 0; nb < 8; nb++) {
            const int gcol = colBase + wn * 64 + nb * 8 + lcol;
            float2 v0 = make_float2(acc[mi][nb][0], acc[mi][nb][1]);
            float2 v1 = make_float2(acc[mi][nb][2], acc[mi][nb][3]);
            *(float2*)(C + (size_t)grow * ldc + gcol) = v0;
            *(float2*)(C + (size_t)(grow + 8) * ldc + gcol) = v1;
        }
    }
#undef LOAD_STAGE
}

// ---------------- split fp32 -> bf16 triple ----------------
// MODEB=0: (hi|hi|lo) for A operands; MODEB=1: (hi|lo|hi) for B operands.
template <int MODEB>
__global__ void split3_kernel(const float* __restrict__ src,
                              __nv_bfloat16* __restrict__ dst, int RK, int K)
{
    const int i4 = blockIdx.x * blockDim.x + threadIdx.x;
    if (i4 * 4 >= RK) return;
    const float4 v = *(const float4*)(src + (size_t)i4 * 4);
    const int r = (i4 * 4) / K;
    const int k = (i4 * 4) % K;
    float vv[4] = {v.x, v.y, v.z, v.w};
    unsigned short hs[4], ls[4];
#pragma unroll
    for (int j = 0; j < 4; j++) {
        __nv_bfloat16 h = __float2bfloat16(vv[j]);
        __nv_bfloat16 lo = __float2bfloat16(vv[j] - __bfloat162float(h));
        hs[j] = __bfloat16_as_ushort(h);
        ls[j] = __bfloat16_as_ushort(lo);
    }
    const ushort4 H = make_ushort4(hs[0], hs[1], hs[2], hs[3]);
    const ushort4 L = make_ushort4(ls[0], ls[1], ls[2], ls[3]);
    const size_t base = (size_t)r * (3 * K) + k;
    *(ushort4*)((unsigned short*)dst + base) = H;
    *(ushort4*)((unsigned short*)dst + base + K) = MODEB ? L : H;
    *(ushort4*)((unsigned short*)dst + base + 2 * K) = MODEB ? H : L;
}

// ---------------- SGEMM (fp32) for dt_proj: softplus epilogue ----------------
template <int EPI>
__global__ void __launch_bounds__(256) sgemm_nt(
    const float* __restrict__ A, int lda,
    const float* __restrict__ B, int ldb,
    float* __restrict__ C, int ldc,
    int K, const float* __restrict__ bias,
    const float* __restrict__ A2, const float* __restrict__ B2,
    float* __restrict__ C2, const float* __restrict__ bias2)
{
    if (blockIdx.z == 1) { A = A2; B = B2; C = C2; bias = bias2; }
    constexpr int BK = 8, TM = 8, TN = 8;
    __shared__ float As[2][BK][128];
    __shared__ float Bs[2][BK][128];
    const int tid = threadIdx.x;
    const int rowBase = blockIdx.y * 128;
    const int colBase = blockIdx.x * 128;
    const int ldRow = tid >> 1;
    const int c4 = (tid & 1) << 2;
    const int trow = tid >> 4;
    const int tcol = tid & 15;
    const float* Aptr = A + (size_t)(rowBase + ldRow) * lda + c4;
    const float* Bptr = B + (size_t)(colBase + ldRow) * ldb + c4;
    float acc[TM][TN];
#pragma unroll
    for (int i = 0; i < TM; i++)
#pragma unroll
        for (int j = 0; j < TN; j++) acc[i][j] = 0.f;
    {
        float4 av = *(const float4*)(Aptr);
        float4 bv = *(const float4*)(Bptr);
        As[0][c4 + 0][ldRow] = av.x; As[0][c4 + 1][ldRow] = av.y;
        As[0][c4 + 2][ldRow] = av.z; As[0][c4 + 3][ldRow] = av.w;
        Bs[0][c4 + 0][ldRow] = bv.x; Bs[0][c4 + 1][ldRow] = bv.y;
        Bs[0][c4 + 2][ldRow] = bv.z; Bs[0][c4 + 3][ldRow] = bv.w;
    }
    __syncthreads();
    int buf = 0;
    for (int k0 = BK; k0 <= K; k0 += BK) {
        float4 av, bv;
        const bool more = (k0 < K);
        if (more) { av = *(const float4*)(Aptr + k0); bv = *(const float4*)(Bptr + k0); }
#pragma unroll
        for (int kk = 0; kk < BK; kk++) {
            float4 a0 = *(const float4*)(&As[buf][kk][trow * TM]);
            float4 a1 = *(const float4*)(&As[buf][kk][trow * TM + 4]);
            float4 b0 = *(const float4*)(&Bs[buf][kk][tcol * TN]);
            float4 b1 = *(const float4*)(&Bs[buf][kk][tcol * TN + 4]);
            float ra[8] = {a0.x, a0.y, a0.z, a0.w, a1.x, a1.y, a1.z, a1.w};
            float rb[8] = {b0.x, b0.y, b0.z, b0.w, b1.x, b1.y, b1.z, b1.w};
#pragma unroll
            for (int i = 0; i < 8; i++)
#pragma unroll
                for (int j = 0; j < 8; j++)
                    acc[i][j] = fmaf(ra[i], rb[j], acc[i][j]);
        }
        if (more) {
            const int nb = buf ^ 1;
            As[nb][c4 + 0][ldRow] = av.x; As[nb][c4 + 1][ldRow] = av.y;
            As[nb][c4 + 2][ldRow] = av.z; As[nb][c4 + 3][ldRow] = av.w;
            Bs[nb][c4 + 0][ldRow] = bv.x; Bs[nb][c4 + 1][ldRow] = bv.y;
            Bs[nb][c4 + 2][ldRow] = bv.z; Bs[nb][c4 + 3][ldRow] = bv.w;
        }
        __syncthreads();
        buf ^= 1;
    }
#pragma unroll
    for (int i = 0; i < TM; i++) {
        const int r = rowBase + trow * TM + i;
        float* Crow = C + (size_t)r * ldc + colBase + tcol * TN;
#pragma unroll
        for (int g = 0; g < 2; g++) {
            float vv[4];
#pragma unroll
            for (int q = 0; q < 4; q++) {
                float t = acc[i][g * 4 + q];
                if (EPI == 1) {
                    const int cidx = colBase + tcol * TN + g * 4 + q;
                    t = softplusf(t + bias[cidx]);
                }
                vv[q] = t;
            }
            float4 v; v.x = vv[0]; v.y = vv[1]; v.z = vv[2]; v.w = vv[3];
            *(float4*)(Crow + g * 4) = v;
        }
    }
}

// ---------------- x_proj: dbc[M,80] = xs @ W^T, both dirs ----------------
__global__ void __launch_bounds__(256) xproj_kernel(
    const float* __restrict__ xsc,
    const float* __restrict__ w_f, const float* __restrict__ w_b,
    float* __restrict__ dbc_f, float* __restrict__ dbc_b)
{
    const int dir = blockIdx.y;
    const float* W = dir ? w_b : w_f;
    float* C = dir ? dbc_b : dbc_f;
    const int m0 = blockIdx.x * 32;
    const int tid = threadIdx.x;
    const int trow = tid >> 4;
    const int tcol = tid & 15;
    constexpr int BK = 32;
    __shared__ float As[BK][32];
    __shared__ float Bs[BK][80];
    float acc0[5] = {0, 0, 0, 0, 0};
    float acc1[5] = {0, 0, 0, 0, 0};
    const int arow = tid >> 3;
    const int ac4 = (tid & 7) << 2;
    for (int k0 = 0; k0 < D_INNER; k0 += BK) {
        {
            float4 v = *(const float4*)(xsc + (size_t)(m0 + arow) * D_INNER + k0 + ac4);
            As[ac4 + 0][arow] = v.x; As[ac4 + 1][arow] = v.y;
            As[ac4 + 2][arow] = v.z; As[ac4 + 3][arow] = v.w;
        }
#pragma unroll
        for (int i = 0; i < 3; i++) {
            const int idx = tid + 256 * i;
            if (idx < 640) {
                const int n = idx >> 3;
                const int bc4 = (idx & 7) << 2;
                float4 v = *(const float4*)(W + (size_t)n * D_INNER + k0 + bc4);
                Bs[bc4 + 0][n] = v.x; Bs[bc4 + 1][n] = v.y;
                Bs[bc4 + 2][n] = v.z; Bs[bc4 + 3][n] = v.w;
            }
        }
        __syncthreads();
#pragma unroll
        for (int kk = 0; kk < BK; kk++) {
            const float a0 = As[kk][trow * 2];
            const float a1 = As[kk][trow * 2 + 1];
#pragma unroll
            for (int j = 0; j < 5; j++) {
                const float b = Bs[kk][tcol + 16 * j];
                acc0[j] = fmaf(a0, b, acc0[j]);
                acc1[j] = fmaf(a1, b, acc1[j]);
            }
        }
        __syncthreads();
    }
    const int r0 = m0 + trow * 2;
#pragma unroll
    for (int j = 0; j < 5; j++) {
        C[(size_t)r0 * DBC_N + tcol + 16 * j] = acc0[j];
        C[(size_t)(r0 + 1) * DBC_N + tcol + 16 * j] = acc1[j];
    }
}

// ---------------- causal depthwise conv(4) + SiLU, and silu(z) ----------------
__global__ void conv_silu_kernel(
    const float* __restrict__ xz, const float* __restrict__ cw,
    const float* __restrict__ cb, float* __restrict__ xsc, float* __restrict__ zs)
{
    const int idx = blockIdx.x * blockDim.x + threadIdx.x;
    if (idx >= BL * D_INNER) return;
    const int e = idx % D_INNER;
    const int row = idx / D_INNER;
    const int l = row & (SEQ - 1);
    const float w0 = cw[e * 4 + 0];
    const float w1 = cw[e * 4 + 1];
    const float w2 = cw[e * 4 + 2];
    const float w3 = cw[e * 4 + 3];
    const float* base = xz + (size_t)row * (2 * D_INNER) + e;
    float acc = cb[e];
    acc = fmaf(w3, base[0], acc);
    if (l >= 1) acc = fmaf(w2, base[-(ptrdiff_t)(2 * D_INNER)], acc);
    if (l >= 2) acc = fmaf(w1, base[-(ptrdiff_t)(4 * D_INNER)], acc);
    if (l >= 3) acc = fmaf(w0, base[-(ptrdiff_t)(6 * D_INNER)], acc);
    xsc[idx] = siluf(acc);
    const float z = xz[(size_t)row * (2 * D_INNER) + D_INNER + e];
    zs[idx] = siluf(z);
}

// ---------------- selective scan ----------------
__global__ void __launch_bounds__(512) scan_kernel(
    const float* __restrict__ delta_f, const float* __restrict__ delta_b,
    const float* __restrict__ dbc_f,  const float* __restrict__ dbc_b,
    const float* __restrict__ A_log,  const float* __restrict__ A_b_log,
    const float* __restrict__ xsc,
    float* __restrict__ y_f, float* __restrict__ y_b)
{
    const int dir = blockIdx.z;
    const int b = blockIdx.y;
    const int e0 = blockIdx.x * 32;
    const int t = threadIdx.x;
    const int el = t >> 4;
    const int n = t & 15;
    const int e = e0 + el;
    const float* delta = dir ? delta_b : delta_f;
    const float* dbc = dir ? dbc_b : dbc_f;
    const float* Alog = dir ? A_b_log : A_log;
    float* y = dir ? y_b : y_f;
    const float An = -__expf(Alog[e * D_STATE + n]);
    __shared__ float s_d[16 * 32];
    __shared__ float s_x[16 * 32];
    __shared__ float s_bc[16 * 32];
    __shared__ float s_y[16 * 32];
    const int lj = t >> 5;
    const int lc = t & 31;
    float h = 0.f;
    const size_t rowb = (size_t)b * SEQ;
    for (int c = 0; c < SEQ / 16; c++) {
        {
            const int i = c * 16 + lj;
            const int l = dir ? (SEQ - 1 - i) : i;
            const size_t row = rowb + l;
            s_d[lj * 32 + lc]  = delta[row * D_INNER + e0 + lc];
            s_x[lj * 32 + lc]  = xsc[row * D_INNER + e0 + lc];
            s_bc[lj * 32 + lc] = dbc[row * DBC_N + DT_RANK + lc];
        }
        __syncthreads();
#pragma unroll
        for (int j = 0; j < 16; j++) {
            const float dlt = s_d[j * 32 + el];
            const float xv  = s_x[j * 32 + el];
            const float Bv  = s_bc[j * 32 + n];
            const float Cv  = s_bc[j * 32 + 16 + n];
            const float dA = __expf(dlt * An);
            h = fmaf(dA, h, dlt * xv * Bv);
            float p = h * Cv;
            p += __shfl_xor_sync(0xffffffffu, p, 8);
            p += __shfl_xor_sync(0xffffffffu, p, 4);
            p += __shfl_xor_sync(0xffffffffu, p, 2);
            p += __shfl_xor_sync(0xffffffffu, p, 1);
            if (n == 0) s_y[j * 32 + el] = p;
        }
        __syncthreads();
        {
            const int i = c * 16 + lj;
            const int l = dir ? (SEQ - 1 - i) : i;
            y[(rowb + l) * D_INNER + e0 + lc] = s_y[lj * 32 + lc];
        }
    }
}

// ---------------- fuse: u = (y_f + y_b + (D+D_b)*xs)*silu(z) -> bf16 triple ----------------
__global__ void fuse_kernel(
    const float* __restrict__ yf, const float* __restrict__ yb,
    const float* __restrict__ xsc, const float* __restrict__ zs,
    const float* __restrict__ D1, const float* __restrict__ D2,
    __nv_bfloat16* __restrict__ u3)
{
    const int idx4 = blockIdx.x * blockDim.x + threadIdx.x;
    if (idx4 >= (BL * D_INNER) / 4) return;
    const int e4 = (idx4 * 4) % D_INNER;
    const int r = (idx4 * 4) / D_INNER;
    const float4 a = *(const float4*)(yf + (size_t)idx4 * 4);
    const float4 bq = *(const float4*)(yb + (size_t)idx4 * 4);
    const float4 xv = *(const float4*)(xsc + (size_t)idx4 * 4);
    const float4 zv = *(const float4*)(zs + (size_t)idx4 * 4);
    const float4 d1 = *(const float4*)(D1 + e4);
    const float4 d2 = *(const float4*)(D2 + e4);
    float vv[4];
    vv[0] = (a.x + bq.x + (d1.x + d2.x) * xv.x) * zv.x;
    vv[1] = (a.y + bq.y + (d1.y + d2.y) * xv.y) * zv.y;
    vv[2] = (a.z + bq.z + (d1.z + d2.z) * xv.z) * zv.z;
    vv[3] = (a.w + bq.w + (d1.w + d2.w) * xv.w) * zv.w;
    unsigned short hs[4], ls[4];
#pragma unroll
    for (int j = 0; j < 4; j++) {
        __nv_bfloat16 h = __float2bfloat16(vv[j]);
        __nv_bfloat16 lo = __float2bfloat16(vv[j] - __bfloat162float(h));
        hs[j] = __bfloat16_as_ushort(h);
        ls[j] = __bfloat16_as_ushort(lo);
    }
    const ushort4 H = make_ushort4(hs[0], hs[1], hs[2], hs[3]);
    const ushort4 L = make_ushort4(ls[0], ls[1], ls[2], ls[3]);
    const size_t base = (size_t)r * KOUT3 + e4;
    *(ushort4*)((unsigned short*)u3 + base) = H;
    *(ushort4*)((unsigned short*)u3 + base + KOUT) = H;
    *(ushort4*)((unsigned short*)u3 + base + 2 * KOUT) = L;
}

// ---------------- launcher ----------------
extern "C" void kernel_launch(void* const* d_in, const int* in_sizes, int n_in,
                              void* d_out, int out_size)
{
    const float* x          = (const float*)d_in[0];
    const float* in_proj_w  = (const float*)d_in[1];
    const float* conv_w     = (const float*)d_in[2];
    const float* conv_bias  = (const float*)d_in[3];
    const float* x_proj_w   = (const float*)d_in[4];
    const float* dt_proj_w  = (const float*)d_in[5];
    const float* dt_proj_b  = (const float*)d_in[6];
    const float* A_log      = (const float*)d_in[7];
    const float* D_param    = (const float*)d_in[8];
    const float* out_proj_w = (const float*)d_in[9];
    const float* A_b_log    = (const float*)d_in[10];
    const float* x_proj_b_w = (const float*)d_in[11];
    const float* dt_proj_b_w= (const float*)d_in[12];
    const float* dt_proj_b_b= (const float*)d_in[13];
    const float* D_b        = (const float*)d_in[14];
    float* out = (float*)d_out;

    float *p_xz, *p_xsc, *p_zs, *p_dbc_f, *p_dbc_b;
    float *p_delta_f, *p_delta_b, *p_y_f, *p_y_b;
    __nv_bfloat16 *p_ax, *p_wi, *p_u3, *p_wo;
    cudaGetSymbolAddress((void**)&p_xz, g_xz);
    cudaGetSymbolAddress((void**)&p_xsc, g_xsc);
    cudaGetSymbolAddress((void**)&p_zs, g_zs);
    cudaGetSymbolAddress((void**)&p_dbc_f, g_dbc_f);
    cudaGetSymbolAddress((void**)&p_dbc_b, g_dbc_b);
    cudaGetSymbolAddress((void**)&p_delta_f, g_delta_f);
    cudaGetSymbolAddress((void**)&p_delta_b, g_delta_b);
    cudaGetSymbolAddress((void**)&p_y_f, g_y_f);
    cudaGetSymbolAddress((void**)&p_y_b, g_y_b);
    cudaGetSymbolAddress((void**)&p_ax, g_ax);
    cudaGetSymbolAddress((void**)&p_wi, g_wi);
    cudaGetSymbolAddress((void**)&p_u3, g_u3);
    cudaGetSymbolAddress((void**)&p_wo, g_wo);

    const int SMEM_MMA = 4 * STAGE_BYTES; // 81920
    cudaFuncSetAttribute(hmma_bf16_nt, cudaFuncAttributeMaxDynamicSharedMemorySize, SMEM_MMA);

    // 0) split operands to bf16 triples
    split3_kernel<0><<<(BL * KIN / 4 + 255) / 256, 256>>>(x, p_ax, BL * KIN, KIN);
    split3_kernel<1><<<(2 * D_INNER * KIN / 4 + 255) / 256, 256>>>(
        in_proj_w, p_wi, 2 * D_INNER * KIN, KIN);
    split3_kernel<1><<<(D_MODEL * KOUT / 4 + 255) / 256, 256>>>(
        out_proj_w, p_wo, D_MODEL * KOUT, KOUT);

    // 1) xz = x @ in_proj_w^T  (HMMA bf16x3)
    hmma_bf16_nt<<<dim3((2 * D_INNER) / 128, BL / 128), 256, SMEM_MMA>>>(
        p_ax, p_wi, p_xz, 2 * D_INNER, KIN3, KIN3 / 32);

    // 2) causal conv + silu, silu(z)
    conv_silu_kernel<<<(BL * D_INNER + 255) / 256, 256>>>(
        p_xz, conv_w, conv_bias, p_xsc, p_zs);

    // 3) dbc_{f,b}
    xproj_kernel<<<dim3(BL / 32, 2), 256>>>(
        p_xsc, x_proj_w, x_proj_b_w, p_dbc_f, p_dbc_b);

    // 4) delta_{f,b}
    sgemm_nt<1><<<dim3(D_INNER / 128, BL / 128, 2), 256>>>(
        p_dbc_f, DBC_N, dt_proj_w, DT_RANK, p_delta_f, D_INNER,
        DT_RANK, dt_proj_b,
        p_dbc_b, dt_proj_b_w, p_delta_b, dt_proj_b_b);

    // 5) selective scan
    scan_kernel<<<dim3(D_INNER / 32, NB, 2), 512>>>(
        p_delta_f, p_delta_b, p_dbc_f, p_dbc_b,
        A_log, A_b_log, p_xsc, p_y_f, p_y_b);

    // 6) fuse -> u bf16 triple
    fuse_kernel<<<(BL * D_INNER / 4 + 255) / 256, 256>>>(
        p_y_f, p_y_b, p_xsc, p_zs, D_param, D_b, p_u3);

    // 7) out = u @ out_proj_w^T  (HMMA bf16x3)
    hmma_bf16_nt<<<dim3(D_MODEL / 128, BL / 128), 256, SMEM_MMA>>>(
        p_u3, p_wo, out, D_MODEL, KOUT3, KOUT3 / 32);
}

// round 5
// speedup vs baseline: 2.6317x; 1.0041x over previous
#include <cuda_runtime.h>
#include <cuda_bf16.h>
#include <cstdint>
#include <cstddef>

// ---------------- problem constants ----------------
#define D_MODEL 768
#define D_INNER 1536
#define D_STATE 16
#define DT_RANK 48
#define NB 2
#define SEQ 1024
#define BL (NB * SEQ)                 // 2048
#define DBC_N (DT_RANK + 2 * D_STATE) // 80
#define KIN  D_MODEL                  // 768
#define KIN3 (3 * KIN)                // 2304
#define KOUT D_INNER                  // 1536
#define KOUT3 (3 * KOUT)              // 4608

// ---------------- scratch (static __device__ arrays; no allocs) ----------------
__device__ float g_xz[BL * 2 * D_INNER];
__device__ float g_xsc[BL * D_INNER];
__device__ float g_zs[BL * D_INNER];
__device__ float g_dbc_f[BL * DBC_N];
__device__ float g_dbc_b[BL * DBC_N];
__device__ float g_delta_f[BL * D_INNER];
__device__ float g_delta_b[BL * D_INNER];
__device__ float g_y_f[BL * D_INNER];
__device__ float g_y_b[BL * D_INNER];
__device__ float g_part[BL * D_MODEL];                 // split-K partial for out_proj
__device__ __nv_bfloat16 g_ax[BL * KIN3];              // x split (hi|hi|lo)
__device__ __nv_bfloat16 g_wi[2 * D_INNER * KIN3];     // in_proj_w split (hi|lo|hi)
__device__ __nv_bfloat16 g_u3[BL * KOUT3];             // u split (hi|hi|lo)
__device__ __nv_bfloat16 g_wo[D_MODEL * KOUT3];        // out_proj_w split (hi|lo|hi)

// ---------------- math helpers ----------------
__device__ __forceinline__ float siluf(float x) { return x / (1.f + __expf(-x)); }
__device__ __forceinline__ float softplusf(float x) {
    return (x > 20.f) ? x : log1pf(__expf(x));
}

__device__ __forceinline__ uint32_t smem_u32(const void* p) {
    uint32_t a;
    asm("{ .reg .u64 t; cvta.to.shared.u64 t, %1; cvt.u32.u64 %0, t; }" : "=r"(a) : "l"(p));
    return a;
}
__device__ __forceinline__ void cp_async16(uint32_t saddr, const void* g) {
    asm volatile("cp.async.cg.shared.global [%0], [%1], 16;" :: "r"(saddr), "l"(g));
}
__device__ __forceinline__ void cp_commit() {
    asm volatile("cp.async.commit_group;" ::: "memory");
}
__device__ __forceinline__ void ldm_x4(uint32_t& r0, uint32_t& r1, uint32_t& r2,
                                       uint32_t& r3, uint32_t addr) {
    asm volatile("ldmatrix.sync.aligned.m8n8.x4.shared.b16 {%0,%1,%2,%3}, [%4];"
                 : "=r"(r0), "=r"(r1), "=r"(r2), "=r"(r3) : "r"(addr));
}
__device__ __forceinline__ void mma_bf16(float* c, const uint32_t* a, const uint32_t* b) {
    asm volatile(
        "mma.sync.aligned.m16n8k16.row.col.f32.bf16.bf16.f32 "
        "{%0,%1,%2,%3}, {%4,%5,%6,%7}, {%8,%9}, {%0,%1,%2,%3};"
        : "+f"(c[0]), "+f"(c[1]), "+f"(c[2]), "+f"(c[3])
        : "r"(a[0]), "r"(a[1]), "r"(a[2]), "r"(a[3]), "r"(b[0]), "r"(b[1]));
}

// ---------------- HMMA bf16 GEMM: C[M,N] = A'[M,Kp] * B'[N,Kp]^T ----------------
// BM=BN=128, BK=32 bf16, 8 warps (4M x 2N), warp tile 32x64,
// 4-stage cp.async pipeline (single barrier per chunk), 80B-padded rows.
// Split-K over blockIdx.z: z=0 -> C, z=1 -> Cpart (summed afterwards).
// grid (N/128, M/128, nsplit), 256 threads, dynamic smem 81920B.
#define ROWB 80
#define STAGE_BYTES 20480
#define OFFB 10240
__global__ void __launch_bounds__(256) hmma_bf16_nt(
    const __nv_bfloat16* __restrict__ A,
    const __nv_bfloat16* __restrict__ B,
    float* __restrict__ C, int ldc, int Kp, int nChunks,
    float* __restrict__ Cpart)
{
    extern __shared__ char smem[];
    const uint32_t sb = smem_u32(smem);
    const int tid = threadIdx.x;
    const int rowBase = blockIdx.y * 128;
    const int colBase = blockIdx.x * 128;
    const int chunkBase = blockIdx.z * nChunks;
    float* Cw = (blockIdx.z == 0) ? C : Cpart;

    // per-thread global->smem load slots (2 x 16B for A, 2 x 16B for B per stage)
    const int r0 = tid >> 2, c0 = tid & 3;
    const int r1 = (tid + 256) >> 2, c1 = (tid + 256) & 3;
    const char* gA0 = (const char*)(A + (size_t)(rowBase + r0) * Kp + c0 * 8)
                      + (size_t)chunkBase * 64;
    const char* gA1 = (const char*)(A + (size_t)(rowBase + r1) * Kp + c1 * 8)
                      + (size_t)chunkBase * 64;
    const char* gB0 = (const char*)(B + (size_t)(colBase + r0) * Kp + c0 * 8)
                      + (size_t)chunkBase * 64;
    const char* gB1 = (const char*)(B + (size_t)(colBase + r1) * Kp + c1 * 8)
                      + (size_t)chunkBase * 64;
    const uint32_t sA0 = r0 * ROWB + c0 * 16, sA1 = r1 * ROWB + c1 * 16;
    const uint32_t sB0 = OFFB + sA0, sB1 = OFFB + sA1;

#define LOAD_STAGE(c) do {                                                  \
    const uint32_t _base = sb + ((c) & 3) * STAGE_BYTES;                    \
    const size_t _gk = (size_t)(c) * 64;                                    \
    cp_async16(_base + sA0, gA0 + _gk);                                     \
    cp_async16(_base + sA1, gA1 + _gk);                                     \
    cp_async16(_base + sB0, gB0 + _gk);                                     \
    cp_async16(_base + sB1, gB1 + _gk);                                     \
} while (0)

    const int wid = tid >> 5;
    const int l = tid & 31;
    const int wm = wid & 3;       // 0..3 (M)
    const int wn = wid >> 2;      // 0..1 (N)

    // ldmatrix lane offsets
    const int a_row = ((l >> 3) & 1) * 8 + (l & 7);
    const int a_k   = (l >> 4) * 8;
    const int b_n   = (l >> 4) * 8 + (l & 7);
    const int b_k   = ((l >> 3) & 1) * 8;

    float acc[2][8][4];
#pragma unroll
    for (int i = 0; i < 2; i++)
#pragma unroll
        for (int j = 0; j < 8; j++)
#pragma unroll
            for (int q = 0; q < 4; q++) acc[i][j][q] = 0.f;

    LOAD_STAGE(0); cp_commit();
    LOAD_STAGE(1); cp_commit();
    LOAD_STAGE(2); cp_commit();

    for (int c = 0; c < nChunks; c++) {
        asm volatile("cp.async.wait_group 2;" ::: "memory");
        __syncthreads();

        // issue next stage's loads first (stage (c+3)&3 was consumed at c-1,
        // ordered by the barrier above), then compute chunk c
        if (c + 3 < nChunks) LOAD_STAGE(c + 3);
        cp_commit();

        const uint32_t stb = sb + (c & 3) * STAGE_BYTES;
        const uint32_t aW = stb + (wm * 32) * ROWB;
        const uint32_t bW = stb + OFFB + (wn * 64) * ROWB;

#pragma unroll
        for (int ks = 0; ks < 2; ks++) {
            uint32_t a[2][4];
#pragma unroll
            for (int mi = 0; mi < 2; mi++)
                ldm_x4(a[mi][0], a[mi][1], a[mi][2], a[mi][3],
                       aW + (mi * 16 + a_row) * ROWB + (ks * 16 + a_k) * 2);
            uint32_t b[8][2];
#pragma unroll
            for (int nf = 0; nf < 4; nf++) {
                uint32_t q0, q1, q2, q3;
                ldm_x4(q0, q1, q2, q3,
                       bW + (nf * 16 + b_n) * ROWB + (ks * 16 + b_k) * 2);
                b[nf * 2][0] = q0; b[nf * 2][1] = q1;
                b[nf * 2 + 1][0] = q2; b[nf * 2 + 1][1] = q3;
            }
#pragma unroll
            for (int mi = 0; mi < 2; mi++)
#pragma unroll
                for (int nb = 0; nb < 8; nb++)
                    mma_bf16(acc[mi][nb], a[mi], b[nb]);
        }
    }

    // epilogue: direct float2 stores
    const int lrow = l >> 2;
    const int lcol = (l & 3) * 2;
#pragma unroll
    for (int mi = 0; mi < 2; mi++) {
        const int grow = rowBase + wm * 32 + mi * 16 + lrow;
#pragma unroll
        for (int nb = 0; nb < 8; nb++) {
            const int gcol = colBase + wn * 64 + nb * 8 + lcol;
            float2 v0 = make_float2(acc[mi][nb][0], acc[mi][nb][1]);
            float2 v1 = make_float2(acc[mi][nb][2], acc[mi][nb][3]);
            *(float2*)(Cw + (size_t)grow * ldc + gcol) = v0;
            *(float2*)(Cw + (size_t)(grow + 8) * ldc + gcol) = v1;
        }
    }
#undef LOAD_STAGE
}

// ---------------- split-K reduction: out += part ----------------
__global__ void addout_kernel(float* __restrict__ out, const float* __restrict__ part)
{
    const int i4 = blockIdx.x * blockDim.x + threadIdx.x;
    if (i4 * 4 >= BL * D_MODEL) return;
    float4 a = *(float4*)(out + (size_t)i4 * 4);
    const float4 b = *(const float4*)(part + (size_t)i4 * 4);
    a.x += b.x; a.y += b.y; a.z += b.z; a.w += b.w;
    *(float4*)(out + (size_t)i4 * 4) = a;
}

// ---------------- split fp32 -> bf16 triple ----------------
// MODEB=0: (hi|hi|lo) for A operands; MODEB=1: (hi|lo|hi) for B operands.
template <int MODEB>
__global__ void split3_kernel(const float* __restrict__ src,
                              __nv_bfloat16* __restrict__ dst, int RK, int K)
{
    const int i4 = blockIdx.x * blockDim.x + threadIdx.x;
    if (i4 * 4 >= RK) return;
    const float4 v = *(const float4*)(src + (size_t)i4 * 4);
    const int r = (i4 * 4) / K;
    const int k = (i4 * 4) % K;
    float vv[4] = {v.x, v.y, v.z, v.w};
    unsigned short hs[4], ls[4];
#pragma unroll
    for (int j = 0; j < 4; j++) {
        __nv_bfloat16 h = __float2bfloat16(vv[j]);
        __nv_bfloat16 lo = __float2bfloat16(vv[j] - __bfloat162float(h));
        hs[j] = __bfloat16_as_ushort(h);
        ls[j] = __bfloat16_as_ushort(lo);
    }
    const ushort4 H = make_ushort4(hs[0], hs[1], hs[2], hs[3]);
    const ushort4 L = make_ushort4(ls[0], ls[1], ls[2], ls[3]);
    const size_t base = (size_t)r * (3 * K) + k;
    *(ushort4*)((unsigned short*)dst + base) = H;
    *(ushort4*)((unsigned short*)dst + base + K) = MODEB ? L : H;
    *(ushort4*)((unsigned short*)dst + base + 2 * K) = MODEB ? H : L;
}

// ---------------- SGEMM (fp32) for dt_proj: softplus epilogue ----------------
template <int EPI>
__global__ void __launch_bounds__(256) sgemm_nt(
    const float* __restrict__ A, int lda,
    const float* __restrict__ B, int ldb,
    float* __restrict__ C, int ldc,
    int K, const float* __restrict__ bias,
    const float* __restrict__ A2, const float* __restrict__ B2,
    float* __restrict__ C2, const float* __restrict__ bias2)
{
    if (blockIdx.z == 1) { A = A2; B = B2; C = C2; bias = bias2; }
    constexpr int BK = 8, TM = 8, TN = 8;
    __shared__ float As[2][BK][128];
    __shared__ float Bs[2][BK][128];
    const int tid = threadIdx.x;
    const int rowBase = blockIdx.y * 128;
    const int colBase = blockIdx.x * 128;
    const int ldRow = tid >> 1;
    const int c4 = (tid & 1) << 2;
    const int trow = tid >> 4;
    const int tcol = tid & 15;
    const float* Aptr = A + (size_t)(rowBase + ldRow) * lda + c4;
    const float* Bptr = B + (size_t)(colBase + ldRow) * ldb + c4;
    float acc[TM][TN];
#pragma unroll
    for (int i = 0; i < TM; i++)
#pragma unroll
        for (int j = 0; j < TN; j++) acc[i][j] = 0.f;
    {
        float4 av = *(const float4*)(Aptr);
        float4 bv = *(const float4*)(Bptr);
        As[0][c4 + 0][ldRow] = av.x; As[0][c4 + 1][ldRow] = av.y;
        As[0][c4 + 2][ldRow] = av.z; As[0][c4 + 3][ldRow] = av.w;
        Bs[0][c4 + 0][ldRow] = bv.x; Bs[0][c4 + 1][ldRow] = bv.y;
        Bs[0][c4 + 2][ldRow] = bv.z; Bs[0][c4 + 3][ldRow] = bv.w;
    }
    __syncthreads();
    int buf = 0;
    for (int k0 = BK; k0 <= K; k0 += BK) {
        float4 av, bv;
        const bool more = (k0 < K);
        if (more) { av = *(const float4*)(Aptr + k0); bv = *(const float4*)(Bptr + k0); }
#pragma unroll
        for (int kk = 0; kk < BK; kk++) {
            float4 a0 = *(const float4*)(&As[buf][kk][trow * TM]);
            float4 a1 = *(const float4*)(&As[buf][kk][trow * TM + 4]);
            float4 b0 = *(const float4*)(&Bs[buf][kk][tcol * TN]);
            float4 b1 = *(const float4*)(&Bs[buf][kk][tcol * TN + 4]);
            float ra[8] = {a0.x, a0.y, a0.z, a0.w, a1.x, a1.y, a1.z, a1.w};
            float rb[8] = {b0.x, b0.y, b0.z, b0.w, b1.x, b1.y, b1.z, b1.w};
#pragma unroll
            for (int i = 0; i < 8; i++)
#pragma unroll
                for (int j = 0; j < 8; j++)
                    acc[i][j] = fmaf(ra[i], rb[j], acc[i][j]);
        }
        if (more) {
            const int nb = buf ^ 1;
            As[nb][c4 + 0][ldRow] = av.x; As[nb][c4 + 1][ldRow] = av.y;
            As[nb][c4 + 2][ldRow] = av.z; As[nb][c4 + 3][ldRow] = av.w;
            Bs[nb][c4 + 0][ldRow] = bv.x; Bs[nb][c4 + 1][ldRow] = bv.y;
            Bs[nb][c4 + 2][ldRow] = bv.z; Bs[nb][c4 + 3][ldRow] = bv.w;
        }
        __syncthreads();
        buf ^= 1;
    }
#pragma unroll
    for (int i = 0; i < TM; i++) {
        const int r = rowBase + trow * TM + i;
        float* Crow = C + (size_t)r * ldc + colBase + tcol * TN;
#pragma unroll
        for (int g = 0; g < 2; g++) {
            float vv[4];
#pragma unroll
            for (int q = 0; q < 4; q++) {
                float t = acc[i][g * 4 + q];
                if (EPI == 1) {
                    const int cidx = colBase + tcol * TN + g * 4 + q;
                    t = softplusf(t + bias[cidx]);
                }
                vv[q] = t;
            }
            float4 v; v.x = vv[0]; v.y = vv[1]; v.z = vv[2]; v.w = vv[3];
            *(float4*)(Crow + g * 4) = v;
        }
    }
}

// ---------------- x_proj: dbc[M,80] = xs @ W^T, both dirs ----------------
__global__ void __launch_bounds__(256) xproj_kernel(
    const float* __restrict__ xsc,
    const float* __restrict__ w_f, const float* __restrict__ w_b,
    float* __restrict__ dbc_f, float* __restrict__ dbc_b)
{
    const int dir = blockIdx.y;
    const float* W = dir ? w_b : w_f;
    float* C = dir ? dbc_b : dbc_f;
    const int m0 = blockIdx.x * 32;
    const int tid = threadIdx.x;
    const int trow = tid >> 4;
    const int tcol = tid & 15;
    constexpr int BK = 32;
    __shared__ float As[BK][32];
    __shared__ float Bs[BK][80];
    float acc0[5] = {0, 0, 0, 0, 0};
    float acc1[5] = {0, 0, 0, 0, 0};
    const int arow = tid >> 3;
    const int ac4 = (tid & 7) << 2;
    for (int k0 = 0; k0 < D_INNER; k0 += BK) {
        {
            float4 v = *(const float4*)(xsc + (size_t)(m0 + arow) * D_INNER + k0 + ac4);
            As[ac4 + 0][arow] = v.x; As[ac4 + 1][arow] = v.y;
            As[ac4 + 2][arow] = v.z; As[ac4 + 3][arow] = v.w;
        }
#pragma unroll
        for (int i = 0; i < 3; i++) {
            const int idx = tid + 256 * i;
            if (idx < 640) {
                const int n = idx >> 3;
                const int bc4 = (idx & 7) << 2;
                float4 v = *(const float4*)(W + (size_t)n * D_INNER + k0 + bc4);
                Bs[bc4 + 0][n] = v.x; Bs[bc4 + 1][n] = v.y;
                Bs[bc4 + 2][n] = v.z; Bs[bc4 + 3][n] = v.w;
            }
        }
        __syncthreads();
#pragma unroll
        for (int kk = 0; kk < BK; kk++) {
            const float a0 = As[kk][trow * 2];
            const float a1 = As[kk][trow * 2 + 1];
#pragma unroll
            for (int j = 0; j < 5; j++) {
                const float b = Bs[kk][tcol + 16 * j];
                acc0[j] = fmaf(a0, b, acc0[j]);
                acc1[j] = fmaf(a1, b, acc1[j]);
            }
        }
        __syncthreads();
    }
    const int r0 = m0 + trow * 2;
#pragma unroll
    for (int j = 0; j < 5; j++) {
        C[(size_t)r0 * DBC_N + tcol + 16 * j] = acc0[j];
        C[(size_t)(r0 + 1) * DBC_N + tcol + 16 * j] = acc1[j];
    }
}

// ---------------- causal depthwise conv(4) + SiLU, and silu(z) ----------------
__global__ void conv_silu_kernel(
    const float* __restrict__ xz, const float* __restrict__ cw,
    const float* __restrict__ cb, float* __restrict__ xsc, float* __restrict__ zs)
{
    const int idx = blockIdx.x * blockDim.x + threadIdx.x;
    if (idx >= BL * D_INNER) return;
    const int e = idx % D_INNER;
    const int row = idx / D_INNER;
    const int l = row & (SEQ - 1);
    const float w0 = cw[e * 4 + 0];
    const float w1 = cw[e * 4 + 1];
    const float w2 = cw[e * 4 + 2];
    const float w3 = cw[e * 4 + 3];
    const float* base = xz + (size_t)row * (2 * D_INNER) + e;
    float acc = cb[e];
    acc = fmaf(w3, base[0], acc);
    if (l >= 1) acc = fmaf(w2, base[-(ptrdiff_t)(2 * D_INNER)], acc);
    if (l >= 2) acc = fmaf(w1, base[-(ptrdiff_t)(4 * D_INNER)], acc);
    if (l >= 3) acc = fmaf(w0, base[-(ptrdiff_t)(6 * D_INNER)], acc);
    xsc[idx] = siluf(acc);
    const float z = xz[(size_t)row * (2 * D_INNER) + D_INNER + e];
    zs[idx] = siluf(z);
}

// ---------------- selective scan ----------------
__global__ void __launch_bounds__(512) scan_kernel(
    const float* __restrict__ delta_f, const float* __restrict__ delta_b,
    const float* __restrict__ dbc_f,  const float* __restrict__ dbc_b,
    const float* __restrict__ A_log,  const float* __restrict__ A_b_log,
    const float* __restrict__ xsc,
    float* __restrict__ y_f, float* __restrict__ y_b)
{
    const int dir = blockIdx.z;
    const int b = blockIdx.y;
    const int e0 = blockIdx.x * 32;
    const int t = threadIdx.x;
    const int el = t >> 4;
    const int n = t & 15;
    const int e = e0 + el;
    const float* delta = dir ? delta_b : delta_f;
    const float* dbc = dir ? dbc_b : dbc_f;
    const float* Alog = dir ? A_b_log : A_log;
    float* y = dir ? y_b : y_f;
    const float An = -__expf(Alog[e * D_STATE + n]);
    __shared__ float s_d[16 * 32];
    __shared__ float s_x[16 * 32];
    __shared__ float s_bc[16 * 32];
    __shared__ float s_y[16 * 32];
    const int lj = t >> 5;
    const int lc = t & 31;
    float h = 0.f;
    const size_t rowb = (size_t)b * SEQ;
    for (int c = 0; c < SEQ / 16; c++) {
        {
            const int i = c * 16 + lj;
            const int l = dir ? (SEQ - 1 - i) : i;
            const size_t row = rowb + l;
            s_d[lj * 32 + lc]  = delta[row * D_INNER + e0 + lc];
            s_x[lj * 32 + lc]  = xsc[row * D_INNER + e0 + lc];
            s_bc[lj * 32 + lc] = dbc[row * DBC_N + DT_RANK + lc];
        }
        __syncthreads();
#pragma unroll
        for (int j = 0; j < 16; j++) {
            const float dlt = s_d[j * 32 + el];
            const float xv  = s_x[j * 32 + el];
            const float Bv  = s_bc[j * 32 + n];
            const float Cv  = s_bc[j * 32 + 16 + n];
            const float dA = __expf(dlt * An);
            h = fmaf(dA, h, dlt * xv * Bv);
            float p = h * Cv;
            p += __shfl_xor_sync(0xffffffffu, p, 8);
            p += __shfl_xor_sync(0xffffffffu, p, 4);
            p += __shfl_xor_sync(0xffffffffu, p, 2);
            p += __shfl_xor_sync(0xffffffffu, p, 1);
            if (n == 0) s_y[j * 32 + el] = p;
        }
        __syncthreads();
        {
            const int i = c * 16 + lj;
            const int l = dir ? (SEQ - 1 - i) : i;
            y[(rowb + l) * D_INNER + e0 + lc] = s_y[lj * 32 + lc];
        }
    }
}

// ---------------- fuse: u = (y_f + y_b + (D+D_b)*xs)*silu(z) -> bf16 triple ----------------
__global__ void fuse_kernel(
    const float* __restrict__ yf, const float* __restrict__ yb,
    const float* __restrict__ xsc, const float* __restrict__ zs,
    const float* __restrict__ D1, const float* __restrict__ D2,
    __nv_bfloat16* __restrict__ u3)
{
    const int idx4 = blockIdx.x * blockDim.x + threadIdx.x;
    if (idx4 >= (BL * D_INNER) / 4) return;
    const int e4 = (idx4 * 4) % D_INNER;
    const int r = (idx4 * 4) / D_INNER;
    const float4 a = *(const float4*)(yf + (size_t)idx4 * 4);
    const float4 bq = *(const float4*)(yb + (size_t)idx4 * 4);
    const float4 xv = *(const float4*)(xsc + (size_t)idx4 * 4);
    const float4 zv = *(const float4*)(zs + (size_t)idx4 * 4);
    const float4 d1 = *(const float4*)(D1 + e4);
    const float4 d2 = *(const float4*)(D2 + e4);
    float vv[4];
    vv[0] = (a.x + bq.x + (d1.x + d2.x) * xv.x) * zv.x;
    vv[1] = (a.y + bq.y + (d1.y + d2.y) * xv.y) * zv.y;
    vv[2] = (a.z + bq.z + (d1.z + d2.z) * xv.z) * zv.z;
    vv[3] = (a.w + bq.w + (d1.w + d2.w) * xv.w) * zv.w;
    unsigned short hs[4], ls[4];
#pragma unroll
    for (int j = 0; j < 4; j++) {
        __nv_bfloat16 h = __float2bfloat16(vv[j]);
        __nv_bfloat16 lo = __float2bfloat16(vv[j] - __bfloat162float(h));
        hs[j] = __bfloat16_as_ushort(h);
        ls[j] = __bfloat16_as_ushort(lo);
    }
    const ushort4 H = make_ushort4(hs[0], hs[1], hs[2], hs[3]);
    const ushort4 L = make_ushort4(ls[0], ls[1], ls[2], ls[3]);
    const size_t base = (size_t)r * KOUT3 + e4;
    *(ushort4*)((unsigned short*)u3 + base) = H;
    *(ushort4*)((unsigned short*)u3 + base + KOUT) = H;
    *(ushort4*)((unsigned short*)u3 + base + 2 * KOUT) = L;
}

// ---------------- launcher ----------------
extern "C" void kernel_launch(void* const* d_in, const int* in_sizes, int n_in,
                              void* d_out, int out_size)
{
    const float* x          = (const float*)d_in[0];
    const float* in_proj_w  = (const float*)d_in[1];
    const float* conv_w     = (const float*)d_in[2];
    const float* conv_bias  = (const float*)d_in[3];
    const float* x_proj_w   = (const float*)d_in[4];
    const float* dt_proj_w  = (const float*)d_in[5];
    const float* dt_proj_b  = (const float*)d_in[6];
    const float* A_log      = (const float*)d_in[7];
    const float* D_param    = (const float*)d_in[8];
    const float* out_proj_w = (const float*)d_in[9];
    const float* A_b_log    = (const float*)d_in[10];
    const float* x_proj_b_w = (const float*)d_in[11];
    const float* dt_proj_b_w= (const float*)d_in[12];
    const float* dt_proj_b_b= (const float*)d_in[13];
    const float* D_b        = (const float*)d_in[14];
    float* out = (float*)d_out;

    float *p_xz, *p_xsc, *p_zs, *p_dbc_f, *p_dbc_b;
    float *p_delta_f, *p_delta_b, *p_y_f, *p_y_b, *p_part;
    __nv_bfloat16 *p_ax, *p_wi, *p_u3, *p_wo;
    cudaGetSymbolAddress((void**)&p_xz, g_xz);
    cudaGetSymbolAddress((void**)&p_xsc, g_xsc);
    cudaGetSymbolAddress((void**)&p_zs, g_zs);
    cudaGetSymbolAddress((void**)&p_dbc_f, g_dbc_f);
    cudaGetSymbolAddress((void**)&p_dbc_b, g_dbc_b);
    cudaGetSymbolAddress((void**)&p_delta_f, g_delta_f);
    cudaGetSymbolAddress((void**)&p_delta_b, g_delta_b);
    cudaGetSymbolAddress((void**)&p_y_f, g_y_f);
    cudaGetSymbolAddress((void**)&p_y_b, g_y_b);
    cudaGetSymbolAddress((void**)&p_part, g_part);
    cudaGetSymbolAddress((void**)&p_ax, g_ax);
    cudaGetSymbolAddress((void**)&p_wi, g_wi);
    cudaGetSymbolAddress((void**)&p_u3, g_u3);
    cudaGetSymbolAddress((void**)&p_wo, g_wo);

    const int SMEM_MMA = 4 * STAGE_BYTES; // 81920
    cudaFuncSetAttribute(hmma_bf16_nt, cudaFuncAttributeMaxDynamicSharedMemorySize, SMEM_MMA);

    // 0) split operands to bf16 triples
    split3_kernel<0><<<(BL * KIN / 4 + 255) / 256, 256>>>(x, p_ax, BL * KIN, KIN);
    split3_kernel<1><<<(2 * D_INNER * KIN / 4 + 255) / 256, 256>>>(
        in_proj_w, p_wi, 2 * D_INNER * KIN, KIN);
    split3_kernel<1><<<(D_MODEL * KOUT / 4 + 255) / 256, 256>>>(
        out_proj_w, p_wo, D_MODEL * KOUT, KOUT);

    // 1) xz = x @ in_proj_w^T  (HMMA bf16x3)
    hmma_bf16_nt<<<dim3((2 * D_INNER) / 128, BL / 128, 1), 256, SMEM_MMA>>>(
        p_ax, p_wi, p_xz, 2 * D_INNER, KIN3, KIN3 / 32, nullptr);

    // 2) causal conv + silu, silu(z)
    conv_silu_kernel<<<(BL * D_INNER + 255) / 256, 256>>>(
        p_xz, conv_w, conv_bias, p_xsc, p_zs);

    // 3) dbc_{f,b}
    xproj_kernel<<<dim3(BL / 32, 2), 256>>>(
        p_xsc, x_proj_w, x_proj_b_w, p_dbc_f, p_dbc_b);

    // 4) delta_{f,b}
    sgemm_nt<1><<<dim3(D_INNER / 128, BL / 128, 2), 256>>>(
        p_dbc_f, DBC_N, dt_proj_w, DT_RANK, p_delta_f, D_INNER,
        DT_RANK, dt_proj_b,
        p_dbc_b, dt_proj_b_w, p_delta_b, dt_proj_b_b);

    // 5) selective scan
    scan_kernel<<<dim3(D_INNER / 32, NB, 2), 512>>>(
        p_delta_f, p_delta_b, p_dbc_f, p_dbc_b,
        A_log, A_b_log, p_xsc, p_y_f, p_y_b);

    // 6) fuse -> u bf16 triple
    fuse_kernel<<<(BL * D_INNER / 4 + 255) / 256, 256>>>(
        p_y_f, p_y_b, p_xsc, p_zs, D_param, D_b, p_u3);

    // 7) out = u @ out_proj_w^T  (HMMA bf16x3, split-K=2)
    hmma_bf16_nt<<<dim3(D_MODEL / 128, BL / 128, 2), 256, SMEM_MMA>>>(
        p_u3, p_wo, out, D_MODEL, KOUT3, KOUT3 / 32 / 2, p_part);
    addout_kernel<<<(BL * D_MODEL / 4 + 255) / 256, 256>>>(out, p_part);
}

// round 6
// speedup vs baseline: 2.8985x; 1.1014x over previous
#include <cuda_runtime.h>
#include <cuda_fp16.h>
#include <cstdint>
#include <cstddef>

// ---------------- problem constants ----------------
#define D_MODEL 768
#define D_INNER 1536
#define D_STATE 16
#define DT_RANK 48
#define NB 2
#define SEQ 1024
#define BL (NB * SEQ)                 // 2048
#define DBC_N (DT_RANK + 2 * D_STATE) // 80
#define KIN  D_MODEL                  // 768
#define KIN2 (2 * KIN)                // 1536
#define KOUT D_INNER                  // 1536
#define KOUT2 (2 * KOUT)              // 3072

// ---------------- scratch (static __device__ arrays; no allocs) ----------------
__device__ float g_xz[BL * 2 * D_INNER];
__device__ float g_partxz[BL * 2 * D_INNER];           // split-K partial for in_proj
__device__ float g_xsc[BL * D_INNER];
__device__ float g_zs[BL * D_INNER];
__device__ float g_dbc_f[BL * DBC_N];
__device__ float g_dbc_b[BL * DBC_N];
__device__ float g_delta_f[BL * D_INNER];
__device__ float g_delta_b[BL * D_INNER];
__device__ float g_y_f[BL * D_INNER];
__device__ float g_y_b[BL * D_INNER];
__device__ float g_part[BL * D_MODEL];                 // split-K partial for out_proj
__device__ __half g_ax[BL * KIN2];                     // x split (hi|lo)
__device__ __half g_wi[2 * D_INNER * KIN2];            // in_proj_w split (hi|hi)
__device__ __half g_u2[BL * KOUT2];                    // u split (hi|lo)
__device__ __half g_wo[D_MODEL * KOUT2];               // out_proj_w split (hi|hi)

// ---------------- math helpers ----------------
__device__ __forceinline__ float siluf(float x) { return x / (1.f + __expf(-x)); }
__device__ __forceinline__ float softplusf(float x) {
    return (x > 20.f) ? x : log1pf(__expf(x));
}

__device__ __forceinline__ uint32_t smem_u32(const void* p) {
    uint32_t a;
    asm("{ .reg .u64 t; cvta.to.shared.u64 t, %1; cvt.u32.u64 %0, t; }" : "=r"(a) : "l"(p));
    return a;
}
__device__ __forceinline__ void cp_async16(uint32_t saddr, const void* g) {
    asm volatile("cp.async.cg.shared.global [%0], [%1], 16;" :: "r"(saddr), "l"(g));
}
__device__ __forceinline__ void cp_commit() {
    asm volatile("cp.async.commit_group;" ::: "memory");
}
__device__ __forceinline__ void ldm_x4(uint32_t& r0, uint32_t& r1, uint32_t& r2,
                                       uint32_t& r3, uint32_t addr) {
    asm volatile("ldmatrix.sync.aligned.m8n8.x4.shared.b16 {%0,%1,%2,%3}, [%4];"
                 : "=r"(r0), "=r"(r1), "=r"(r2), "=r"(r3) : "r"(addr));
}
__device__ __forceinline__ void mma_f16(float* c, const uint32_t* a, const uint32_t* b) {
    asm volatile(
        "mma.sync.aligned.m16n8k16.row.col.f32.f16.f16.f32 "
        "{%0,%1,%2,%3}, {%4,%5,%6,%7}, {%8,%9}, {%0,%1,%2,%3};"
        : "+f"(c[0]), "+f"(c[1]), "+f"(c[2]), "+f"(c[3])
        : "r"(a[0]), "r"(a[1]), "r"(a[2]), "r"(a[3]), "r"(b[0]), "r"(b[1]));
}

// ---------------- HMMA fp16 GEMM: C[M,N] = A'[M,Kp] * B'[N,Kp]^T ----------------
// BM=BN=128, BK=32 fp16, 8 warps (4M x 2N), warp tile 32x64,
// 4-stage cp.async pipeline, 80B-padded rows, register-level B prefetch.
// Split-K over blockIdx.z: z=0 -> C, z=1 -> Cpart (summed afterwards).
// grid (N/128, M/128, nsplit), 256 threads, dynamic smem 81920B.
#define ROWB 80
#define STAGE_BYTES 20480
#define OFFB 10240
__global__ void __launch_bounds__(256) hmma_f16_nt(
    const __half* __restrict__ A,
    const __half* __restrict__ B,
    float* __restrict__ C, int ldc, int Kp, int nChunks,
    float* __restrict__ Cpart)
{
    extern __shared__ char smem[];
    const uint32_t sb = smem_u32(smem);
    const int tid = threadIdx.x;
    const int rowBase = blockIdx.y * 128;
    const int colBase = blockIdx.x * 128;
    const int chunkBase = blockIdx.z * nChunks;
    float* Cw = (blockIdx.z == 0) ? C : Cpart;

    // per-thread global->smem load slots (2 x 16B for A, 2 x 16B for B per stage)
    const int r0 = tid >> 2, c0 = tid & 3;
    const int r1 = (tid + 256) >> 2, c1 = (tid + 256) & 3;
    const char* gA0 = (const char*)(A + (size_t)(rowBase + r0) * Kp + c0 * 8)
                      + (size_t)chunkBase * 64;
    const char* gA1 = (const char*)(A + (size_t)(rowBase + r1) * Kp + c1 * 8)
                      + (size_t)chunkBase * 64;
    const char* gB0 = (const char*)(B + (size_t)(colBase + r0) * Kp + c0 * 8)
                      + (size_t)chunkBase * 64;
    const char* gB1 = (const char*)(B + (size_t)(colBase + r1) * Kp + c1 * 8)
                      + (size_t)chunkBase * 64;
    const uint32_t sA0 = r0 * ROWB + c0 * 16, sA1 = r1 * ROWB + c1 * 16;
    const uint32_t sB0 = OFFB + sA0, sB1 = OFFB + sA1;

#define LOAD_STAGE(c) do {                                                  \
    const uint32_t _base = sb + ((c) & 3) * STAGE_BYTES;                    \
    const size_t _gk = (size_t)(c) * 64;                                    \
    cp_async16(_base + sA0, gA0 + _gk);                                     \
    cp_async16(_base + sA1, gA1 + _gk);                                     \
    cp_async16(_base + sB0, gB0 + _gk);                                     \
    cp_async16(_base + sB1, gB1 + _gk);                                     \
} while (0)

    const int wid = tid >> 5;
    const int l = tid & 31;
    const int wm = wid & 3;       // 0..3 (M)
    const int wn = wid >> 2;      // 0..1 (N)

    // ldmatrix lane offsets
    const int a_row = ((l >> 3) & 1) * 8 + (l & 7);
    const int a_k   = (l >> 4) * 8;
    const int b_n   = (l >> 4) * 8 + (l & 7);
    const int b_k   = ((l >> 3) & 1) * 8;

    float acc[2][8][4];
#pragma unroll
    for (int i = 0; i < 2; i++)
#pragma unroll
        for (int j = 0; j < 8; j++)
#pragma unroll
            for (int q = 0; q < 4; q++) acc[i][j][q] = 0.f;

    LOAD_STAGE(0); cp_commit();
    LOAD_STAGE(1); cp_commit();
    LOAD_STAGE(2); cp_commit();

    for (int c = 0; c < nChunks; c++) {
        asm volatile("cp.async.wait_group 2;" ::: "memory");
        __syncthreads();

        if (c + 3 < nChunks) LOAD_STAGE(c + 3);
        cp_commit();

        const uint32_t stb = sb + (c & 3) * STAGE_BYTES;
        const uint32_t aW = stb + (wm * 32) * ROWB;
        const uint32_t bW = stb + OFFB + (wn * 64) * ROWB;

#pragma unroll
        for (int ks = 0; ks < 2; ks++) {
            uint32_t a[2][4];
#pragma unroll
            for (int mi = 0; mi < 2; mi++)
                ldm_x4(a[mi][0], a[mi][1], a[mi][2], a[mi][3],
                       aW + (mi * 16 + a_row) * ROWB + (ks * 16 + a_k) * 2);
            // register-level double buffer for B fragments
            uint32_t b[2][2][2];
            {
                uint32_t q0, q1, q2, q3;
                ldm_x4(q0, q1, q2, q3, bW + b_n * ROWB + (ks * 16 + b_k) * 2);
                b[0][0][0] = q0; b[0][0][1] = q1;
                b[0][1][0] = q2; b[0][1][1] = q3;
            }
#pragma unroll
            for (int nf = 0; nf < 4; nf++) {
                if (nf < 3) {
                    uint32_t q0, q1, q2, q3;
                    ldm_x4(q0, q1, q2, q3,
                           bW + ((nf + 1) * 16 + b_n) * ROWB + (ks * 16 + b_k) * 2);
                    const int nxt = (nf + 1) & 1;
                    b[nxt][0][0] = q0; b[nxt][0][1] = q1;
                    b[nxt][1][0] = q2; b[nxt][1][1] = q3;
                }
                const int cur = nf & 1;
#pragma unroll
                for (int mi = 0; mi < 2; mi++) {
                    mma_f16(acc[mi][nf * 2],     a[mi], b[cur][0]);
                    mma_f16(acc[mi][nf * 2 + 1], a[mi], b[cur][1]);
                }
            }
        }
    }

    // epilogue: direct float2 stores
    const int lrow = l >> 2;
    const int lcol = (l & 3) * 2;
#pragma unroll
    for (int mi = 0; mi < 2; mi++) {
        const int grow = rowBase + wm * 32 + mi * 16 + lrow;
#pragma unroll
        for (int nb = 0; nb < 8; nb++) {
            const int gcol = colBase + wn * 64 + nb * 8 + lcol;
            float2 v0 = make_float2(acc[mi][nb][0], acc[mi][nb][1]);
            float2 v1 = make_float2(acc[mi][nb][2], acc[mi][nb][3]);
            *(float2*)(Cw + (size_t)grow * ldc + gcol) = v0;
            *(float2*)(Cw + (size_t)(grow + 8) * ldc + gcol) = v1;
        }
    }
#undef LOAD_STAGE
}

// ---------------- split-K reduction: out += part ----------------
__global__ void addout_kernel(float* __restrict__ out, const float* __restrict__ part)
{
    const int i4 = blockIdx.x * blockDim.x + threadIdx.x;
    if (i4 * 4 >= BL * D_MODEL) return;
    float4 a = *(float4*)(out + (size_t)i4 * 4);
    const float4 b = *(const float4*)(part + (size_t)i4 * 4);
    a.x += b.x; a.y += b.y; a.z += b.z; a.w += b.w;
    *(float4*)(out + (size_t)i4 * 4) = a;
}

// ---------------- split fp32 -> fp16 pair ----------------
// MODEB=0: [hi|lo] for A operands; MODEB=1: [hi|hi] for B operands.
template <int MODEB>
__global__ void split2_kernel(const float* __restrict__ src,
                              __half* __restrict__ dst, int RK, int K)
{
    const int i4 = blockIdx.x * blockDim.x + threadIdx.x;
    if (i4 * 4 >= RK) return;
    const float4 v = *(const float4*)(src + (size_t)i4 * 4);
    const int r = (i4 * 4) / K;
    const int k = (i4 * 4) % K;
    float vv[4] = {v.x, v.y, v.z, v.w};
    unsigned short hs[4], ls[4];
#pragma unroll
    for (int j = 0; j < 4; j++) {
        __half h = __float2half_rn(vv[j]);
        __half lo = __float2half_rn(vv[j] - __half2float(h));
        hs[j] = __half_as_ushort(h);
        ls[j] = __half_as_ushort(lo);
    }
    const ushort4 H = make_ushort4(hs[0], hs[1], hs[2], hs[3]);
    const ushort4 L = make_ushort4(ls[0], ls[1], ls[2], ls[3]);
    const size_t base = (size_t)r * (2 * K) + k;
    *(ushort4*)((unsigned short*)dst + base) = H;
    *(ushort4*)((unsigned short*)dst + base + K) = MODEB ? H : L;
}

// ---------------- SGEMM (fp32) for dt_proj: softplus epilogue ----------------
template <int EPI>
__global__ void __launch_bounds__(256) sgemm_nt(
    const float* __restrict__ A, int lda,
    const float* __restrict__ B, int ldb,
    float* __restrict__ C, int ldc,
    int K, const float* __restrict__ bias,
    const float* __restrict__ A2, const float* __restrict__ B2,
    float* __restrict__ C2, const float* __restrict__ bias2)
{
    if (blockIdx.z == 1) { A = A2; B = B2; C = C2; bias = bias2; }
    constexpr int BK = 8, TM = 8, TN = 8;
    __shared__ float As[2][BK][128];
    __shared__ float Bs[2][BK][128];
    const int tid = threadIdx.x;
    const int rowBase = blockIdx.y * 128;
    const int colBase = blockIdx.x * 128;
    const int ldRow = tid >> 1;
    const int c4 = (tid & 1) << 2;
    const int trow = tid >> 4;
    const int tcol = tid & 15;
    const float* Aptr = A + (size_t)(rowBase + ldRow) * lda + c4;
    const float* Bptr = B + (size_t)(colBase + ldRow) * ldb + c4;
    float acc[TM][TN];
#pragma unroll
    for (int i = 0; i < TM; i++)
#pragma unroll
        for (int j = 0; j < TN; j++) acc[i][j] = 0.f;
    {
        float4 av = *(const float4*)(Aptr);
        float4 bv = *(const float4*)(Bptr);
        As[0][c4 + 0][ldRow] = av.x; As[0][c4 + 1][ldRow] = av.y;
        As[0][c4 + 2][ldRow] = av.z; As[0][c4 + 3][ldRow] = av.w;
        Bs[0][c4 + 0][ldRow] = bv.x; Bs[0][c4 + 1][ldRow] = bv.y;
        Bs[0][c4 + 2][ldRow] = bv.z; Bs[0][c4 + 3][ldRow] = bv.w;
    }
    __syncthreads();
    int buf = 0;
    for (int k0 = BK; k0 <= K; k0 += BK) {
        float4 av, bv;
        const bool more = (k0 < K);
        if (more) { av = *(const float4*)(Aptr + k0); bv = *(const float4*)(Bptr + k0); }
#pragma unroll
        for (int kk = 0; kk < BK; kk++) {
            float4 a0 = *(const float4*)(&As[buf][kk][trow * TM]);
            float4 a1 = *(const float4*)(&As[buf][kk][trow * TM + 4]);
            float4 b0 = *(const float4*)(&Bs[buf][kk][tcol * TN]);
            float4 b1 = *(const float4*)(&Bs[buf][kk][tcol * TN + 4]);
            float ra[8] = {a0.x, a0.y, a0.z, a0.w, a1.x, a1.y, a1.z, a1.w};
            float rb[8] = {b0.x, b0.y, b0.z, b0.w, b1.x, b1.y, b1.z, b1.w};
#pragma unroll
            for (int i = 0; i < 8; i++)
#pragma unroll
                for (int j = 0; j < 8; j++)
                    acc[i][j] = fmaf(ra[i], rb[j], acc[i][j]);
        }
        if (more) {
            const int nb = buf ^ 1;
            As[nb][c4 + 0][ldRow] = av.x; As[nb][c4 + 1][ldRow] = av.y;
            As[nb][c4 + 2][ldRow] = av.z; As[nb][c4 + 3][ldRow] = av.w;
            Bs[nb][c4 + 0][ldRow] = bv.x; Bs[nb][c4 + 1][ldRow] = bv.y;
            Bs[nb][c4 + 2][ldRow] = bv.z; Bs[nb][c4 + 3][ldRow] = bv.w;
        }
        __syncthreads();
        buf ^= 1;
    }
#pragma unroll
    for (int i = 0; i < TM; i++) {
        const int r = rowBase + trow * TM + i;
        float* Crow = C + (size_t)r * ldc + colBase + tcol * TN;
#pragma unroll
        for (int g = 0; g < 2; g++) {
            float vv[4];
#pragma unroll
            for (int q = 0; q < 4; q++) {
                float t = acc[i][g * 4 + q];
                if (EPI == 1) {
                    const int cidx = colBase + tcol * TN + g * 4 + q;
                    t = softplusf(t + bias[cidx]);
                }
                vv[q] = t;
            }
            float4 v; v.x = vv[0]; v.y = vv[1]; v.z = vv[2]; v.w = vv[3];
            *(float4*)(Crow + g * 4) = v;
        }
    }
}

// ---------------- x_proj: dbc[M,80] = xs @ W^T, both dirs ----------------
__global__ void __launch_bounds__(256) xproj_kernel(
    const float* __restrict__ xsc,
    const float* __restrict__ w_f, const float* __restrict__ w_b,
    float* __restrict__ dbc_f, float* __restrict__ dbc_b)
{
    const int dir = blockIdx.y;
    const float* W = dir ? w_b : w_f;
    float* C = dir ? dbc_b : dbc_f;
    const int m0 = blockIdx.x * 32;
    const int tid = threadIdx.x;
    const int trow = tid >> 4;
    const int tcol = tid & 15;
    constexpr int BK = 32;
    __shared__ float As[BK][32];
    __shared__ float Bs[BK][80];
    float acc0[5] = {0, 0, 0, 0, 0};
    float acc1[5] = {0, 0, 0, 0, 0};
    const int arow = tid >> 3;
    const int ac4 = (tid & 7) << 2;
    for (int k0 = 0; k0 < D_INNER; k0 += BK) {
        {
            float4 v = *(const float4*)(xsc + (size_t)(m0 + arow) * D_INNER + k0 + ac4);
            As[ac4 + 0][arow] = v.x; As[ac4 + 1][arow] = v.y;
            As[ac4 + 2][arow] = v.z; As[ac4 + 3][arow] = v.w;
        }
#pragma unroll
        for (int i = 0; i < 3; i++) {
            const int idx = tid + 256 * i;
            if (idx < 640) {
                const int n = idx >> 3;
                const int bc4 = (idx & 7) << 2;
                float4 v = *(const float4*)(W + (size_t)n * D_INNER + k0 + bc4);
                Bs[bc4 + 0][n] = v.x; Bs[bc4 + 1][n] = v.y;
                Bs[bc4 + 2][n] = v.z; Bs[bc4 + 3][n] = v.w;
            }
        }
        __syncthreads();
#pragma unroll
        for (int kk = 0; kk < BK; kk++) {
            const float a0 = As[kk][trow * 2];
            const float a1 = As[kk][trow * 2 + 1];
#pragma unroll
            for (int j = 0; j < 5; j++) {
                const float b = Bs[kk][tcol + 16 * j];
                acc0[j] = fmaf(a0, b, acc0[j]);
                acc1[j] = fmaf(a1, b, acc1[j]);
            }
        }
        __syncthreads();
    }
    const int r0 = m0 + trow * 2;
#pragma unroll
    for (int j = 0; j < 5; j++) {
        C[(size_t)r0 * DBC_N + tcol + 16 * j] = acc0[j];
        C[(size_t)(r0 + 1) * DBC_N + tcol + 16 * j] = acc1[j];
    }
}

// ---------------- causal conv(4) + SiLU + silu(z), fused in_proj split-K add ----------------
__global__ void conv_silu_kernel(
    const float* __restrict__ xz, const float* __restrict__ part,
    const float* __restrict__ cw, const float* __restrict__ cb,
    float* __restrict__ xsc, float* __restrict__ zs)
{
    const int idx = blockIdx.x * blockDim.x + threadIdx.x;
    if (idx >= BL * D_INNER) return;
    const int e = idx % D_INNER;
    const int row = idx / D_INNER;
    const int l = row & (SEQ - 1);
    const float w0 = cw[e * 4 + 0];
    const float w1 = cw[e * 4 + 1];
    const float w2 = cw[e * 4 + 2];
    const float w3 = cw[e * 4 + 3];
    const size_t base = (size_t)row * (2 * D_INNER) + e;
    float acc = cb[e];
    acc = fmaf(w3, xz[base] + part[base], acc);
    if (l >= 1) acc = fmaf(w2, xz[base - 2 * D_INNER] + part[base - 2 * D_INNER], acc);
    if (l >= 2) acc = fmaf(w1, xz[base - 4 * D_INNER] + part[base - 4 * D_INNER], acc);
    if (l >= 3) acc = fmaf(w0, xz[base - 6 * D_INNER] + part[base - 6 * D_INNER], acc);
    xsc[idx] = siluf(acc);
    const float z = xz[base + D_INNER] + part[base + D_INNER];
    zs[idx] = siluf(z);
}

// ---------------- selective scan ----------------
__global__ void __launch_bounds__(512) scan_kernel(
    const float* __restrict__ delta_f, const float* __restrict__ delta_b,
    const float* __restrict__ dbc_f,  const float* __restrict__ dbc_b,
    const float* __restrict__ A_log,  const float* __restrict__ A_b_log,
    const float* __restrict__ xsc,
    float* __restrict__ y_f, float* __restrict__ y_b)
{
    const int dir = blockIdx.z;
    const int b = blockIdx.y;
    const int e0 = blockIdx.x * 32;
    const int t = threadIdx.x;
    const int el = t >> 4;
    const int n = t & 15;
    const int e = e0 + el;
    const float* delta = dir ? delta_b : delta_f;
    const float* dbc = dir ? dbc_b : dbc_f;
    const float* Alog = dir ? A_b_log : A_log;
    float* y = dir ? y_b : y_f;
    const float An = -__expf(Alog[e * D_STATE + n]);
    __shared__ float s_d[16 * 32];
    __shared__ float s_x[16 * 32];
    __shared__ float s_bc[16 * 32];
    __shared__ float s_y[16 * 32];
    const int lj = t >> 5;
    const int lc = t & 31;
    float h = 0.f;
    const size_t rowb = (size_t)b * SEQ;
    for (int c = 0; c < SEQ / 16; c++) {
        {
            const int i = c * 16 + lj;
            const int l = dir ? (SEQ - 1 - i) : i;
            const size_t row = rowb + l;
            s_d[lj * 32 + lc]  = delta[row * D_INNER + e0 + lc];
            s_x[lj * 32 + lc]  = xsc[row * D_INNER + e0 + lc];
            s_bc[lj * 32 + lc] = dbc[row * DBC_N + DT_RANK + lc];
        }
        __syncthreads();
#pragma unroll
        for (int j = 0; j < 16; j++) {
            const float dlt = s_d[j * 32 + el];
            const float xv  = s_x[j * 32 + el];
            const float Bv  = s_bc[j * 32 + n];
            const float Cv  = s_bc[j * 32 + 16 + n];
            const float dA = __expf(dlt * An);
            h = fmaf(dA, h, dlt * xv * Bv);
            float p = h * Cv;
            p += __shfl_xor_sync(0xffffffffu, p, 8);
            p += __shfl_xor_sync(0xffffffffu, p, 4);
            p += __shfl_xor_sync(0xffffffffu, p, 2);
            p += __shfl_xor_sync(0xffffffffu, p, 1);
            if (n == 0) s_y[j * 32 + el] = p;
        }
        __syncthreads();
        {
            const int i = c * 16 + lj;
            const int l = dir ? (SEQ - 1 - i) : i;
            y[(rowb + l) * D_INNER + e0 + lc] = s_y[lj * 32 + lc];
        }
    }
}

// ---------------- fuse: u = (y_f + y_b + (D+D_b)*xs)*silu(z) -> fp16 pair ----------------
__global__ void fuse_kernel(
    const float* __restrict__ yf, const float* __restrict__ yb,
    const float* __restrict__ xsc, const float* __restrict__ zs,
    const float* __restrict__ D1, const float* __restrict__ D2,
    __half* __restrict__ u2)
{
    const int idx4 = blockIdx.x * blockDim.x + threadIdx.x;
    if (idx4 >= (BL * D_INNER) / 4) return;
    const int e4 = (idx4 * 4) % D_INNER;
    const int r = (idx4 * 4) / D_INNER;
    const float4 a = *(const float4*)(yf + (size_t)idx4 * 4);
    const float4 bq = *(const float4*)(yb + (size_t)idx4 * 4);
    const float4 xv = *(const float4*)(xsc + (size_t)idx4 * 4);
    const float4 zv = *(const float4*)(zs + (size_t)idx4 * 4);
    const float4 d1 = *(const float4*)(D1 + e4);
    const float4 d2 = *(const float4*)(D2 + e4);
    float vv[4];
    vv[0] = (a.x + bq.x + (d1.x + d2.x) * xv.x) * zv.x;
    vv[1] = (a.y + bq.y + (d1.y + d2.y) * xv.y) * zv.y;
    vv[2] = (a.z + bq.z + (d1.z + d2.z) * xv.z) * zv.z;
    vv[3] = (a.w + bq.w + (d1.w + d2.w) * xv.w) * zv.w;
    unsigned short hs[4], ls[4];
#pragma unroll
    for (int j = 0; j < 4; j++) {
        __half h = __float2half_rn(vv[j]);
        __half lo = __float2half_rn(vv[j] - __half2float(h));
        hs[j] = __half_as_ushort(h);
        ls[j] = __half_as_ushort(lo);
    }
    const ushort4 H = make_ushort4(hs[0], hs[1], hs[2], hs[3]);
    const ushort4 L = make_ushort4(ls[0], ls[1], ls[2], ls[3]);
    const size_t base = (size_t)r * KOUT2 + e4;
    *(ushort4*)((unsigned short*)u2 + base) = H;
    *(ushort4*)((unsigned short*)u2 + base + KOUT) = L;
}

// ---------------- launcher ----------------
extern "C" void kernel_launch(void* const* d_in, const int* in_sizes, int n_in,
                              void* d_out, int out_size)
{
    const float* x          = (const float*)d_in[0];
    const float* in_proj_w  = (const float*)d_in[1];
    const float* conv_w     = (const float*)d_in[2];
    const float* conv_bias  = (const float*)d_in[3];
    const float* x_proj_w   = (const float*)d_in[4];
    const float* dt_proj_w  = (const float*)d_in[5];
    const float* dt_proj_b  = (const float*)d_in[6];
    const float* A_log      = (const float*)d_in[7];
    const float* D_param    = (const float*)d_in[8];
    const float* out_proj_w = (const float*)d_in[9];
    const float* A_b_log    = (const float*)d_in[10];
    const float* x_proj_b_w = (const float*)d_in[11];
    const float* dt_proj_b_w= (const float*)d_in[12];
    const float* dt_proj_b_b= (const float*)d_in[13];
    const float* D_b        = (const float*)d_in[14];
    float* out = (float*)d_out;

    float *p_xz, *p_partxz, *p_xsc, *p_zs, *p_dbc_f, *p_dbc_b;
    float *p_delta_f, *p_delta_b, *p_y_f, *p_y_b, *p_part;
    __half *p_ax, *p_wi, *p_u2, *p_wo;
    cudaGetSymbolAddress((void**)&p_xz, g_xz);
    cudaGetSymbolAddress((void**)&p_partxz, g_partxz);
    cudaGetSymbolAddress((void**)&p_xsc, g_xsc);
    cudaGetSymbolAddress((void**)&p_zs, g_zs);
    cudaGetSymbolAddress((void**)&p_dbc_f, g_dbc_f);
    cudaGetSymbolAddress((void**)&p_dbc_b, g_dbc_b);
    cudaGetSymbolAddress((void**)&p_delta_f, g_delta_f);
    cudaGetSymbolAddress((void**)&p_delta_b, g_delta_b);
    cudaGetSymbolAddress((void**)&p_y_f, g_y_f);
    cudaGetSymbolAddress((void**)&p_y_b, g_y_b);
    cudaGetSymbolAddress((void**)&p_part, g_part);
    cudaGetSymbolAddress((void**)&p_ax, g_ax);
    cudaGetSymbolAddress((void**)&p_wi, g_wi);
    cudaGetSymbolAddress((void**)&p_u2, g_u2);
    cudaGetSymbolAddress((void**)&p_wo, g_wo);

    const int SMEM_MMA = 4 * STAGE_BYTES; // 81920
    cudaFuncSetAttribute(hmma_f16_nt, cudaFuncAttributeMaxDynamicSharedMemorySize, SMEM_MMA);

    // 0) split operands to fp16 pairs
    split2_kernel<0><<<(BL * KIN / 4 + 255) / 256, 256>>>(x, p_ax, BL * KIN, KIN);
    split2_kernel<1><<<(2 * D_INNER * KIN / 4 + 255) / 256, 256>>>(
        in_proj_w, p_wi, 2 * D_INNER * KIN, KIN);
    split2_kernel<1><<<(D_MODEL * KOUT / 4 + 255) / 256, 256>>>(
        out_proj_w, p_wo, D_MODEL * KOUT, KOUT);

    // 1) xz = x @ in_proj_w^T  (HMMA fp16x2, split-K=2)
    hmma_f16_nt<<<dim3((2 * D_INNER) / 128, BL / 128, 2), 256, SMEM_MMA>>>(
        p_ax, p_wi, p_xz, 2 * D_INNER, KIN2, KIN2 / 32 / 2, p_partxz);

    // 2) causal conv + silu, silu(z); fuses the in_proj split-K partial add
    conv_silu_kernel<<<(BL * D_INNER + 255) / 256, 256>>>(
        p_xz, p_partxz, conv_w, conv_bias, p_xsc, p_zs);

    // 3) dbc_{f,b}
    xproj_kernel<<<dim3(BL / 32, 2), 256>>>(
        p_xsc, x_proj_w, x_proj_b_w, p_dbc_f, p_dbc_b);

    // 4) delta_{f,b}
    sgemm_nt<1><<<dim3(D_INNER / 128, BL / 128, 2), 256>>>(
        p_dbc_f, DBC_N, dt_proj_w, DT_RANK, p_delta_f, D_INNER,
        DT_RANK, dt_proj_b,
        p_dbc_b, dt_proj_b_w, p_delta_b, dt_proj_b_b);

    // 5) selective scan
    scan_kernel<<<dim3(D_INNER / 32, NB, 2), 512>>>(
        p_delta_f, p_delta_b, p_dbc_f, p_dbc_b,
        A_log, A_b_log, p_xsc, p_y_f, p_y_b);

    // 6) fuse -> u fp16 pair
    fuse_kernel<<<(BL * D_INNER / 4 + 255) / 256, 256>>>(
        p_y_f, p_y_b, p_xsc, p_zs, D_param, D_b, p_u2);

    // 7) out = u @ out_proj_w^T  (HMMA fp16x2, split-K=2)
    hmma_f16_nt<<<dim3(D_MODEL / 128, BL / 128, 2), 256, SMEM_MMA>>>(
        p_u2, p_wo, out, D_MODEL, KOUT2, KOUT2 / 32 / 2, p_part);
    addout_kernel<<<(BL * D_MODEL / 4 + 255) / 256, 256>>>(out, p_part);
}

// round 7
// speedup vs baseline: 3.0215x; 1.0424x over previous
#include <cuda_runtime.h>
#include <cuda_fp16.h>
#include <cstdint>
#include <cstddef>

// ---------------- problem constants ----------------
#define D_MODEL 768
#define D_INNER 1536
#define D_STATE 16
#define DT_RANK 48
#define NB 2
#define SEQ 1024
#define BL (NB * SEQ)                 // 2048
#define DBC_N (DT_RANK + 2 * D_STATE) // 80
#define KIN  D_MODEL                  // 768
#define KIN2 (2 * KIN)                // 1536
#define KOUT D_INNER                  // 1536
#define KOUT2 (2 * KOUT)              // 3072

// ---------------- scratch (static __device__ arrays; no allocs) ----------------
__device__ float g_xz[BL * 2 * D_INNER];
__device__ float g_partxz[BL * 2 * D_INNER];           // split-K partial for in_proj
__device__ float g_xsc[BL * D_INNER];
__device__ float g_zs[BL * D_INNER];
__device__ float g_dbc_f[BL * DBC_N];
__device__ float g_dbc_b[BL * DBC_N];
__device__ float g_delta_f[BL * D_INNER];
__device__ float g_delta_b[BL * D_INNER];
__device__ float g_y_f[BL * D_INNER];
__device__ float g_y_b[BL * D_INNER];
__device__ float g_part[BL * D_MODEL];                 // split-K partial 1 for out_proj
__device__ float g_part2[BL * D_MODEL];                // split-K partial 2 for out_proj
__device__ __half g_ax[BL * KIN2];                     // x split (hi|lo)
__device__ __half g_wi[2 * D_INNER * KIN2];            // in_proj_w split (hi|hi)
__device__ __half g_u2[BL * KOUT2];                    // u split (hi|lo)
__device__ __half g_wo[D_MODEL * KOUT2];               // out_proj_w split (hi|hi)

// ---------------- math helpers ----------------
__device__ __forceinline__ float siluf(float x) { return x / (1.f + __expf(-x)); }
__device__ __forceinline__ float softplusf(float x) {
    return (x > 20.f) ? x : log1pf(__expf(x));
}

__device__ __forceinline__ uint32_t smem_u32(const void* p) {
    uint32_t a;
    asm("{ .reg .u64 t; cvta.to.shared.u64 t, %1; cvt.u32.u64 %0, t; }" : "=r"(a) : "l"(p));
    return a;
}
__device__ __forceinline__ void cp_async16(uint32_t saddr, const void* g) {
    asm volatile("cp.async.cg.shared.global [%0], [%1], 16;" :: "r"(saddr), "l"(g));
}
__device__ __forceinline__ void cp_commit() {
    asm volatile("cp.async.commit_group;" ::: "memory");
}
__device__ __forceinline__ void ldm_x4(uint32_t& r0, uint32_t& r1, uint32_t& r2,
                                       uint32_t& r3, uint32_t addr) {
    asm volatile("ldmatrix.sync.aligned.m8n8.x4.shared.b16 {%0,%1,%2,%3}, [%4];"
                 : "=r"(r0), "=r"(r1), "=r"(r2), "=r"(r3) : "r"(addr));
}
__device__ __forceinline__ void mma_f16(float* c, const uint32_t* a, const uint32_t* b) {
    asm volatile(
        "mma.sync.aligned.m16n8k16.row.col.f32.f16.f16.f32 "
        "{%0,%1,%2,%3}, {%4,%5,%6,%7}, {%8,%9}, {%0,%1,%2,%3};"
        : "+f"(c[0]), "+f"(c[1]), "+f"(c[2]), "+f"(c[3])
        : "r"(a[0]), "r"(a[1]), "r"(a[2]), "r"(a[3]), "r"(b[0]), "r"(b[1]));
}

// ---------------- HMMA fp16 GEMM: C[M,N] = A'[M,Kp] * B'[N,Kp]^T ----------------
// BM=BN=128, BK=32 fp16, 8 warps (4M x 2N), warp tile 32x64,
// 4-stage cp.async pipeline, 80B-padded rows.
// Per-chunk fragment pipeline: all A ldmatrix issued up front, B streamed
// through a 3-deep register ring with MMAs interleaved (4:1 MMA:ldm).
// Split-K over blockIdx.z: z=0 -> C, z=1 -> Cp1, z=2 -> Cp2.
// grid (N/128, M/128, nsplit), 256 threads, dynamic smem 81920B.
#define ROWB 80
#define STAGE_BYTES 20480
#define OFFB 10240
__global__ void __launch_bounds__(256) hmma_f16_nt(
    const __half* __restrict__ A,
    const __half* __restrict__ B,
    float* __restrict__ C, int ldc, int Kp, int nChunks,
    float* __restrict__ Cp1, float* __restrict__ Cp2)
{
    extern __shared__ char smem[];
    const uint32_t sb = smem_u32(smem);
    const int tid = threadIdx.x;
    const int rowBase = blockIdx.y * 128;
    const int colBase = blockIdx.x * 128;
    const int chunkBase = blockIdx.z * nChunks;
    float* Cw = (blockIdx.z == 0) ? C : ((blockIdx.z == 1) ? Cp1 : Cp2);

    // per-thread global->smem load slots (2 x 16B for A, 2 x 16B for B per stage)
    const int r0 = tid >> 2, c0 = tid & 3;
    const int r1 = (tid + 256) >> 2, c1 = (tid + 256) & 3;
    const char* gA0 = (const char*)(A + (size_t)(rowBase + r0) * Kp + c0 * 8)
                      + (size_t)chunkBase * 64;
    const char* gA1 = (const char*)(A + (size_t)(rowBase + r1) * Kp + c1 * 8)
                      + (size_t)chunkBase * 64;
    const char* gB0 = (const char*)(B + (size_t)(colBase + r0) * Kp + c0 * 8)
                      + (size_t)chunkBase * 64;
    const char* gB1 = (const char*)(B + (size_t)(colBase + r1) * Kp + c1 * 8)
                      + (size_t)chunkBase * 64;
    const uint32_t sA0 = r0 * ROWB + c0 * 16, sA1 = r1 * ROWB + c1 * 16;
    const uint32_t sB0 = OFFB + sA0, sB1 = OFFB + sA1;

#define LOAD_STAGE(c) do {                                                  \
    const uint32_t _base = sb + ((c) & 3) * STAGE_BYTES;                    \
    const size_t _gk = (size_t)(c) * 64;                                    \
    cp_async16(_base + sA0, gA0 + _gk);                                     \
    cp_async16(_base + sA1, gA1 + _gk);                                     \
    cp_async16(_base + sB0, gB0 + _gk);                                     \
    cp_async16(_base + sB1, gB1 + _gk);                                     \
} while (0)

    const int wid = tid >> 5;
    const int l = tid & 31;
    const int wm = wid & 3;       // 0..3 (M)
    const int wn = wid >> 2;      // 0..1 (N)

    // ldmatrix lane offsets
    const int a_row = ((l >> 3) & 1) * 8 + (l & 7);
    const int a_k   = (l >> 4) * 8;
    const int b_n   = (l >> 4) * 8 + (l & 7);
    const int b_k   = ((l >> 3) & 1) * 8;

    float acc[2][8][4];
#pragma unroll
    for (int i = 0; i < 2; i++)
#pragma unroll
        for (int j = 0; j < 8; j++)
#pragma unroll
            for (int q = 0; q < 4; q++) acc[i][j][q] = 0.f;

    LOAD_STAGE(0); cp_commit();
    LOAD_STAGE(1); cp_commit();
    LOAD_STAGE(2); cp_commit();

    for (int c = 0; c < nChunks; c++) {
        asm volatile("cp.async.wait_group 2;" ::: "memory");
        __syncthreads();

        if (c + 3 < nChunks) LOAD_STAGE(c + 3);
        cp_commit();

        const uint32_t stb = sb + (c & 3) * STAGE_BYTES;
        const uint32_t aW = stb + (wm * 32) * ROWB;
        const uint32_t bW = stb + OFFB + (wn * 64) * ROWB;

        // all A fragments for both k-halves up front (4 independent ldmatrix)
        uint32_t a[2][2][4];
#pragma unroll
        for (int ks = 0; ks < 2; ks++)
#pragma unroll
            for (int mi = 0; mi < 2; mi++)
                ldm_x4(a[ks][mi][0], a[ks][mi][1], a[ks][mi][2], a[ks][mi][3],
                       aW + (mi * 16 + a_row) * ROWB + (ks * 16 + a_k) * 2);

        // B fragment stream: 8 ldmatrix through a 3-deep register ring
        uint32_t b[3][4];
        ldm_x4(b[0][0], b[0][1], b[0][2], b[0][3],
               bW + b_n * ROWB + b_k * 2);                       // (ks0,nf0)
        ldm_x4(b[1][0], b[1][1], b[1][2], b[1][3],
               bW + (16 + b_n) * ROWB + b_k * 2);                // (ks0,nf1)
#pragma unroll
        for (int i = 0; i < 8; i++) {
            if (i + 2 < 8) {
                const int ks2 = (i + 2) >> 2, nf2 = (i + 2) & 3;
                const int slot = (i + 2) % 3;
                ldm_x4(b[slot][0], b[slot][1], b[slot][2], b[slot][3],
                       bW + (nf2 * 16 + b_n) * ROWB + (ks2 * 16 + b_k) * 2);
            }
            const int ks = i >> 2, nf = i & 3;
            const uint32_t* bb = b[i % 3];
#pragma unroll
            for (int mi = 0; mi < 2; mi++) {
                mma_f16(acc[mi][nf * 2],     a[ks][mi], bb);
                mma_f16(acc[mi][nf * 2 + 1], a[ks][mi], bb + 2);
            }
        }
    }

    // epilogue: direct float2 stores
    const int lrow = l >> 2;
    const int lcol = (l & 3) * 2;
#pragma unroll
    for (int mi = 0; mi < 2; mi++) {
        const int grow = rowBase + wm * 32 + mi * 16 + lrow;
#pragma unroll
        for (int nb = 0; nb < 8; nb++) {
            const int gcol = colBase + wn * 64 + nb * 8 + lcol;
            float2 v0 = make_float2(acc[mi][nb][0], acc[mi][nb][1]);
            float2 v1 = make_float2(acc[mi][nb][2], acc[mi][nb][3]);
            *(float2*)(Cw + (size_t)grow * ldc + gcol) = v0;
            *(float2*)(Cw + (size_t)(grow + 8) * ldc + gcol) = v1;
        }
    }
#undef LOAD_STAGE
}

// ---------------- split-K reduction: out += p1 + p2 ----------------
__global__ void addout2_kernel(float* __restrict__ out,
                               const float* __restrict__ p1,
                               const float* __restrict__ p2)
{
    const int i4 = blockIdx.x * blockDim.x + threadIdx.x;
    if (i4 * 4 >= BL * D_MODEL) return;
    float4 a = *(float4*)(out + (size_t)i4 * 4);
    const float4 b = *(const float4*)(p1 + (size_t)i4 * 4);
    const float4 c = *(const float4*)(p2 + (size_t)i4 * 4);
    a.x += b.x + c.x; a.y += b.y + c.y; a.z += b.z + c.z; a.w += b.w + c.w;
    *(float4*)(out + (size_t)i4 * 4) = a;
}

// ---------------- split fp32 -> fp16 pair ----------------
// MODEB=0: [hi|lo] for A operands; MODEB=1: [hi|hi] for B operands.
template <int MODEB>
__global__ void split2_kernel(const float* __restrict__ src,
                              __half* __restrict__ dst, int RK, int K)
{
    const int i4 = blockIdx.x * blockDim.x + threadIdx.x;
    if (i4 * 4 >= RK) return;
    const float4 v = *(const float4*)(src + (size_t)i4 * 4);
    const int r = (i4 * 4) / K;
    const int k = (i4 * 4) % K;
    float vv[4] = {v.x, v.y, v.z, v.w};
    unsigned short hs[4], ls[4];
#pragma unroll
    for (int j = 0; j < 4; j++) {
        __half h = __float2half_rn(vv[j]);
        __half lo = __float2half_rn(vv[j] - __half2float(h));
        hs[j] = __half_as_ushort(h);
        ls[j] = __half_as_ushort(lo);
    }
    const ushort4 H = make_ushort4(hs[0], hs[1], hs[2], hs[3]);
    const ushort4 L = make_ushort4(ls[0], ls[1], ls[2], ls[3]);
    const size_t base = (size_t)r * (2 * K) + k;
    *(ushort4*)((unsigned short*)dst + base) = H;
    *(ushort4*)((unsigned short*)dst + base + K) = MODEB ? H : L;
}

// ---------------- SGEMM (fp32) for dt_proj: softplus epilogue ----------------
template <int EPI>
__global__ void __launch_bounds__(256) sgemm_nt(
    const float* __restrict__ A, int lda,
    const float* __restrict__ B, int ldb,
    float* __restrict__ C, int ldc,
    int K, const float* __restrict__ bias,
    const float* __restrict__ A2, const float* __restrict__ B2,
    float* __restrict__ C2, const float* __restrict__ bias2)
{
    if (blockIdx.z == 1) { A = A2; B = B2; C = C2; bias = bias2; }
    constexpr int BK = 8, TM = 8, TN = 8;
    __shared__ float As[2][BK][128];
    __shared__ float Bs[2][BK][128];
    const int tid = threadIdx.x;
    const int rowBase = blockIdx.y * 128;
    const int colBase = blockIdx.x * 128;
    const int ldRow = tid >> 1;
    const int c4 = (tid & 1) << 2;
    const int trow = tid >> 4;
    const int tcol = tid & 15;
    const float* Aptr = A + (size_t)(rowBase + ldRow) * lda + c4;
    const float* Bptr = B + (size_t)(colBase + ldRow) * ldb + c4;
    float acc[TM][TN];
#pragma unroll
    for (int i = 0; i < TM; i++)
#pragma unroll
        for (int j = 0; j < TN; j++) acc[i][j] = 0.f;
    {
        float4 av = *(const float4*)(Aptr);
        float4 bv = *(const float4*)(Bptr);
        As[0][c4 + 0][ldRow] = av.x; As[0][c4 + 1][ldRow] = av.y;
        As[0][c4 + 2][ldRow] = av.z; As[0][c4 + 3][ldRow] = av.w;
        Bs[0][c4 + 0][ldRow] = bv.x; Bs[0][c4 + 1][ldRow] = bv.y;
        Bs[0][c4 + 2][ldRow] = bv.z; Bs[0][c4 + 3][ldRow] = bv.w;
    }
    __syncthreads();
    int buf = 0;
    for (int k0 = BK; k0 <= K; k0 += BK) {
        float4 av, bv;
        const bool more = (k0 < K);
        if (more) { av = *(const float4*)(Aptr + k0); bv = *(const float4*)(Bptr + k0); }
#pragma unroll
        for (int kk = 0; kk < BK; kk++) {
            float4 a0 = *(const float4*)(&As[buf][kk][trow * TM]);
            float4 a1 = *(const float4*)(&As[buf][kk][trow * TM + 4]);
            float4 b0 = *(const float4*)(&Bs[buf][kk][tcol * TN]);
            float4 b1 = *(const float4*)(&Bs[buf][kk][tcol * TN + 4]);
            float ra[8] = {a0.x, a0.y, a0.z, a0.w, a1.x, a1.y, a1.z, a1.w};
            float rb[8] = {b0.x, b0.y, b0.z, b0.w, b1.x, b1.y, b1.z, b1.w};
#pragma unroll
            for (int i = 0; i < 8; i++)
#pragma unroll
                for (int j = 0; j < 8; j++)
                    acc[i][j] = fmaf(ra[i], rb[j], acc[i][j]);
        }
        if (more) {
            const int nb = buf ^ 1;
            As[nb][c4 + 0][ldRow] = av.x; As[nb][c4 + 1][ldRow] = av.y;
            As[nb][c4 + 2][ldRow] = av.z; As[nb][c4 + 3][ldRow] = av.w;
            Bs[nb][c4 + 0][ldRow] = bv.x; Bs[nb][c4 + 1][ldRow] = bv.y;
            Bs[nb][c4 + 2][ldRow] = bv.z; Bs[nb][c4 + 3][ldRow] = bv.w;
        }
        __syncthreads();
        buf ^= 1;
    }
#pragma unroll
    for (int i = 0; i < TM; i++) {
        const int r = rowBase + trow * TM + i;
        float* Crow = C + (size_t)r * ldc + colBase + tcol * TN;
#pragma unroll
        for (int g = 0; g < 2; g++) {
            float vv[4];
#pragma unroll
            for (int q = 0; q < 4; q++) {
                float t = acc[i][g * 4 + q];
                if (EPI == 1) {
                    const int cidx = colBase + tcol * TN + g * 4 + q;
                    t = softplusf(t + bias[cidx]);
                }
                vv[q] = t;
            }
            float4 v; v.x = vv[0]; v.y = vv[1]; v.z = vv[2]; v.w = vv[3];
            *(float4*)(Crow + g * 4) = v;
        }
    }
}

// ---------------- x_proj: dbc[M,80] = xs @ W^T, both dirs ----------------
__global__ void __launch_bounds__(256) xproj_kernel(
    const float* __restrict__ xsc,
    const float* __restrict__ w_f, const float* __restrict__ w_b,
    float* __restrict__ dbc_f, float* __restrict__ dbc_b)
{
    const int dir = blockIdx.y;
    const float* W = dir ? w_b : w_f;
    float* C = dir ? dbc_b : dbc_f;
    const int m0 = blockIdx.x * 32;
    const int tid = threadIdx.x;
    const int trow = tid >> 4;
    const int tcol = tid & 15;
    constexpr int BK = 32;
    __shared__ float As[BK][32];
    __shared__ float Bs[BK][80];
    float acc0[5] = {0, 0, 0, 0, 0};
    float acc1[5] = {0, 0, 0, 0, 0};
    const int arow = tid >> 3;
    const int ac4 = (tid & 7) << 2;
    for (int k0 = 0; k0 < D_INNER; k0 += BK) {
        {
            float4 v = *(const float4*)(xsc + (size_t)(m0 + arow) * D_INNER + k0 + ac4);
            As[ac4 + 0][arow] = v.x; As[ac4 + 1][arow] = v.y;
            As[ac4 + 2][arow] = v.z; As[ac4 + 3][arow] = v.w;
        }
#pragma unroll
        for (int i = 0; i < 3; i++) {
            const int idx = tid + 256 * i;
            if (idx < 640) {
                const int n = idx >> 3;
                const int bc4 = (idx & 7) << 2;
                float4 v = *(const float4*)(W + (size_t)n * D_INNER + k0 + bc4);
                Bs[bc4 + 0][n] = v.x; Bs[bc4 + 1][n] = v.y;
                Bs[bc4 + 2][n] = v.z; Bs[bc4 + 3][n] = v.w;
            }
        }
        __syncthreads();
#pragma unroll
        for (int kk = 0; kk < BK; kk++) {
            const float a0 = As[kk][trow * 2];
            const float a1 = As[kk][trow * 2 + 1];
#pragma unroll
            for (int j = 0; j < 5; j++) {
                const float b = Bs[kk][tcol + 16 * j];
                acc0[j] = fmaf(a0, b, acc0[j]);
                acc1[j] = fmaf(a1, b, acc1[j]);
            }
        }
        __syncthreads();
    }
    const int r0 = m0 + trow * 2;
#pragma unroll
    for (int j = 0; j < 5; j++) {
        C[(size_t)r0 * DBC_N + tcol + 16 * j] = acc0[j];
        C[(size_t)(r0 + 1) * DBC_N + tcol + 16 * j] = acc1[j];
    }
}

// ---------------- causal conv(4) + SiLU + silu(z), fused in_proj split-K add ----------------
__global__ void conv_silu_kernel(
    const float* __restrict__ xz, const float* __restrict__ part,
    const float* __restrict__ cw, const float* __restrict__ cb,
    float* __restrict__ xsc, float* __restrict__ zs)
{
    const int idx = blockIdx.x * blockDim.x + threadIdx.x;
    if (idx >= BL * D_INNER) return;
    const int e = idx % D_INNER;
    const int row = idx / D_INNER;
    const int l = row & (SEQ - 1);
    const float w0 = cw[e * 4 + 0];
    const float w1 = cw[e * 4 + 1];
    const float w2 = cw[e * 4 + 2];
    const float w3 = cw[e * 4 + 3];
    const size_t base = (size_t)row * (2 * D_INNER) + e;
    float acc = cb[e];
    acc = fmaf(w3, xz[base] + part[base], acc);
    if (l >= 1) acc = fmaf(w2, xz[base - 2 * D_INNER] + part[base - 2 * D_INNER], acc);
    if (l >= 2) acc = fmaf(w1, xz[base - 4 * D_INNER] + part[base - 4 * D_INNER], acc);
    if (l >= 3) acc = fmaf(w0, xz[base - 6 * D_INNER] + part[base - 6 * D_INNER], acc);
    xsc[idx] = siluf(acc);
    const float z = xz[base + D_INNER] + part[base + D_INNER];
    zs[idx] = siluf(z);
}

// ---------------- selective scan ----------------
__global__ void __launch_bounds__(512) scan_kernel(
    const float* __restrict__ delta_f, const float* __restrict__ delta_b,
    const float* __restrict__ dbc_f,  const float* __restrict__ dbc_b,
    const float* __restrict__ A_log,  const float* __restrict__ A_b_log,
    const float* __restrict__ xsc,
    float* __restrict__ y_f, float* __restrict__ y_b)
{
    const int dir = blockIdx.z;
    const int b = blockIdx.y;
    const int e0 = blockIdx.x * 32;
    const int t = threadIdx.x;
    const int el = t >> 4;
    const int n = t & 15;
    const int e = e0 + el;
    const float* delta = dir ? delta_b : delta_f;
    const float* dbc = dir ? dbc_b : dbc_f;
    const float* Alog = dir ? A_b_log : A_log;
    float* y = dir ? y_b : y_f;
    const float An = -__expf(Alog[e * D_STATE + n]);
    __shared__ float s_d[16 * 32];
    __shared__ float s_x[16 * 32];
    __shared__ float s_bc[16 * 32];
    __shared__ float s_y[16 * 32];
    const int lj = t >> 5;
    const int lc = t & 31;
    float h = 0.f;
    const size_t rowb = (size_t)b * SEQ;
    for (int c = 0; c < SEQ / 16; c++) {
        {
            const int i = c * 16 + lj;
            const int l = dir ? (SEQ - 1 - i) : i;
            const size_t row = rowb + l;
            s_d[lj * 32 + lc]  = delta[row * D_INNER + e0 + lc];
            s_x[lj * 32 + lc]  = xsc[row * D_INNER + e0 + lc];
            s_bc[lj * 32 + lc] = dbc[row * DBC_N + DT_RANK + lc];
        }
        __syncthreads();
#pragma unroll
        for (int j = 0; j < 16; j++) {
            const float dlt = s_d[j * 32 + el];
            const float xv  = s_x[j * 32 + el];
            const float Bv  = s_bc[j * 32 + n];
            const float Cv  = s_bc[j * 32 + 16 + n];
            const float dA = __expf(dlt * An);
            h = fmaf(dA, h, dlt * xv * Bv);
            float p = h * Cv;
            p += __shfl_xor_sync(0xffffffffu, p, 8);
            p += __shfl_xor_sync(0xffffffffu, p, 4);
            p += __shfl_xor_sync(0xffffffffu, p, 2);
            p += __shfl_xor_sync(0xffffffffu, p, 1);
            if (n == 0) s_y[j * 32 + el] = p;
        }
        __syncthreads();
        {
            const int i = c * 16 + lj;
            const int l = dir ? (SEQ - 1 - i) : i;
            y[(rowb + l) * D_INNER + e0 + lc] = s_y[lj * 32 + lc];
        }
    }
}

// ---------------- fuse: u = (y_f + y_b + (D+D_b)*xs)*silu(z) -> fp16 pair ----------------
__global__ void fuse_kernel(
    const float* __restrict__ yf, const float* __restrict__ yb,
    const float* __restrict__ xsc, const float* __restrict__ zs,
    const float* __restrict__ D1, const float* __restrict__ D2,
    __half* __restrict__ u2)
{
    const int idx4 = blockIdx.x * blockDim.x + threadIdx.x;
    if (idx4 >= (BL * D_INNER) / 4) return;
    const int e4 = (idx4 * 4) % D_INNER;
    const int r = (idx4 * 4) / D_INNER;
    const float4 a = *(const float4*)(yf + (size_t)idx4 * 4);
    const float4 bq = *(const float4*)(yb + (size_t)idx4 * 4);
    const float4 xv = *(const float4*)(xsc + (size_t)idx4 * 4);
    const float4 zv = *(const float4*)(zs + (size_t)idx4 * 4);
    const float4 d1 = *(const float4*)(D1 + e4);
    const float4 d2 = *(const float4*)(D2 + e4);
    float vv[4];
    vv[0] = (a.x + bq.x + (d1.x + d2.x) * xv.x) * zv.x;
    vv[1] = (a.y + bq.y + (d1.y + d2.y) * xv.y) * zv.y;
    vv[2] = (a.z + bq.z + (d1.z + d2.z) * xv.z) * zv.z;
    vv[3] = (a.w + bq.w + (d1.w + d2.w) * xv.w) * zv.w;
    unsigned short hs[4], ls[4];
#pragma unroll
    for (int j = 0; j < 4; j++) {
        __half h = __float2half_rn(vv[j]);
        __half lo = __float2half_rn(vv[j] - __half2float(h));
        hs[j] = __half_as_ushort(h);
        ls[j] = __half_as_ushort(lo);
    }
    const ushort4 H = make_ushort4(hs[0], hs[1], hs[2], hs[3]);
    const ushort4 L = make_ushort4(ls[0], ls[1], ls[2], ls[3]);
    const size_t base = (size_t)r * KOUT2 + e4;
    *(ushort4*)((unsigned short*)u2 + base) = H;
    *(ushort4*)((unsigned short*)u2 + base + KOUT) = L;
}

// ---------------- launcher ----------------
extern "C" void kernel_launch(void* const* d_in, const int* in_sizes, int n_in,
                              void* d_out, int out_size)
{
    const float* x          = (const float*)d_in[0];
    const float* in_proj_w  = (const float*)d_in[1];
    const float* conv_w     = (const float*)d_in[2];
    const float* conv_bias  = (const float*)d_in[3];
    const float* x_proj_w   = (const float*)d_in[4];
    const float* dt_proj_w  = (const float*)d_in[5];
    const float* dt_proj_b  = (const float*)d_in[6];
    const float* A_log      = (const float*)d_in[7];
    const float* D_param    = (const float*)d_in[8];
    const float* out_proj_w = (const float*)d_in[9];
    const float* A_b_log    = (const float*)d_in[10];
    const float* x_proj_b_w = (const float*)d_in[11];
    const float* dt_proj_b_w= (const float*)d_in[12];
    const float* dt_proj_b_b= (const float*)d_in[13];
    const float* D_b        = (const float*)d_in[14];
    float* out = (float*)d_out;

    float *p_xz, *p_partxz, *p_xsc, *p_zs, *p_dbc_f, *p_dbc_b;
    float *p_delta_f, *p_delta_b, *p_y_f, *p_y_b, *p_part, *p_part2;
    __half *p_ax, *p_wi, *p_u2, *p_wo;
    cudaGetSymbolAddress((void**)&p_xz, g_xz);
    cudaGetSymbolAddress((void**)&p_partxz, g_partxz);
    cudaGetSymbolAddress((void**)&p_xsc, g_xsc);
    cudaGetSymbolAddress((void**)&p_zs, g_zs);
    cudaGetSymbolAddress((void**)&p_dbc_f, g_dbc_f);
    cudaGetSymbolAddress((void**)&p_dbc_b, g_dbc_b);
    cudaGetSymbolAddress((void**)&p_delta_f, g_delta_f);
    cudaGetSymbolAddress((void**)&p_delta_b, g_delta_b);
    cudaGetSymbolAddress((void**)&p_y_f, g_y_f);
    cudaGetSymbolAddress((void**)&p_y_b, g_y_b);
    cudaGetSymbolAddress((void**)&p_part, g_part);
    cudaGetSymbolAddress((void**)&p_part2, g_part2);
    cudaGetSymbolAddress((void**)&p_ax, g_ax);
    cudaGetSymbolAddress((void**)&p_wi, g_wi);
    cudaGetSymbolAddress((void**)&p_u2, g_u2);
    cudaGetSymbolAddress((void**)&p_wo, g_wo);

    const int SMEM_MMA = 4 * STAGE_BYTES; // 81920
    cudaFuncSetAttribute(hmma_f16_nt, cudaFuncAttributeMaxDynamicSharedMemorySize, SMEM_MMA);

    // 0) split operands to fp16 pairs
    split2_kernel<0><<<(BL * KIN / 4 + 255) / 256, 256>>>(x, p_ax, BL * KIN, KIN);
    split2_kernel<1><<<(2 * D_INNER * KIN / 4 + 255) / 256, 256>>>(
        in_proj_w, p_wi, 2 * D_INNER * KIN, KIN);
    split2_kernel<1><<<(D_MODEL * KOUT / 4 + 255) / 256, 256>>>(
        out_proj_w, p_wo, D_MODEL * KOUT, KOUT);

    // 1) xz = x @ in_proj_w^T  (HMMA fp16x2, split-K=2)
    hmma_f16_nt<<<dim3((2 * D_INNER) / 128, BL / 128, 2), 256, SMEM_MMA>>>(
        p_ax, p_wi, p_xz, 2 * D_INNER, KIN2, KIN2 / 32 / 2, p_partxz, nullptr);

    // 2) causal conv + silu, silu(z); fuses the in_proj split-K partial add
    conv_silu_kernel<<<(BL * D_INNER + 255) / 256, 256>>>(
        p_xz, p_partxz, conv_w, conv_bias, p_xsc, p_zs);

    // 3) dbc_{f,b}
    xproj_kernel<<<dim3(BL / 32, 2), 256>>>(
        p_xsc, x_proj_w, x_proj_b_w, p_dbc_f, p_dbc_b);

    // 4) delta_{f,b}
    sgemm_nt<1><<<dim3(D_INNER / 128, BL / 128, 2), 256>>>(
        p_dbc_f, DBC_N, dt_proj_w, DT_RANK, p_delta_f, D_INNER,
        DT_RANK, dt_proj_b,
        p_dbc_b, dt_proj_b_w, p_delta_b, dt_proj_b_b);

    // 5) selective scan
    scan_kernel<<<dim3(D_INNER / 32, NB, 2), 512>>>(
        p_delta_f, p_delta_b, p_dbc_f, p_dbc_b,
        A_log, A_b_log, p_xsc, p_y_f, p_y_b);

    // 6) fuse -> u fp16 pair
    fuse_kernel<<<(BL * D_INNER / 4 + 255) / 256, 256>>>(
        p_y_f, p_y_b, p_xsc, p_zs, D_param, D_b, p_u2);

    // 7) out = u @ out_proj_w^T  (HMMA fp16x2, split-K=3 -> exactly 1 wave)
    hmma_f16_nt<<<dim3(D_MODEL / 128, BL / 128, 3), 256, SMEM_MMA>>>(
        p_u2, p_wo, out, D_MODEL, KOUT2, KOUT2 / 32 / 3, p_part, p_part2);
    addout2_kernel<<<(BL * D_MODEL / 4 + 255) / 256, 256>>>(out, p_part, p_part2);
}

// round 8
// speedup vs baseline: 3.4813x; 1.1522x over previous
#include <cuda_runtime.h>
#include <cuda_fp16.h>
#include <cstdint>
#include <cstddef>

// ---------------- problem constants ----------------
#define D_MODEL 768
#define D_INNER 1536
#define D_STATE 16
#define DT_RANK 48
#define NB 2
#define SEQ 1024
#define BL (NB * SEQ)                 // 2048
#define KIN  D_MODEL                  // 768
#define KIN2 (2 * KIN)                // 1536
#define KOUT D_INNER                  // 1536
#define KOUT2 (2 * KOUT)              // 3072
#define DBC_PAD 256                   // padded dbc width (2 dirs x 128)

// ---------------- scratch (static __device__ arrays; zero-initialized) ----------------
__device__ float g_xz[BL * 2 * D_INNER];
__device__ float g_partxz[BL * 2 * D_INNER];
__device__ float g_xsc[BL * D_INNER];
__device__ float g_zs[BL * D_INNER];
__device__ float g_dbcp0[BL * DBC_PAD];
__device__ float g_dbcp1[BL * DBC_PAD];
__device__ float g_dbcp2[BL * DBC_PAD];
__device__ float g_dbc[BL * DBC_PAD];
__device__ float g_delta_f[BL * D_INNER];
__device__ float g_delta_b[BL * D_INNER];
__device__ float g_y_f[BL * D_INNER];
__device__ float g_y_b[BL * D_INNER];
__device__ float g_part[BL * D_MODEL];
__device__ float g_part2[BL * D_MODEL];
__device__ __half g_ax[BL * KIN2];                  // x split (hi|lo)
__device__ __half g_wi[2 * D_INNER * KIN2];         // in_proj_w split (hi|hi)
__device__ __half g_xsc16[BL * KOUT2];              // xsc split (hi|lo)
__device__ __half g_w3[DBC_PAD * KOUT2];            // x_proj weights padded (hi|hi), zero rows 80-127/208-255
__device__ __half g_wdt_f[D_INNER * 2 * DT_RANK];   // dt_proj_w split (hi|hi)
__device__ __half g_wdt_b[D_INNER * 2 * DT_RANK];
__device__ __half g_dbc48_f[BL * 2 * DT_RANK];      // dbc[:, :48] split (hi|lo)
__device__ __half g_dbc48_b[BL * 2 * DT_RANK];
__device__ __half g_u2[BL * KOUT2];                 // u split (hi|lo)
__device__ __half g_wo[D_MODEL * KOUT2];            // out_proj_w split (hi|hi)

// ---------------- math helpers ----------------
__device__ __forceinline__ float siluf(float x) { return x / (1.f + __expf(-x)); }
__device__ __forceinline__ float softplusf(float x) {
    return (x > 20.f) ? x : log1pf(__expf(x));
}

__device__ __forceinline__ uint32_t smem_u32(const void* p) {
    uint32_t a;
    asm("{ .reg .u64 t; cvta.to.shared.u64 t, %1; cvt.u32.u64 %0, t; }" : "=r"(a) : "l"(p));
    return a;
}
__device__ __forceinline__ void cp_async16(uint32_t saddr, const void* g) {
    asm volatile("cp.async.cg.shared.global [%0], [%1], 16;" :: "r"(saddr), "l"(g));
}
__device__ __forceinline__ void cp_commit() {
    asm volatile("cp.async.commit_group;" ::: "memory");
}
__device__ __forceinline__ void ldm_x4(uint32_t& r0, uint32_t& r1, uint32_t& r2,
                                       uint32_t& r3, uint32_t addr) {
    asm volatile("ldmatrix.sync.aligned.m8n8.x4.shared.b16 {%0,%1,%2,%3}, [%4];"
                 : "=r"(r0), "=r"(r1), "=r"(r2), "=r"(r3) : "r"(addr));
}
__device__ __forceinline__ void mma_f16(float* c, const uint32_t* a, const uint32_t* b) {
    asm volatile(
        "mma.sync.aligned.m16n8k16.row.col.f32.f16.f16.f32 "
        "{%0,%1,%2,%3}, {%4,%5,%6,%7}, {%8,%9}, {%0,%1,%2,%3};"
        : "+f"(c[0]), "+f"(c[1]), "+f"(c[2]), "+f"(c[3])
        : "r"(a[0]), "r"(a[1]), "r"(a[2]), "r"(a[3]), "r"(b[0]), "r"(b[1]));
}
__device__ __forceinline__ void split_h(float v, unsigned short& hi, unsigned short& lo) {
    __half h = __float2half_rn(v);
    __half l = __float2half_rn(v - __half2float(h));
    hi = __half_as_ushort(h); lo = __half_as_ushort(l);
}

// ---------------- HMMA fp16 GEMM: C[M,N] = A'[M,Kp] * B'[N,Kp]^T ----------------
// BM=BN=128, BK=32 fp16, 8 warps (4M x 2N), warp tile 32x64,
// 4-stage cp.async pipeline, 80B-padded rows.
// EPI: 0 = plain store, 1 = softplus(v + bias[col]).
// ZMODE: 0 = split-K (z -> C/Cp1/Cp2); 1 = two problems (z=1 -> A2/B2/C2/bias2).
#define ROWB 80
#define STAGE_BYTES 20480
#define OFFB 10240
template <int EPI, int ZMODE>
__global__ void __launch_bounds__(256) hmma_f16_nt(
    const __half* __restrict__ A,
    const __half* __restrict__ B,
    float* __restrict__ C, int ldc, int Kp, int nChunks,
    float* __restrict__ Cp1, float* __restrict__ Cp2,
    const float* __restrict__ bias,
    const __half* __restrict__ A2, const __half* __restrict__ B2,
    float* __restrict__ C2, const float* __restrict__ bias2)
{
    extern __shared__ char smem[];
    const uint32_t sb = smem_u32(smem);
    const int tid = threadIdx.x;
    const int rowBase = blockIdx.y * 128;
    const int colBase = blockIdx.x * 128;
    float* Cw;
    int chunkBase;
    if (ZMODE == 1) {
        if (blockIdx.z == 1) { A = A2; B = B2; C = C2; bias = bias2; }
        Cw = C; chunkBase = 0;
    } else {
        Cw = (blockIdx.z == 0) ? C : ((blockIdx.z == 1) ? Cp1 : Cp2);
        chunkBase = blockIdx.z * nChunks;
    }

    const int r0 = tid >> 2, c0 = tid & 3;
    const int r1 = (tid + 256) >> 2, c1 = (tid + 256) & 3;
    const char* gA0 = (const char*)(A + (size_t)(rowBase + r0) * Kp + c0 * 8)
                      + (size_t)chunkBase * 64;
    const char* gA1 = (const char*)(A + (size_t)(rowBase + r1) * Kp + c1 * 8)
                      + (size_t)chunkBase * 64;
    const char* gB0 = (const char*)(B + (size_t)(colBase + r0) * Kp + c0 * 8)
                      + (size_t)chunkBase * 64;
    const char* gB1 = (const char*)(B + (size_t)(colBase + r1) * Kp + c1 * 8)
                      + (size_t)chunkBase * 64;
    const uint32_t sA0 = r0 * ROWB + c0 * 16, sA1 = r1 * ROWB + c1 * 16;
    const uint32_t sB0 = OFFB + sA0, sB1 = OFFB + sA1;

#define LOAD_STAGE(c) do {                                                  \
    const uint32_t _base = sb + ((c) & 3) * STAGE_BYTES;                    \
    const size_t _gk = (size_t)(c) * 64;                                    \
    cp_async16(_base + sA0, gA0 + _gk);                                     \
    cp_async16(_base + sA1, gA1 + _gk);                                     \
    cp_async16(_base + sB0, gB0 + _gk);                                     \
    cp_async16(_base + sB1, gB1 + _gk);                                     \
} while (0)

    const int wid = tid >> 5;
    const int l = tid & 31;
    const int wm = wid & 3;
    const int wn = wid >> 2;

    const int a_row = ((l >> 3) & 1) * 8 + (l & 7);
    const int a_k   = (l >> 4) * 8;
    const int b_n   = (l >> 4) * 8 + (l & 7);
    const int b_k   = ((l >> 3) & 1) * 8;

    float acc[2][8][4];
#pragma unroll
    for (int i = 0; i < 2; i++)
#pragma unroll
        for (int j = 0; j < 8; j++)
#pragma unroll
            for (int q = 0; q < 4; q++) acc[i][j][q] = 0.f;

    LOAD_STAGE(0); cp_commit();
    if (nChunks > 1) LOAD_STAGE(1);
    cp_commit();
    if (nChunks > 2) LOAD_STAGE(2);
    cp_commit();

    for (int c = 0; c < nChunks; c++) {
        asm volatile("cp.async.wait_group 2;" ::: "memory");
        __syncthreads();

        if (c + 3 < nChunks) LOAD_STAGE(c + 3);
        cp_commit();

        const uint32_t stb = sb + (c & 3) * STAGE_BYTES;
        const uint32_t aW = stb + (wm * 32) * ROWB;
        const uint32_t bW = stb + OFFB + (wn * 64) * ROWB;

        uint32_t a[2][2][4];
#pragma unroll
        for (int ks = 0; ks < 2; ks++)
#pragma unroll
            for (int mi = 0; mi < 2; mi++)
                ldm_x4(a[ks][mi][0], a[ks][mi][1], a[ks][mi][2], a[ks][mi][3],
                       aW + (mi * 16 + a_row) * ROWB + (ks * 16 + a_k) * 2);

        uint32_t b[3][4];
        ldm_x4(b[0][0], b[0][1], b[0][2], b[0][3],
               bW + b_n * ROWB + b_k * 2);
        ldm_x4(b[1][0], b[1][1], b[1][2], b[1][3],
               bW + (16 + b_n) * ROWB + b_k * 2);
#pragma unroll
        for (int i = 0; i < 8; i++) {
            if (i + 2 < 8) {
                const int ks2 = (i + 2) >> 2, nf2 = (i + 2) & 3;
                const int slot = (i + 2) % 3;
                ldm_x4(b[slot][0], b[slot][1], b[slot][2], b[slot][3],
                       bW + (nf2 * 16 + b_n) * ROWB + (ks2 * 16 + b_k) * 2);
            }
            const int ks = i >> 2, nf = i & 3;
            const uint32_t* bb = b[i % 3];
#pragma unroll
            for (int mi = 0; mi < 2; mi++) {
                mma_f16(acc[mi][nf * 2],     a[ks][mi], bb);
                mma_f16(acc[mi][nf * 2 + 1], a[ks][mi], bb + 2);
            }
        }
    }

    const int lrow = l >> 2;
    const int lcol = (l & 3) * 2;
#pragma unroll
    for (int mi = 0; mi < 2; mi++) {
        const int grow = rowBase + wm * 32 + mi * 16 + lrow;
#pragma unroll
        for (int nb = 0; nb < 8; nb++) {
            const int gcol = colBase + wn * 64 + nb * 8 + lcol;
            float v0 = acc[mi][nb][0], v1 = acc[mi][nb][1];
            float v2 = acc[mi][nb][2], v3 = acc[mi][nb][3];
            if (EPI == 1) {
                v0 = softplusf(v0 + bias[gcol]);
                v1 = softplusf(v1 + bias[gcol + 1]);
                v2 = softplusf(v2 + bias[gcol]);
                v3 = softplusf(v3 + bias[gcol + 1]);
            }
            *(float2*)(Cw + (size_t)grow * ldc + gcol) = make_float2(v0, v1);
            *(float2*)(Cw + (size_t)(grow + 8) * ldc + gcol) = make_float2(v2, v3);
        }
    }
#undef LOAD_STAGE
}

// ---------------- split-K reduction: out += p1 + p2 ----------------
__global__ void addout2_kernel(float* __restrict__ out,
                               const float* __restrict__ p1,
                               const float* __restrict__ p2)
{
    const int i4 = blockIdx.x * blockDim.x + threadIdx.x;
    if (i4 * 4 >= BL * D_MODEL) return;
    float4 a = *(float4*)(out + (size_t)i4 * 4);
    const float4 b = *(const float4*)(p1 + (size_t)i4 * 4);
    const float4 c = *(const float4*)(p2 + (size_t)i4 * 4);
    a.x += b.x + c.x; a.y += b.y + c.y; a.z += b.z + c.z; a.w += b.w + c.w;
    *(float4*)(out + (size_t)i4 * 4) = a;
}

// ---------------- split fp32 -> fp16 pair ----------------
// MODEB=0: [hi|lo]; MODEB=1: [hi|hi].
template <int MODEB>
__global__ void split2_kernel(const float* __restrict__ src,
                              __half* __restrict__ dst, int RK, int K)
{
    const int i4 = blockIdx.x * blockDim.x + threadIdx.x;
    if (i4 * 4 >= RK) return;
    const float4 v = *(const float4*)(src + (size_t)i4 * 4);
    const int r = (i4 * 4) / K;
    const int k = (i4 * 4) % K;
    float vv[4] = {v.x, v.y, v.z, v.w};
    unsigned short hs[4], ls[4];
#pragma unroll
    for (int j = 0; j < 4; j++) split_h(vv[j], hs[j], ls[j]);
    const ushort4 H = make_ushort4(hs[0], hs[1], hs[2], hs[3]);
    const ushort4 L = make_ushort4(ls[0], ls[1], ls[2], ls[3]);
    const size_t base = (size_t)r * (2 * K) + k;
    *(ushort4*)((unsigned short*)dst + base) = H;
    *(ushort4*)((unsigned short*)dst + base + K) = MODEB ? H : L;
}

// ---------------- build padded x_proj weight (hi|hi), both dirs ----------------
__global__ void splitw3_kernel(const float* __restrict__ wf,
                               const float* __restrict__ wb,
                               __half* __restrict__ w3)
{
    const int i4 = blockIdx.x * blockDim.x + threadIdx.x;
    const int total = 2 * 80 * D_INNER;
    if (i4 * 4 >= total) return;
    const int t = i4 * 4;
    const int dir = t / (80 * D_INNER);
    const int rem = t % (80 * D_INNER);
    const int n = rem / D_INNER;
    const int k = rem % D_INNER;
    const float* w = dir ? wb : wf;
    const float4 v = *(const float4*)(w + (size_t)n * D_INNER + k);
    float vv[4] = {v.x, v.y, v.z, v.w};
    unsigned short hs[4], ls[4];
#pragma unroll
    for (int j = 0; j < 4; j++) split_h(vv[j], hs[j], ls[j]);
    const ushort4 H = make_ushort4(hs[0], hs[1], hs[2], hs[3]);
    const size_t base = (size_t)(dir * 128 + n) * KOUT2 + k;
    *(ushort4*)((unsigned short*)w3 + base) = H;
    *(ushort4*)((unsigned short*)w3 + base + D_INNER) = H;
}

// ---------------- split dt_proj weights (hi|hi), both dirs ----------------
__global__ void splitdt_kernel(const float* __restrict__ wf,
                               const float* __restrict__ wb,
                               __half* __restrict__ of, __half* __restrict__ ob)
{
    const int i4 = blockIdx.x * blockDim.x + threadIdx.x;
    const int total = 2 * D_INNER * DT_RANK;
    if (i4 * 4 >= total) return;
    const int t = i4 * 4;
    const int dir = t / (D_INNER * DT_RANK);
    const int rem = t % (D_INNER * DT_RANK);
    const int n = rem / DT_RANK;
    const int k = rem % DT_RANK;
    const float* w = dir ? wb : wf;
    __half* o = dir ? ob : of;
    const float4 v = *(const float4*)(w + (size_t)n * DT_RANK + k);
    float vv[4] = {v.x, v.y, v.z, v.w};
    unsigned short hs[4], ls[4];
#pragma unroll
    for (int j = 0; j < 4; j++) split_h(vv[j], hs[j], ls[j]);
    const ushort4 H = make_ushort4(hs[0], hs[1], hs[2], hs[3]);
    const size_t base = (size_t)n * (2 * DT_RANK) + k;
    *(ushort4*)((unsigned short*)o + base) = H;
    *(ushort4*)((unsigned short*)o + base + DT_RANK) = H;
}

// ---------------- combine x_proj split-K partials; emit fp16 dbc48 ----------------
__global__ void dbc_combine_kernel(const float* __restrict__ p0,
                                   const float* __restrict__ p1,
                                   const float* __restrict__ p2,
                                   float* __restrict__ dbc,
                                   __half* __restrict__ d48f,
                                   __half* __restrict__ d48b)
{
    const int i4 = blockIdx.x * blockDim.x + threadIdx.x;
    if (i4 * 4 >= BL * DBC_PAD) return;
    const int t = i4 * 4;
    const int row = t / DBC_PAD;
    const int c = t % DBC_PAD;
    const float4 a = *(const float4*)(p0 + (size_t)i4 * 4);
    const float4 b = *(const float4*)(p1 + (size_t)i4 * 4);
    const float4 d = *(const float4*)(p2 + (size_t)i4 * 4);
    float vv[4] = {a.x + b.x + d.x, a.y + b.y + d.y, a.z + b.z + d.z, a.w + b.w + d.w};
    *(float4*)(dbc + (size_t)i4 * 4) = make_float4(vv[0], vv[1], vv[2], vv[3]);

    __half* o = nullptr;
    int cc = 0;
    if (c < DT_RANK) { o = d48f; cc = c; }
    else if (c >= 128 && c < 128 + DT_RANK) { o = d48b; cc = c - 128; }
    if (o) {
        unsigned short hs[4], ls[4];
#pragma unroll
        for (int j = 0; j < 4; j++) split_h(vv[j], hs[j], ls[j]);
        const size_t base = (size_t)row * (2 * DT_RANK) + cc;
        *(ushort4*)((unsigned short*)o + base) = make_ushort4(hs[0], hs[1], hs[2], hs[3]);
        *(ushort4*)((unsigned short*)o + base + DT_RANK) = make_ushort4(ls[0], ls[1], ls[2], ls[3]);
    }
}

// ---------------- causal conv(4) + SiLU + silu(z) + fp16 split of xsc ----------------
__global__ void conv_silu_kernel(
    const float* __restrict__ xz, const float* __restrict__ part,
    const float* __restrict__ cw, const float* __restrict__ cb,
    float* __restrict__ xsc, float* __restrict__ zs,
    __half* __restrict__ xsc16)
{
    const int idx = blockIdx.x * blockDim.x + threadIdx.x;
    if (idx >= BL * D_INNER) return;
    const int e = idx % D_INNER;
    const int row = idx / D_INNER;
    const int l = row & (SEQ - 1);
    const float w0 = cw[e * 4 + 0];
    const float w1 = cw[e * 4 + 1];
    const float w2 = cw[e * 4 + 2];
    const float w3 = cw[e * 4 + 3];
    const size_t base = (size_t)row * (2 * D_INNER) + e;
    float acc = cb[e];
    acc = fmaf(w3, xz[base] + part[base], acc);
    if (l >= 1) acc = fmaf(w2, xz[base - 2 * D_INNER] + part[base - 2 * D_INNER], acc);
    if (l >= 2) acc = fmaf(w1, xz[base - 4 * D_INNER] + part[base - 4 * D_INNER], acc);
    if (l >= 3) acc = fmaf(w0, xz[base - 6 * D_INNER] + part[base - 6 * D_INNER], acc);
    const float xs = siluf(acc);
    xsc[idx] = xs;
    unsigned short hi, lo;
    split_h(xs, hi, lo);
    unsigned short* o = (unsigned short*)xsc16 + (size_t)row * KOUT2 + e;
    o[0] = hi;
    o[D_INNER] = lo;
    const float z = xz[base + D_INNER] + part[base + D_INNER];
    zs[idx] = siluf(z);
}

// ---------------- selective scan ----------------
__global__ void __launch_bounds__(512) scan_kernel(
    const float* __restrict__ delta_f, const float* __restrict__ delta_b,
    const float* __restrict__ dbc,
    const float* __restrict__ A_log,  const float* __restrict__ A_b_log,
    const float* __restrict__ xsc,
    float* __restrict__ y_f, float* __restrict__ y_b)
{
    const int dir = blockIdx.z;
    const int b = blockIdx.y;
    const int e0 = blockIdx.x * 32;
    const int t = threadIdx.x;
    const int el = t >> 4;
    const int n = t & 15;
    const int e = e0 + el;
    const float* delta = dir ? delta_b : delta_f;
    const float* Alog = dir ? A_b_log : A_log;
    float* y = dir ? y_b : y_f;
    const int bcoff = dir * 128 + DT_RANK;
    const float An = -__expf(Alog[e * D_STATE + n]);
    __shared__ float s_d[16 * 32];
    __shared__ float s_x[16 * 32];
    __shared__ float s_bc[16 * 32];
    __shared__ float s_y[16 * 32];
    const int lj = t >> 5;
    const int lc = t & 31;
    float h = 0.f;
    const size_t rowb = (size_t)b * SEQ;
    for (int c = 0; c < SEQ / 16; c++) {
        {
            const int i = c * 16 + lj;
            const int l = dir ? (SEQ - 1 - i) : i;
            const size_t row = rowb + l;
            s_d[lj * 32 + lc]  = delta[row * D_INNER + e0 + lc];
            s_x[lj * 32 + lc]  = xsc[row * D_INNER + e0 + lc];
            s_bc[lj * 32 + lc] = dbc[row * DBC_PAD + bcoff + lc];
        }
        __syncthreads();
#pragma unroll
        for (int j = 0; j < 16; j++) {
            const float dlt = s_d[j * 32 + el];
            const float xv  = s_x[j * 32 + el];
            const float Bv  = s_bc[j * 32 + n];
            const float Cv  = s_bc[j * 32 + 16 + n];
            const float dA = __expf(dlt * An);
            h = fmaf(dA, h, dlt * xv * Bv);
            float p = h * Cv;
            p += __shfl_xor_sync(0xffffffffu, p, 8);
            p += __shfl_xor_sync(0xffffffffu, p, 4);
            p += __shfl_xor_sync(0xffffffffu, p, 2);
            p += __shfl_xor_sync(0xffffffffu, p, 1);
            if (n == 0) s_y[j * 32 + el] = p;
        }
        __syncthreads();
        {
            const int i = c * 16 + lj;
            const int l = dir ? (SEQ - 1 - i) : i;
            y[(rowb + l) * D_INNER + e0 + lc] = s_y[lj * 32 + lc];
        }
    }
}

// ---------------- fuse: u = (y_f + y_b + (D+D_b)*xs)*silu(z) -> fp16 pair ----------------
__global__ void fuse_kernel(
    const float* __restrict__ yf, const float* __restrict__ yb,
    const float* __restrict__ xsc, const float* __restrict__ zs,
    const float* __restrict__ D1, const float* __restrict__ D2,
    __half* __restrict__ u2)
{
    const int idx4 = blockIdx.x * blockDim.x + threadIdx.x;
    if (idx4 >= (BL * D_INNER) / 4) return;
    const int e4 = (idx4 * 4) % D_INNER;
    const int r = (idx4 * 4) / D_INNER;
    const float4 a = *(const float4*)(yf + (size_t)idx4 * 4);
    const float4 bq = *(const float4*)(yb + (size_t)idx4 * 4);
    const float4 xv = *(const float4*)(xsc + (size_t)idx4 * 4);
    const float4 zv = *(const float4*)(zs + (size_t)idx4 * 4);
    const float4 d1 = *(const float4*)(D1 + e4);
    const float4 d2 = *(const float4*)(D2 + e4);
    float vv[4];
    vv[0] = (a.x + bq.x + (d1.x + d2.x) * xv.x) * zv.x;
    vv[1] = (a.y + bq.y + (d1.y + d2.y) * xv.y) * zv.y;
    vv[2] = (a.z + bq.z + (d1.z + d2.z) * xv.z) * zv.z;
    vv[3] = (a.w + bq.w + (d1.w + d2.w) * xv.w) * zv.w;
    unsigned short hs[4], ls[4];
#pragma unroll
    for (int j = 0; j < 4; j++) split_h(vv[j], hs[j], ls[j]);
    const size_t base = (size_t)r * KOUT2 + e4;
    *(ushort4*)((unsigned short*)u2 + base) = make_ushort4(hs[0], hs[1], hs[2], hs[3]);
    *(ushort4*)((unsigned short*)u2 + base + KOUT) = make_ushort4(ls[0], ls[1], ls[2], ls[3]);
}

// ---------------- launcher ----------------
extern "C" void kernel_launch(void* const* d_in, const int* in_sizes, int n_in,
                              void* d_out, int out_size)
{
    const float* x          = (const float*)d_in[0];
    const float* in_proj_w  = (const float*)d_in[1];
    const float* conv_w     = (const float*)d_in[2];
    const float* conv_bias  = (const float*)d_in[3];
    const float* x_proj_w   = (const float*)d_in[4];
    const float* dt_proj_w  = (const float*)d_in[5];
    const float* dt_proj_b  = (const float*)d_in[6];
    const float* A_log      = (const float*)d_in[7];
    const float* D_param    = (const float*)d_in[8];
    const float* out_proj_w = (const float*)d_in[9];
    const float* A_b_log    = (const float*)d_in[10];
    const float* x_proj_b_w = (const float*)d_in[11];
    const float* dt_proj_b_w= (const float*)d_in[12];
    const float* dt_proj_b_b= (const float*)d_in[13];
    const float* D_b        = (const float*)d_in[14];
    float* out = (float*)d_out;

    float *p_xz, *p_partxz, *p_xsc, *p_zs, *p_dbcp0, *p_dbcp1, *p_dbcp2, *p_dbc;
    float *p_delta_f, *p_delta_b, *p_y_f, *p_y_b, *p_part, *p_part2;
    __half *p_ax, *p_wi, *p_xsc16, *p_w3, *p_wdtf, *p_wdtb, *p_d48f, *p_d48b, *p_u2, *p_wo;
    cudaGetSymbolAddress((void**)&p_xz, g_xz);
    cudaGetSymbolAddress((void**)&p_partxz, g_partxz);
    cudaGetSymbolAddress((void**)&p_xsc, g_xsc);
    cudaGetSymbolAddress((void**)&p_zs, g_zs);
    cudaGetSymbolAddress((void**)&p_dbcp0, g_dbcp0);
    cudaGetSymbolAddress((void**)&p_dbcp1, g_dbcp1);
    cudaGetSymbolAddress((void**)&p_dbcp2, g_dbcp2);
    cudaGetSymbolAddress((void**)&p_dbc, g_dbc);
    cudaGetSymbolAddress((void**)&p_delta_f, g_delta_f);
    cudaGetSymbolAddress((void**)&p_delta_b, g_delta_b);
    cudaGetSymbolAddress((void**)&p_y_f, g_y_f);
    cudaGetSymbolAddress((void**)&p_y_b, g_y_b);
    cudaGetSymbolAddress((void**)&p_part, g_part);
    cudaGetSymbolAddress((void**)&p_part2, g_part2);
    cudaGetSymbolAddress((void**)&p_ax, g_ax);
    cudaGetSymbolAddress((void**)&p_wi, g_wi);
    cudaGetSymbolAddress((void**)&p_xsc16, g_xsc16);
    cudaGetSymbolAddress((void**)&p_w3, g_w3);
    cudaGetSymbolAddress((void**)&p_wdtf, g_wdt_f);
    cudaGetSymbolAddress((void**)&p_wdtb, g_wdt_b);
    cudaGetSymbolAddress((void**)&p_d48f, g_dbc48_f);
    cudaGetSymbolAddress((void**)&p_d48b, g_dbc48_b);
    cudaGetSymbolAddress((void**)&p_u2, g_u2);
    cudaGetSymbolAddress((void**)&p_wo, g_wo);

    const int SMEM_MMA = 4 * STAGE_BYTES; // 81920
    cudaFuncSetAttribute(hmma_f16_nt<0, 0>, cudaFuncAttributeMaxDynamicSharedMemorySize, SMEM_MMA);
    cudaFuncSetAttribute(hmma_f16_nt<1, 1>, cudaFuncAttributeMaxDynamicSharedMemorySize, SMEM_MMA);

    // 0) weight/input splits
    split2_kernel<0><<<(BL * KIN / 4 + 255) / 256, 256>>>(x, p_ax, BL * KIN, KIN);
    split2_kernel<1><<<(2 * D_INNER * KIN / 4 + 255) / 256, 256>>>(
        in_proj_w, p_wi, 2 * D_INNER * KIN, KIN);
    split2_kernel<1><<<(D_MODEL * KOUT / 4 + 255) / 256, 256>>>(
        out_proj_w, p_wo, D_MODEL * KOUT, KOUT);
    splitw3_kernel<<<(2 * 80 * D_INNER / 4 + 255) / 256, 256>>>(
        x_proj_w, x_proj_b_w, p_w3);
    splitdt_kernel<<<(2 * D_INNER * DT_RANK / 4 + 255) / 256, 256>>>(
        dt_proj_w, dt_proj_b_w, p_wdtf, p_wdtb);

    // 1) xz = x @ in_proj_w^T  (HMMA fp16x2, split-K=2)
    hmma_f16_nt<0, 0><<<dim3((2 * D_INNER) / 128, BL / 128, 2), 256, SMEM_MMA>>>(
        p_ax, p_wi, p_xz, 2 * D_INNER, KIN2, KIN2 / 32 / 2,
        p_partxz, nullptr, nullptr, nullptr, nullptr, nullptr, nullptr);

    // 2) causal conv + silu + silu(z) + fp16 split of xsc
    conv_silu_kernel<<<(BL * D_INNER + 255) / 256, 256>>>(
        p_xz, p_partxz, conv_w, conv_bias, p_xsc, p_zs, p_xsc16);

    // 3) x_proj both dirs (HMMA, padded N=256, split-K=3)
    hmma_f16_nt<0, 0><<<dim3(DBC_PAD / 128, BL / 128, 3), 256, SMEM_MMA>>>(
        p_xsc16, p_w3, p_dbcp0, DBC_PAD, KOUT2, KOUT2 / 32 / 3,
        p_dbcp1, p_dbcp2, nullptr, nullptr, nullptr, nullptr, nullptr);

    // 4) combine partials -> dbc (fp32) + dbc48 (fp16 hi|lo)
    dbc_combine_kernel<<<(BL * DBC_PAD / 4 + 255) / 256, 256>>>(
        p_dbcp0, p_dbcp1, p_dbcp2, p_dbc, p_d48f, p_d48b);

    // 5) delta_{f,b} = softplus(dbc48 @ wdt^T + bias)  (HMMA, two problems)
    hmma_f16_nt<1, 1><<<dim3(D_INNER / 128, BL / 128, 2), 256, SMEM_MMA>>>(
        p_d48f, p_wdtf, p_delta_f, D_INNER, 2 * DT_RANK, (2 * DT_RANK) / 32,
        nullptr, nullptr, dt_proj_b,
        p_d48b, p_wdtb, p_delta_b, dt_proj_b_b);

    // 6) selective scan
    scan_kernel<<<dim3(D_INNER / 32, NB, 2), 512>>>(
        p_delta_f, p_delta_b, p_dbc,
        A_log, A_b_log, p_xsc, p_y_f, p_y_b);

    // 7) fuse -> u fp16 pair
    fuse_kernel<<<(BL * D_INNER / 4 + 255) / 256, 256>>>(
        p_y_f, p_y_b, p_xsc, p_zs, D_param, D_b, p_u2);

    // 8) out = u @ out_proj_w^T  (HMMA fp16x2, split-K=3)
    hmma_f16_nt<0, 0><<<dim3(D_MODEL / 128, BL / 128, 3), 256, SMEM_MMA>>>(
        p_u2, p_wo, out, D_MODEL, KOUT2, KOUT2 / 32 / 3,
        p_part, p_part2, nullptr, nullptr, nullptr, nullptr, nullptr);
    addout2_kernel<<<(BL * D_MODEL / 4 + 255) / 256, 256>>>(out, p_part, p_part2);
}

// round 9
// speedup vs baseline: 3.6509x; 1.0487x over previous
#include <cuda_runtime.h>
#include <cuda_fp16.h>
#include <cstdint>
#include <cstddef>

// ---------------- problem constants ----------------
#define D_MODEL 768
#define D_INNER 1536
#define D_STATE 16
#define DT_RANK 48
#define NB 2
#define SEQ 1024
#define BL (NB * SEQ)                 // 2048
#define KIN  D_MODEL                  // 768
#define KIN2 (2 * KIN)                // 1536
#define KOUT D_INNER                  // 1536
#define KOUT2 (2 * KOUT)              // 3072
#define DBC_PAD 256                   // padded dbc width (2 dirs x 128)
#define XPROJ_SPLITK 8

// ---------------- scratch (static __device__ arrays; zero-initialized) ----------------
__device__ float g_inp[2 * BL * 2 * D_INNER];       // in_proj split-K slices (z=0,1)
__device__ float g_zs[BL * D_INNER];
__device__ float g_dbcp[XPROJ_SPLITK * BL * DBC_PAD];  // x_proj split-K partials
__device__ float g_dbc_bc[BL * 64];                 // compact B/C: row*64 + dir*32 + n
__device__ float g_delta_f[BL * D_INNER];
__device__ float g_delta_b[BL * D_INNER];
__device__ float g_y_f[BL * D_INNER];
__device__ float g_y_b[BL * D_INNER];
__device__ float g_opart[3 * BL * D_MODEL];         // out_proj split-K slices
__device__ __half g_ax[BL * KIN2];                  // x split (hi|lo)
__device__ __half g_wi[2 * D_INNER * KIN2];         // in_proj_w split (hi|hi)
__device__ __half g_xsc16[BL * KOUT2];              // xsc split (hi|lo)
__device__ __half g_w3[DBC_PAD * KOUT2];            // x_proj weights padded (hi|hi)
__device__ __half g_wdt_f[D_INNER * 2 * DT_RANK];   // dt_proj_w split (hi|hi)
__device__ __half g_wdt_b[D_INNER * 2 * DT_RANK];
__device__ __half g_dbc48_f[BL * 2 * DT_RANK];      // dbc[:, :48] split (hi|lo)
__device__ __half g_dbc48_b[BL * 2 * DT_RANK];
__device__ __half g_u2[BL * KOUT2];                 // u split (hi|lo)
__device__ __half g_wo[D_MODEL * KOUT2];            // out_proj_w split (hi|hi)

// ---------------- math helpers ----------------
__device__ __forceinline__ float siluf(float x) { return x / (1.f + __expf(-x)); }
__device__ __forceinline__ float softplusf(float x) {
    return (x > 20.f) ? x : log1pf(__expf(x));
}
__device__ __forceinline__ uint32_t smem_u32(const void* p) {
    uint32_t a;
    asm("{ .reg .u64 t; cvta.to.shared.u64 t, %1; cvt.u32.u64 %0, t; }" : "=r"(a) : "l"(p));
    return a;
}
__device__ __forceinline__ void cp_async16(uint32_t saddr, const void* g) {
    asm volatile("cp.async.cg.shared.global [%0], [%1], 16;" :: "r"(saddr), "l"(g));
}
__device__ __forceinline__ void cp_commit() {
    asm volatile("cp.async.commit_group;" ::: "memory");
}
__device__ __forceinline__ void ldm_x4(uint32_t& r0, uint32_t& r1, uint32_t& r2,
                                       uint32_t& r3, uint32_t addr) {
    asm volatile("ldmatrix.sync.aligned.m8n8.x4.shared.b16 {%0,%1,%2,%3}, [%4];"
                 : "=r"(r0), "=r"(r1), "=r"(r2), "=r"(r3) : "r"(addr));
}
__device__ __forceinline__ void mma_f16(float* c, const uint32_t* a, const uint32_t* b) {
    asm volatile(
        "mma.sync.aligned.m16n8k16.row.col.f32.f16.f16.f32 "
        "{%0,%1,%2,%3}, {%4,%5,%6,%7}, {%8,%9}, {%0,%1,%2,%3};"
        : "+f"(c[0]), "+f"(c[1]), "+f"(c[2]), "+f"(c[3])
        : "r"(a[0]), "r"(a[1]), "r"(a[2]), "r"(a[3]), "r"(b[0]), "r"(b[1]));
}
__device__ __forceinline__ void split_h(float v, unsigned short& hi, unsigned short& lo) {
    __half h = __float2half_rn(v);
    __half l = __float2half_rn(v - __half2float(h));
    hi = __half_as_ushort(h); lo = __half_as_ushort(l);
}

// ---------------- HMMA fp16 GEMM: C[M,N] = A'[M,Kp] * B'[N,Kp]^T ----------------
// BM=BN=128, BK=32 fp16, 8 warps, warp tile 32x64, 4-stage cp.async pipeline.
// EPI: 0 = plain, 1 = softplus(v + bias[col]).
// ZMODE: 0 = split-K, z slice -> C + z*zstride; 1 = two problems (z=1 -> A2/...).
#define ROWB 80
#define STAGE_BYTES 20480
#define OFFB 10240
template <int EPI, int ZMODE>
__global__ void __launch_bounds__(256) hmma_f16_nt(
    const __half* __restrict__ A,
    const __half* __restrict__ B,
    float* __restrict__ C, int ldc, int Kp, int nChunks, long long zstride,
    const float* __restrict__ bias,
    const __half* __restrict__ A2, const __half* __restrict__ B2,
    float* __restrict__ C2, const float* __restrict__ bias2)
{
    extern __shared__ char smem[];
    const uint32_t sb = smem_u32(smem);
    const int tid = threadIdx.x;
    const int rowBase = blockIdx.y * 128;
    const int colBase = blockIdx.x * 128;
    float* Cw;
    int chunkBase;
    if (ZMODE == 1) {
        if (blockIdx.z == 1) { A = A2; B = B2; C = C2; bias = bias2; }
        Cw = C; chunkBase = 0;
    } else {
        Cw = C + (size_t)blockIdx.z * (size_t)zstride;
        chunkBase = blockIdx.z * nChunks;
    }

    const int r0 = tid >> 2, c0 = tid & 3;
    const int r1 = (tid + 256) >> 2, c1 = (tid + 256) & 3;
    const char* gA0 = (const char*)(A + (size_t)(rowBase + r0) * Kp + c0 * 8)
                      + (size_t)chunkBase * 64;
    const char* gA1 = (const char*)(A + (size_t)(rowBase + r1) * Kp + c1 * 8)
                      + (size_t)chunkBase * 64;
    const char* gB0 = (const char*)(B + (size_t)(colBase + r0) * Kp + c0 * 8)
                      + (size_t)chunkBase * 64;
    const char* gB1 = (const char*)(B + (size_t)(colBase + r1) * Kp + c1 * 8)
                      + (size_t)chunkBase * 64;
    const uint32_t sA0 = r0 * ROWB + c0 * 16, sA1 = r1 * ROWB + c1 * 16;
    const uint32_t sB0 = OFFB + sA0, sB1 = OFFB + sA1;

#define LOAD_STAGE(c) do {                                                  \
    const uint32_t _base = sb + ((c) & 3) * STAGE_BYTES;                    \
    const size_t _gk = (size_t)(c) * 64;                                    \
    cp_async16(_base + sA0, gA0 + _gk);                                     \
    cp_async16(_base + sA1, gA1 + _gk);                                     \
    cp_async16(_base + sB0, gB0 + _gk);                                     \
    cp_async16(_base + sB1, gB1 + _gk);                                     \
} while (0)

    const int wid = tid >> 5;
    const int l = tid & 31;
    const int wm = wid & 3;
    const int wn = wid >> 2;
    const int a_row = ((l >> 3) & 1) * 8 + (l & 7);
    const int a_k   = (l >> 4) * 8;
    const int b_n   = (l >> 4) * 8 + (l & 7);
    const int b_k   = ((l >> 3) & 1) * 8;

    float acc[2][8][4];
#pragma unroll
    for (int i = 0; i < 2; i++)
#pragma unroll
        for (int j = 0; j < 8; j++)
#pragma unroll
            for (int q = 0; q < 4; q++) acc[i][j][q] = 0.f;

    LOAD_STAGE(0); cp_commit();
    if (nChunks > 1) LOAD_STAGE(1);
    cp_commit();
    if (nChunks > 2) LOAD_STAGE(2);
    cp_commit();

    for (int c = 0; c < nChunks; c++) {
        asm volatile("cp.async.wait_group 2;" ::: "memory");
        __syncthreads();
        if (c + 3 < nChunks) LOAD_STAGE(c + 3);
        cp_commit();

        const uint32_t stb = sb + (c & 3) * STAGE_BYTES;
        const uint32_t aW = stb + (wm * 32) * ROWB;
        const uint32_t bW = stb + OFFB + (wn * 64) * ROWB;

        uint32_t a[2][2][4];
#pragma unroll
        for (int ks = 0; ks < 2; ks++)
#pragma unroll
            for (int mi = 0; mi < 2; mi++)
                ldm_x4(a[ks][mi][0], a[ks][mi][1], a[ks][mi][2], a[ks][mi][3],
                       aW + (mi * 16 + a_row) * ROWB + (ks * 16 + a_k) * 2);

        uint32_t b[3][4];
        ldm_x4(b[0][0], b[0][1], b[0][2], b[0][3], bW + b_n * ROWB + b_k * 2);
        ldm_x4(b[1][0], b[1][1], b[1][2], b[1][3], bW + (16 + b_n) * ROWB + b_k * 2);
#pragma unroll
        for (int i = 0; i < 8; i++) {
            if (i + 2 < 8) {
                const int ks2 = (i + 2) >> 2, nf2 = (i + 2) & 3;
                const int slot = (i + 2) % 3;
                ldm_x4(b[slot][0], b[slot][1], b[slot][2], b[slot][3],
                       bW + (nf2 * 16 + b_n) * ROWB + (ks2 * 16 + b_k) * 2);
            }
            const int ks = i >> 2, nf = i & 3;
            const uint32_t* bb = b[i % 3];
#pragma unroll
            for (int mi = 0; mi < 2; mi++) {
                mma_f16(acc[mi][nf * 2],     a[ks][mi], bb);
                mma_f16(acc[mi][nf * 2 + 1], a[ks][mi], bb + 2);
            }
        }
    }

    const int lrow = l >> 2;
    const int lcol = (l & 3) * 2;
#pragma unroll
    for (int mi = 0; mi < 2; mi++) {
        const int grow = rowBase + wm * 32 + mi * 16 + lrow;
#pragma unroll
        for (int nb = 0; nb < 8; nb++) {
            const int gcol = colBase + wn * 64 + nb * 8 + lcol;
            float v0 = acc[mi][nb][0], v1 = acc[mi][nb][1];
            float v2 = acc[mi][nb][2], v3 = acc[mi][nb][3];
            if (EPI == 1) {
                v0 = softplusf(v0 + bias[gcol]);
                v1 = softplusf(v1 + bias[gcol + 1]);
                v2 = softplusf(v2 + bias[gcol]);
                v3 = softplusf(v3 + bias[gcol + 1]);
            }
            *(float2*)(Cw + (size_t)grow * ldc + gcol) = make_float2(v0, v1);
            *(float2*)(Cw + (size_t)(grow + 8) * ldc + gcol) = make_float2(v2, v3);
        }
    }
#undef LOAD_STAGE
}

// ---------------- merged operand-prep kernel (5 former split kernels) ----------------
#define SEG0 (BL * KIN / 4)                 // x -> ax (hi|lo)
#define SEG1 (2 * D_INNER * KIN / 4)        // in_proj_w -> wi (hi|hi)
#define SEG2 (D_MODEL * KOUT / 4)           // out_proj_w -> wo (hi|hi)
#define SEG3 (2 * 80 * D_INNER / 4)         // x_proj_{f,b} -> w3 padded (hi|hi)
#define SEG4 (2 * D_INNER * DT_RANK / 4)    // dt_proj_{f,b}_w -> wdt (hi|hi)
#define PREP_TOTAL (SEG0 + SEG1 + SEG2 + SEG3 + SEG4)
__global__ void prep_kernel(
    const float* __restrict__ x, const float* __restrict__ in_w,
    const float* __restrict__ out_w,
    const float* __restrict__ xp_f, const float* __restrict__ xp_b,
    const float* __restrict__ dt_f, const float* __restrict__ dt_b,
    __half* __restrict__ ax, __half* __restrict__ wi, __half* __restrict__ wo,
    __half* __restrict__ w3, __half* __restrict__ wdtf, __half* __restrict__ wdtb)
{
    int i4 = blockIdx.x * blockDim.x + threadIdx.x;
    if (i4 >= PREP_TOTAL) return;

    const float* src;
    unsigned short* dsth;
    unsigned short* dstl;
    size_t sidx, dbase;
    int doff;

    if (i4 < SEG0) {
        const int t = i4 * 4;
        const int r = t / KIN, k = t % KIN;
        src = x; sidx = t;
        dsth = (unsigned short*)ax; dbase = (size_t)r * KIN2 + k; doff = KIN;
        dstl = dsth; // lo stored
        const float4 v = *(const float4*)(src + sidx);
        float vv[4] = {v.x, v.y, v.z, v.w};
        unsigned short hs[4], ls[4];
#pragma unroll
        for (int j = 0; j < 4; j++) split_h(vv[j], hs[j], ls[j]);
        *(ushort4*)(dsth + dbase) = make_ushort4(hs[0], hs[1], hs[2], hs[3]);
        *(ushort4*)(dsth + dbase + doff) = make_ushort4(ls[0], ls[1], ls[2], ls[3]);
        return;
    }
    i4 -= SEG0;
    if (i4 < SEG1) {
        const int t = i4 * 4;
        const int r = t / KIN, k = t % KIN;
        const float4 v = *(const float4*)(in_w + t);
        float vv[4] = {v.x, v.y, v.z, v.w};
        unsigned short hs[4], ls[4];
#pragma unroll
        for (int j = 0; j < 4; j++) split_h(vv[j], hs[j], ls[j]);
        unsigned short* o = (unsigned short*)wi;
        const size_t base = (size_t)r * KIN2 + k;
        *(ushort4*)(o + base) = make_ushort4(hs[0], hs[1], hs[2], hs[3]);
        *(ushort4*)(o + base + KIN) = make_ushort4(hs[0], hs[1], hs[2], hs[3]);
        return;
    }
    i4 -= SEG1;
    if (i4 < SEG2) {
        const int t = i4 * 4;
        const int r = t / KOUT, k = t % KOUT;
        const float4 v = *(const float4*)(out_w + t);
        float vv[4] = {v.x, v.y, v.z, v.w};
        unsigned short hs[4], ls[4];
#pragma unroll
        for (int j = 0; j < 4; j++) split_h(vv[j], hs[j], ls[j]);
        unsigned short* o = (unsigned short*)wo;
        const size_t base = (size_t)r * KOUT2 + k;
        *(ushort4*)(o + base) = make_ushort4(hs[0], hs[1], hs[2], hs[3]);
        *(ushort4*)(o + base + KOUT) = make_ushort4(hs[0], hs[1], hs[2], hs[3]);
        return;
    }
    i4 -= SEG2;
    if (i4 < SEG3) {
        const int t = i4 * 4;
        const int dir = t / (80 * D_INNER);
        const int rem = t % (80 * D_INNER);
        const int n = rem / D_INNER, k = rem % D_INNER;
        const float* w = dir ? xp_b : xp_f;
        const float4 v = *(const float4*)(w + (size_t)n * D_INNER + k);
        float vv[4] = {v.x, v.y, v.z, v.w};
        unsigned short hs[4], ls[4];
#pragma unroll
        for (int j = 0; j < 4; j++) split_h(vv[j], hs[j], ls[j]);
        unsigned short* o = (unsigned short*)w3;
        const size_t base = (size_t)(dir * 128 + n) * KOUT2 + k;
        *(ushort4*)(o + base) = make_ushort4(hs[0], hs[1], hs[2], hs[3]);
        *(ushort4*)(o + base + D_INNER) = make_ushort4(hs[0], hs[1], hs[2], hs[3]);
        return;
    }
    i4 -= SEG3;
    {
        const int t = i4 * 4;
        const int dir = t / (D_INNER * DT_RANK);
        const int rem = t % (D_INNER * DT_RANK);
        const int n = rem / DT_RANK, k = rem % DT_RANK;
        const float* w = dir ? dt_b : dt_f;
        unsigned short* o = (unsigned short*)(dir ? wdtb : wdtf);
        const float4 v = *(const float4*)(w + (size_t)n * DT_RANK + k);
        float vv[4] = {v.x, v.y, v.z, v.w};
        unsigned short hs[4], ls[4];
#pragma unroll
        for (int j = 0; j < 4; j++) split_h(vv[j], hs[j], ls[j]);
        const size_t base = (size_t)n * (2 * DT_RANK) + k;
        *(ushort4*)(o + base) = make_ushort4(hs[0], hs[1], hs[2], hs[3]);
        *(ushort4*)(o + base + DT_RANK) = make_ushort4(hs[0], hs[1], hs[2], hs[3]);
    }
}

// ---------------- combine x_proj split-K partials (80-col strips only) ----------------
// Emits fp16 dbc48 (hi|lo) for dt GEMM + compact fp32 B/C for scan.
__global__ void dbc48_combine_kernel(const float* __restrict__ parts,
                                     __half* __restrict__ d48f,
                                     __half* __restrict__ d48b,
                                     float* __restrict__ dbc_bc)
{
    const int i4 = blockIdx.x * blockDim.x + threadIdx.x;
    if (i4 * 4 >= BL * 160) return;
    const int t = i4 * 4;
    const int row = t / 160;
    const int rr = t % 160;
    const int dir = rr / 80;
    const int c = rr % 80;
    const size_t src = (size_t)row * DBC_PAD + dir * 128 + c;
    float vv[4] = {0.f, 0.f, 0.f, 0.f};
#pragma unroll
    for (int p = 0; p < XPROJ_SPLITK; p++) {
        const float4 v = *(const float4*)(parts + (size_t)p * (BL * DBC_PAD) + src);
        vv[0] += v.x; vv[1] += v.y; vv[2] += v.z; vv[3] += v.w;
    }
    if (c < DT_RANK) {
        unsigned short hs[4], ls[4];
#pragma unroll
        for (int j = 0; j < 4; j++) split_h(vv[j], hs[j], ls[j]);
        unsigned short* o = (unsigned short*)(dir ? d48b : d48f);
        const size_t base = (size_t)row * (2 * DT_RANK) + c;
        *(ushort4*)(o + base) = make_ushort4(hs[0], hs[1], hs[2], hs[3]);
        *(ushort4*)(o + base + DT_RANK) = make_ushort4(ls[0], ls[1], ls[2], ls[3]);
    } else {
        *(float4*)(dbc_bc + (size_t)row * 64 + dir * 32 + (c - DT_RANK)) =
            make_float4(vv[0], vv[1], vv[2], vv[3]);
    }
}

// ---------------- causal conv(4) + SiLU -> xsc16 (hi|lo); silu(z) ----------------
__global__ void conv_silu_kernel(
    const float* __restrict__ inp,
    const float* __restrict__ cw, const float* __restrict__ cb,
    float* __restrict__ zs, __half* __restrict__ xsc16)
{
    const int idx = blockIdx.x * blockDim.x + threadIdx.x;
    if (idx >= BL * D_INNER) return;
    const int e = idx % D_INNER;
    const int row = idx / D_INNER;
    const int l = row & (SEQ - 1);
    const float w0 = cw[e * 4 + 0];
    const float w1 = cw[e * 4 + 1];
    const float w2 = cw[e * 4 + 2];
    const float w3 = cw[e * 4 + 3];
    const float* part = inp + (size_t)BL * 2 * D_INNER;
    const size_t base = (size_t)row * (2 * D_INNER) + e;
    float acc = cb[e];
    acc = fmaf(w3, inp[base] + part[base], acc);
    if (l >= 1) acc = fmaf(w2, inp[base - 2 * D_INNER] + part[base - 2 * D_INNER], acc);
    if (l >= 2) acc = fmaf(w1, inp[base - 4 * D_INNER] + part[base - 4 * D_INNER], acc);
    if (l >= 3) acc = fmaf(w0, inp[base - 6 * D_INNER] + part[base - 6 * D_INNER], acc);
    const float xs = siluf(acc);
    unsigned short hi, lo;
    split_h(xs, hi, lo);
    unsigned short* o = (unsigned short*)xsc16 + (size_t)row * KOUT2 + e;
    o[0] = hi;
    o[D_INNER] = lo;
    const float z = inp[base + D_INNER] + part[base + D_INNER];
    zs[idx] = siluf(z);
}

// ---------------- selective scan (xsc reconstructed from fp16 pair) ----------------
__global__ void __launch_bounds__(512) scan_kernel(
    const float* __restrict__ delta_f, const float* __restrict__ delta_b,
    const float* __restrict__ dbc_bc,
    const float* __restrict__ A_log,  const float* __restrict__ A_b_log,
    const __half* __restrict__ xsc16,
    float* __restrict__ y_f, float* __restrict__ y_b)
{
    const int dir = blockIdx.z;
    const int b = blockIdx.y;
    const int e0 = blockIdx.x * 32;
    const int t = threadIdx.x;
    const int el = t >> 4;
    const int n = t & 15;
    const int e = e0 + el;
    const float* delta = dir ? delta_b : delta_f;
    const float* Alog = dir ? A_b_log : A_log;
    float* y = dir ? y_b : y_f;
    const float An = -__expf(Alog[e * D_STATE + n]);
    __shared__ float s_d[16 * 32];
    __shared__ float s_x[16 * 32];
    __shared__ float s_bc[16 * 32];
    __shared__ float s_y[16 * 32];
    const int lj = t >> 5;
    const int lc = t & 31;
    float h = 0.f;
    const size_t rowb = (size_t)b * SEQ;
    for (int c = 0; c < SEQ / 16; c++) {
        {
            const int i = c * 16 + lj;
            const int l = dir ? (SEQ - 1 - i) : i;
            const size_t row = rowb + l;
            s_d[lj * 32 + lc] = delta[row * D_INNER + e0 + lc];
            const __half xh = xsc16[row * KOUT2 + e0 + lc];
            const __half xl = xsc16[row * KOUT2 + D_INNER + e0 + lc];
            s_x[lj * 32 + lc] = __half2float(xh) + __half2float(xl);
            s_bc[lj * 32 + lc] = dbc_bc[row * 64 + dir * 32 + lc];
        }
        __syncthreads();
#pragma unroll
        for (int j = 0; j < 16; j++) {
            const float dlt = s_d[j * 32 + el];
            const float xv  = s_x[j * 32 + el];
            const float Bv  = s_bc[j * 32 + n];
            const float Cv  = s_bc[j * 32 + 16 + n];
            const float dA = __expf(dlt * An);
            h = fmaf(dA, h, dlt * xv * Bv);
            float p = h * Cv;
            p += __shfl_xor_sync(0xffffffffu, p, 8);
            p += __shfl_xor_sync(0xffffffffu, p, 4);
            p += __shfl_xor_sync(0xffffffffu, p, 2);
            p += __shfl_xor_sync(0xffffffffu, p, 1);
            if (n == 0) s_y[j * 32 + el] = p;
        }
        __syncthreads();
        {
            const int i = c * 16 + lj;
            const int l = dir ? (SEQ - 1 - i) : i;
            y[(rowb + l) * D_INNER + e0 + lc] = s_y[lj * 32 + lc];
        }
    }
}

// ---------------- fuse: u = (y_f + y_b + (D+D_b)*xs)*silu(z) -> fp16 pair ----------------
__global__ void fuse_kernel(
    const float* __restrict__ yf, const float* __restrict__ yb,
    const __half* __restrict__ xsc16, const float* __restrict__ zs,
    const float* __restrict__ D1, const float* __restrict__ D2,
    __half* __restrict__ u2)
{
    const int idx4 = blockIdx.x * blockDim.x + threadIdx.x;
    if (idx4 >= (BL * D_INNER) / 4) return;
    const int e4 = (idx4 * 4) % D_INNER;
    const int r = (idx4 * 4) / D_INNER;
    const float4 a = *(const float4*)(yf + (size_t)idx4 * 4);
    const float4 bq = *(const float4*)(yb + (size_t)idx4 * 4);
    const float4 zv = *(const float4*)(zs + (size_t)idx4 * 4);
    const float4 d1 = *(const float4*)(D1 + e4);
    const float4 d2 = *(const float4*)(D2 + e4);
    const ushort4 xh = *(const ushort4*)((const unsigned short*)xsc16 + (size_t)r * KOUT2 + e4);
    const ushort4 xl = *(const ushort4*)((const unsigned short*)xsc16 + (size_t)r * KOUT2 + KOUT + e4);
    float xv[4];
    xv[0] = __half2float(__ushort_as_half(xh.x)) + __half2float(__ushort_as_half(xl.x));
    xv[1] = __half2float(__ushort_as_half(xh.y)) + __half2float(__ushort_as_half(xl.y));
    xv[2] = __half2float(__ushort_as_half(xh.z)) + __half2float(__ushort_as_half(xl.z));
    xv[3] = __half2float(__ushort_as_half(xh.w)) + __half2float(__ushort_as_half(xl.w));
    float vv[4];
    vv[0] = (a.x + bq.x + (d1.x + d2.x) * xv[0]) * zv.x;
    vv[1] = (a.y + bq.y + (d1.y + d2.y) * xv[1]) * zv.y;
    vv[2] = (a.z + bq.z + (d1.z + d2.z) * xv[2]) * zv.z;
    vv[3] = (a.w + bq.w + (d1.w + d2.w) * xv[3]) * zv.w;
    unsigned short hs[4], ls[4];
#pragma unroll
    for (int j = 0; j < 4; j++) split_h(vv[j], hs[j], ls[j]);
    const size_t base = (size_t)r * KOUT2 + e4;
    *(ushort4*)((unsigned short*)u2 + base) = make_ushort4(hs[0], hs[1], hs[2], hs[3]);
    *(ushort4*)((unsigned short*)u2 + base + KOUT) = make_ushort4(ls[0], ls[1], ls[2], ls[3]);
}

// ---------------- out = sum of 3 out_proj slices ----------------
__global__ void addout3_kernel(float* __restrict__ out, const float* __restrict__ parts)
{
    const int i4 = blockIdx.x * blockDim.x + threadIdx.x;
    if (i4 * 4 >= BL * D_MODEL) return;
    const float4 a = *(const float4*)(parts + (size_t)i4 * 4);
    const float4 b = *(const float4*)(parts + (size_t)(BL * D_MODEL) + i4 * 4);
    const float4 c = *(const float4*)(parts + (size_t)(2 * BL * D_MODEL) + i4 * 4);
    *(float4*)(out + (size_t)i4 * 4) =
        make_float4(a.x + b.x + c.x, a.y + b.y + c.y, a.z + b.z + c.z, a.w + b.w + c.w);
}

// ---------------- launcher ----------------
extern "C" void kernel_launch(void* const* d_in, const int* in_sizes, int n_in,
                              void* d_out, int out_size)
{
    const float* x          = (const float*)d_in[0];
    const float* in_proj_w  = (const float*)d_in[1];
    const float* conv_w     = (const float*)d_in[2];
    const float* conv_bias  = (const float*)d_in[3];
    const float* x_proj_w   = (const float*)d_in[4];
    const float* dt_proj_w  = (const float*)d_in[5];
    const float* dt_proj_b  = (const float*)d_in[6];
    const float* A_log      = (const float*)d_in[7];
    const float* D_param    = (const float*)d_in[8];
    const float* out_proj_w = (const float*)d_in[9];
    const float* A_b_log    = (const float*)d_in[10];
    const float* x_proj_b_w = (const float*)d_in[11];
    const float* dt_proj_b_w= (const float*)d_in[12];
    const float* dt_proj_b_b= (const float*)d_in[13];
    const float* D_b        = (const float*)d_in[14];
    float* out = (float*)d_out;

    float *p_inp, *p_zs, *p_dbcp, *p_dbc_bc;
    float *p_delta_f, *p_delta_b, *p_y_f, *p_y_b, *p_opart;
    __half *p_ax, *p_wi, *p_xsc16, *p_w3, *p_wdtf, *p_wdtb, *p_d48f, *p_d48b, *p_u2, *p_wo;
    cudaGetSymbolAddress((void**)&p_inp, g_inp);
    cudaGetSymbolAddress((void**)&p_zs, g_zs);
    cudaGetSymbolAddress((void**)&p_dbcp, g_dbcp);
    cudaGetSymbolAddress((void**)&p_dbc_bc, g_dbc_bc);
    cudaGetSymbolAddress((void**)&p_delta_f, g_delta_f);
    cudaGetSymbolAddress((void**)&p_delta_b, g_delta_b);
    cudaGetSymbolAddress((void**)&p_y_f, g_y_f);
    cudaGetSymbolAddress((void**)&p_y_b, g_y_b);
    cudaGetSymbolAddress((void**)&p_opart, g_opart);
    cudaGetSymbolAddress((void**)&p_ax, g_ax);
    cudaGetSymbolAddress((void**)&p_wi, g_wi);
    cudaGetSymbolAddress((void**)&p_xsc16, g_xsc16);
    cudaGetSymbolAddress((void**)&p_w3, g_w3);
    cudaGetSymbolAddress((void**)&p_wdtf, g_wdt_f);
    cudaGetSymbolAddress((void**)&p_wdtb, g_wdt_b);
    cudaGetSymbolAddress((void**)&p_d48f, g_dbc48_f);
    cudaGetSymbolAddress((void**)&p_d48b, g_dbc48_b);
    cudaGetSymbolAddress((void**)&p_u2, g_u2);
    cudaGetSymbolAddress((void**)&p_wo, g_wo);

    const int SMEM_MMA = 4 * STAGE_BYTES; // 81920
    cudaFuncSetAttribute(hmma_f16_nt<0, 0>, cudaFuncAttributeMaxDynamicSharedMemorySize, SMEM_MMA);
    cudaFuncSetAttribute(hmma_f16_nt<1, 1>, cudaFuncAttributeMaxDynamicSharedMemorySize, SMEM_MMA);

    // 0) all operand splits in one launch
    prep_kernel<<<(PREP_TOTAL + 255) / 256, 256>>>(
        x, in_proj_w, out_proj_w, x_proj_w, x_proj_b_w, dt_proj_w, dt_proj_b_w,
        p_ax, p_wi, p_wo, p_w3, p_wdtf, p_wdtb);

    // 1) xz slices = x @ in_proj_w^T  (split-K=2, slices summed in conv)
    hmma_f16_nt<0, 0><<<dim3((2 * D_INNER) / 128, BL / 128, 2), 256, SMEM_MMA>>>(
        p_ax, p_wi, p_inp, 2 * D_INNER, KIN2, KIN2 / 32 / 2, (long long)BL * 2 * D_INNER,
        nullptr, nullptr, nullptr, nullptr, nullptr);

    // 2) causal conv + silu -> xsc16; silu(z)
    conv_silu_kernel<<<(BL * D_INNER + 255) / 256, 256>>>(
        p_inp, conv_w, conv_bias, p_zs, p_xsc16);

    // 3) x_proj both dirs (padded N=256, split-K=8)
    hmma_f16_nt<0, 0><<<dim3(DBC_PAD / 128, BL / 128, XPROJ_SPLITK), 256, SMEM_MMA>>>(
        p_xsc16, p_w3, p_dbcp, DBC_PAD, KOUT2, KOUT2 / 32 / XPROJ_SPLITK,
        (long long)BL * DBC_PAD, nullptr, nullptr, nullptr, nullptr, nullptr);

    // 4) combine partial strips -> d48 fp16 + compact B/C
    dbc48_combine_kernel<<<(BL * 160 / 4 + 255) / 256, 256>>>(
        p_dbcp, p_d48f, p_d48b, p_dbc_bc);

    // 5) delta_{f,b} = softplus(d48 @ wdt^T + bias)
    hmma_f16_nt<1, 1><<<dim3(D_INNER / 128, BL / 128, 2), 256, SMEM_MMA>>>(
        p_d48f, p_wdtf, p_delta_f, D_INNER, 2 * DT_RANK, (2 * DT_RANK) / 32, 0,
        dt_proj_b, p_d48b, p_wdtb, p_delta_b, dt_proj_b_b);

    // 6) selective scan
    scan_kernel<<<dim3(D_INNER / 32, NB, 2), 512>>>(
        p_delta_f, p_delta_b, p_dbc_bc, A_log, A_b_log, p_xsc16, p_y_f, p_y_b);

    // 7) fuse -> u fp16 pair
    fuse_kernel<<<(BL * D_INNER / 4 + 255) / 256, 256>>>(
        p_y_f, p_y_b, p_xsc16, p_zs, D_param, D_b, p_u2);

    // 8) out slices = u @ out_proj_w^T  (split-K=3)
    hmma_f16_nt<0, 0><<<dim3(D_MODEL / 128, BL / 128, 3), 256, SMEM_MMA>>>(
        p_u2, p_wo, p_opart, D_MODEL, KOUT2, KOUT2 / 32 / 3, (long long)BL * D_MODEL,
        nullptr, nullptr, nullptr, nullptr, nullptr);
    addout3_kernel<<<(BL * D_MODEL / 4 + 255) / 256, 256>>>(out, p_opart);
}